// round 1
// baseline (speedup 1.0000x reference)
#include <cuda_runtime.h>
#include <cuda_bf16.h>
#include <cstdint>

// ---------------------------------------------------------------------------
// LinearMessagePassingLayer — GB300 sm_103a
//
// Math restructuring:
//   aggregated_msg = segment_sum(concat(nodes[s], edge_attr) @ Wm^T, recv)
//                  = segment_sum(concat(nodes[s], edge_attr), recv) @ Wm^T   (linearity)
//   node_input @ W1^T = nodes @ W1a^T + agg_msg @ W1b^T
//                     = nodes @ W1a^T + AGG @ (W1b @ Wm)^T                   (fuse)
// where AGG[n] = sum over incoming edges of [nodes[sender] | edge_attr].
//
// Pipeline (all graph-capturable, no allocations):
//   0. detect edge_index dtype (int64 vs int32) on device
//   1. convert indices -> int32 scratch
//   2. zero AGG
//   3. Wf = W1b @ Wm  (tiny GEMM)
//   4. edge scatter: AGG[r] += [nodes[s] | edge_attr[e]]  via red.global.add.v4.f32
//   5. stage1: h = LN1(relu(nodes@W1a^T + AGG@Wf^T + b1))
//   6. stage2: out = LN(nodes@Wn^T + LN2(relu(h@W2^T + b2)))
// ---------------------------------------------------------------------------

#define N_NODES 100000
#define N_EDGES 800000
#define D       128
#define ED      32
#define AD      160   // D + ED
#define NGROUPS (N_NODES / 8)   // 12500, N divisible by 8
#define LN_EPS  1e-5f

// --------------------------- device scratch -------------------------------
__device__ float g_agg[(size_t)N_NODES * AD];   // 64 MB
__device__ float g_h[(size_t)N_NODES * D];      // 51.2 MB
__device__ float g_wf[D * AD];                  // fused W1b @ Wm
__device__ int   g_sr[2 * N_EDGES];             // senders | receivers (int32)
__device__ int   g_idx64;

// --------------------------- helpers ---------------------------------------
__device__ __forceinline__ void red_add_f4(float* p, float4 v) {
    asm volatile("red.global.add.v4.f32 [%0], {%1,%2,%3,%4};"
                 :: "l"(p), "f"(v.x), "f"(v.y), "f"(v.z), "f"(v.w) : "memory");
}

__device__ __forceinline__ void group_bar(int tg) {
    asm volatile("bar.sync %0, 128;" :: "r"(tg + 1) : "memory");
}

// --------------------------- dtype detect / convert ------------------------
__global__ void detect_idx_kernel(const unsigned int* __restrict__ w) {
    __shared__ int anynz;
    if (threadIdx.x == 0) anynz = 0;
    __syncthreads();
    // If edge_index is int64 (LE), every odd 32-bit word is a zero high-half
    // (values in [0, 100000)). If int32, odd words are random indices —
    // probability all 256 samples are zero is negligible.
    if (w[2 * threadIdx.x + 1] != 0u) atomicOr(&anynz, 1);
    __syncthreads();
    if (threadIdx.x == 0) g_idx64 = anynz ? 0 : 1;
}

__global__ void convert_idx_kernel(const void* __restrict__ p) {
    int i = blockIdx.x * blockDim.x + threadIdx.x;
    if (i >= 2 * N_EDGES) return;
    if (g_idx64)
        g_sr[i] = (int)((const long long*)p)[i];
    else
        g_sr[i] = ((const int*)p)[i];
}

// --------------------------- zero agg ---------------------------------------
__global__ void zero_agg_kernel() {
    const int total4 = (N_NODES * AD) / 4;
    float4* p = reinterpret_cast<float4*>(g_agg);
    for (int i = blockIdx.x * blockDim.x + threadIdx.x; i < total4;
         i += gridDim.x * blockDim.x)
        p[i] = make_float4(0.f, 0.f, 0.f, 0.f);
}

// --------------------------- weight fusion ---------------------------------
// Wf[j][c] = sum_k W1[j][128+k] * Wm[k][c],  j<128, c<160
__global__ void fuse_w_kernel(const float* __restrict__ W1,
                              const float* __restrict__ Wm) {
    int i = blockIdx.x * blockDim.x + threadIdx.x;   // i < 128*160
    if (i >= D * AD) return;
    int j = i / AD, c = i - j * AD;
    float s = 0.f;
    #pragma unroll 8
    for (int k = 0; k < D; k++)
        s += W1[j * (D + D) + D + k] * Wm[k * AD + c];
    g_wf[i] = s;
}

// --------------------------- edge scatter ----------------------------------
__global__ void __launch_bounds__(256)
edge_scatter_kernel(const float4* __restrict__ nodes4,
                    const float4* __restrict__ ea4) {
    int e = blockIdx.x * blockDim.x + threadIdx.x;
    if (e >= N_EDGES) return;
    int s = g_sr[e];
    int r = g_sr[N_EDGES + e];
    const float4* src = nodes4 + (size_t)s * (D / 4);
    float* dst = g_agg + (size_t)r * AD;
    #pragma unroll
    for (int i = 0; i < D / 4; i++) {
        float4 v = __ldg(src + i);
        red_add_f4(dst + i * 4, v);
    }
    const float4* a = ea4 + (size_t)e * (ED / 4);
    #pragma unroll
    for (int i = 0; i < ED / 4; i++) {
        float4 v = __ldg(a + i);
        red_add_f4(dst + D + i * 4, v);
    }
}

// --------------------------- stage 1 ----------------------------------------
// h = LN1(relu(nodes @ W1a^T + AGG @ Wf^T + b1))
// Block: 256 threads = 2 independent 128-thread groups; each group handles
// 8 nodes per iteration with 8-way register blocking (thread j owns col j).
#define WPAD 129   // smem weight row stride (conflict-free scalar access)

__global__ void __launch_bounds__(256, 1)
stage1_kernel(const float* __restrict__ nodes,
              const float* __restrict__ W1,
              const float* __restrict__ b1,
              const float* __restrict__ g1,
              const float* __restrict__ be1) {
    extern __shared__ float sm[];
    float* sW1 = sm;                        // [128][WPAD]  W1a^T : sW1[k*WPAD+j]=W1[j][k]
    float* sWf = sW1 + D * WPAD;            // [160][WPAD]  Wf^T  : sWf[c*WPAD+j]=Wf[j][c]
    float* sX  = sWf + AD * WPAD;           // staging: per group 8*128 + 8*160 floats

    __shared__ float sb1[D], sg1[D], sbe[D];
    __shared__ float sred[2][4][16];        // [group][warp][r*2 + {sum,sq}]
    __shared__ float sfin[2][8][2];

    const int tid = threadIdx.x;
    if (tid < D) { sb1[tid] = b1[tid]; sg1[tid] = g1[tid]; sbe[tid] = be1[tid]; }
    for (int i = tid; i < D * D; i += 256) {
        int j = i >> 7, k = i & 127;
        sW1[k * WPAD + j] = W1[j * (2 * D) + k];
    }
    for (int i = tid; i < D * AD; i += 256) {
        int j = i / AD, c = i - j * AD;
        sWf[c * WPAD + j] = g_wf[i];
    }
    __syncthreads();

    const int tg   = tid >> 7;
    const int lj   = tid & 127;
    const int lane = tid & 31;
    const int w4   = (tid >> 5) & 3;

    float* xn = sX + tg * (8 * D + 8 * AD);
    float* xa = xn + 8 * D;

    const int g0   = blockIdx.x * 2 + tg;
    const int step = gridDim.x * 2;

    for (int g = g0; g < NGROUPS; g += step) {
        const int n0 = g * 8;
        group_bar(tg);
        #pragma unroll
        for (int r = 0; r < 8; r++)
            xn[r * D + lj] = nodes[(size_t)(n0 + r) * D + lj];
        for (int i = lj; i < 8 * AD; i += 128)
            xa[i] = g_agg[(size_t)n0 * AD + i];
        group_bar(tg);

        float acc[8];
        #pragma unroll
        for (int r = 0; r < 8; r++) acc[r] = sb1[lj];

        for (int k = 0; k < D; k += 4) {
            float w0 = sW1[(k + 0) * WPAD + lj];
            float w1 = sW1[(k + 1) * WPAD + lj];
            float w2 = sW1[(k + 2) * WPAD + lj];
            float w3 = sW1[(k + 3) * WPAD + lj];
            #pragma unroll
            for (int r = 0; r < 8; r++) {
                float4 x = *reinterpret_cast<const float4*>(&xn[r * D + k]);
                acc[r] += x.x * w0 + x.y * w1 + x.z * w2 + x.w * w3;
            }
        }
        for (int c = 0; c < AD; c += 4) {
            float w0 = sWf[(c + 0) * WPAD + lj];
            float w1 = sWf[(c + 1) * WPAD + lj];
            float w2 = sWf[(c + 2) * WPAD + lj];
            float w3 = sWf[(c + 3) * WPAD + lj];
            #pragma unroll
            for (int r = 0; r < 8; r++) {
                float4 x = *reinterpret_cast<const float4*>(&xa[r * AD + c]);
                acc[r] += x.x * w0 + x.y * w1 + x.z * w2 + x.w * w3;
            }
        }

        float y[8];
        #pragma unroll
        for (int r = 0; r < 8; r++) y[r] = fmaxf(acc[r], 0.f);

        #pragma unroll
        for (int r = 0; r < 8; r++) {
            float s = y[r], q = y[r] * y[r];
            #pragma unroll
            for (int o = 16; o; o >>= 1) {
                s += __shfl_xor_sync(0xffffffffu, s, o);
                q += __shfl_xor_sync(0xffffffffu, q, o);
            }
            if (lane == 0) { sred[tg][w4][r * 2] = s; sred[tg][w4][r * 2 + 1] = q; }
        }
        group_bar(tg);
        if (lj < 16) {
            float t = sred[tg][0][lj] + sred[tg][1][lj] +
                      sred[tg][2][lj] + sred[tg][3][lj];
            sfin[tg][lj >> 1][lj & 1] = t;
        }
        group_bar(tg);
        #pragma unroll
        for (int r = 0; r < 8; r++) {
            float mu  = sfin[tg][r][0] * (1.f / 128.f);
            float var = sfin[tg][r][1] * (1.f / 128.f) - mu * mu;
            float rs  = rsqrtf(var + LN_EPS);
            g_h[(size_t)(n0 + r) * D + lj] = (y[r] - mu) * rs * sg1[lj] + sbe[lj];
        }
    }
}

// --------------------------- stage 2 ----------------------------------------
// out = LN(nodes @ Wn^T + LN2(relu(h @ W2^T + b2)))
__global__ void __launch_bounds__(256, 1)
stage2_kernel(const float* __restrict__ nodes,
              const float* __restrict__ W2,
              const float* __restrict__ b2,
              const float* __restrict__ g2,
              const float* __restrict__ be2,
              const float* __restrict__ Wn,
              const float* __restrict__ gf,
              const float* __restrict__ bef,
              float* __restrict__ out) {
    extern __shared__ float sm[];
    float* sW2 = sm;                        // [128][WPAD]
    float* sWn = sW2 + D * WPAD;            // [128][WPAD]
    float* sX  = sWn + D * WPAD;            // per group: xh 8*128 + xn 8*128

    __shared__ float sb2[D], sg2[D], sbe2[D], sgf[D], sbef[D];
    __shared__ float sred[2][4][16];
    __shared__ float sfin[2][8][2];

    const int tid = threadIdx.x;
    if (tid < D) {
        sb2[tid] = b2[tid]; sg2[tid] = g2[tid]; sbe2[tid] = be2[tid];
        sgf[tid] = gf[tid]; sbef[tid] = bef[tid];
    }
    for (int i = tid; i < D * D; i += 256) {
        int j = i >> 7, k = i & 127;
        sW2[k * WPAD + j] = W2[j * D + k];
        sWn[k * WPAD + j] = Wn[j * D + k];
    }
    __syncthreads();

    const int tg   = tid >> 7;
    const int lj   = tid & 127;
    const int lane = tid & 31;
    const int w4   = (tid >> 5) & 3;

    float* xh = sX + tg * (16 * D);
    float* xn = xh + 8 * D;

    const int g0   = blockIdx.x * 2 + tg;
    const int step = gridDim.x * 2;

    for (int g = g0; g < NGROUPS; g += step) {
        const int n0 = g * 8;
        group_bar(tg);
        #pragma unroll
        for (int r = 0; r < 8; r++) {
            xh[r * D + lj] = g_h[(size_t)(n0 + r) * D + lj];
            xn[r * D + lj] = nodes[(size_t)(n0 + r) * D + lj];
        }
        group_bar(tg);

        // ---- t = relu(h @ W2^T + b2) ----
        float acc[8];
        #pragma unroll
        for (int r = 0; r < 8; r++) acc[r] = sb2[lj];
        for (int k = 0; k < D; k += 4) {
            float w0 = sW2[(k + 0) * WPAD + lj];
            float w1 = sW2[(k + 1) * WPAD + lj];
            float w2 = sW2[(k + 2) * WPAD + lj];
            float w3 = sW2[(k + 3) * WPAD + lj];
            #pragma unroll
            for (int r = 0; r < 8; r++) {
                float4 x = *reinterpret_cast<const float4*>(&xh[r * D + k]);
                acc[r] += x.x * w0 + x.y * w1 + x.z * w2 + x.w * w3;
            }
        }
        float u[8];
        #pragma unroll
        for (int r = 0; r < 8; r++) u[r] = fmaxf(acc[r], 0.f);

        // ---- LN2 ----
        #pragma unroll
        for (int r = 0; r < 8; r++) {
            float s = u[r], q = u[r] * u[r];
            #pragma unroll
            for (int o = 16; o; o >>= 1) {
                s += __shfl_xor_sync(0xffffffffu, s, o);
                q += __shfl_xor_sync(0xffffffffu, q, o);
            }
            if (lane == 0) { sred[tg][w4][r * 2] = s; sred[tg][w4][r * 2 + 1] = q; }
        }
        group_bar(tg);
        if (lj < 16) {
            float t = sred[tg][0][lj] + sred[tg][1][lj] +
                      sred[tg][2][lj] + sred[tg][3][lj];
            sfin[tg][lj >> 1][lj & 1] = t;
        }
        group_bar(tg);
        #pragma unroll
        for (int r = 0; r < 8; r++) {
            float mu  = sfin[tg][r][0] * (1.f / 128.f);
            float var = sfin[tg][r][1] * (1.f / 128.f) - mu * mu;
            float rs  = rsqrtf(var + LN_EPS);
            u[r] = (u[r] - mu) * rs * sg2[lj] + sbe2[lj];
        }

        // ---- p = nodes @ Wn^T;  v = p + u;  out = LN(v) ----
        #pragma unroll
        for (int r = 0; r < 8; r++) acc[r] = 0.f;
        for (int k = 0; k < D; k += 4) {
            float w0 = sWn[(k + 0) * WPAD + lj];
            float w1 = sWn[(k + 1) * WPAD + lj];
            float w2 = sWn[(k + 2) * WPAD + lj];
            float w3 = sWn[(k + 3) * WPAD + lj];
            #pragma unroll
            for (int r = 0; r < 8; r++) {
                float4 x = *reinterpret_cast<const float4*>(&xn[r * D + k]);
                acc[r] += x.x * w0 + x.y * w1 + x.z * w2 + x.w * w3;
            }
        }
        float v[8];
        #pragma unroll
        for (int r = 0; r < 8; r++) v[r] = acc[r] + u[r];

        #pragma unroll
        for (int r = 0; r < 8; r++) {
            float s = v[r], q = v[r] * v[r];
            #pragma unroll
            for (int o = 16; o; o >>= 1) {
                s += __shfl_xor_sync(0xffffffffu, s, o);
                q += __shfl_xor_sync(0xffffffffu, q, o);
            }
            if (lane == 0) { sred[tg][w4][r * 2] = s; sred[tg][w4][r * 2 + 1] = q; }
        }
        group_bar(tg);
        if (lj < 16) {
            float t = sred[tg][0][lj] + sred[tg][1][lj] +
                      sred[tg][2][lj] + sred[tg][3][lj];
            sfin[tg][lj >> 1][lj & 1] = t;
        }
        group_bar(tg);
        #pragma unroll
        for (int r = 0; r < 8; r++) {
            float mu  = sfin[tg][r][0] * (1.f / 128.f);
            float var = sfin[tg][r][1] * (1.f / 128.f) - mu * mu;
            float rs  = rsqrtf(var + LN_EPS);
            out[(size_t)(n0 + r) * D + lj] = (v[r] - mu) * rs * sgf[lj] + sbef[lj];
        }
    }
}

// --------------------------- launch -----------------------------------------
extern "C" void kernel_launch(void* const* d_in, const int* in_sizes, int n_in,
                              void* d_out, int out_size) {
    const float* nodes     = (const float*)d_in[0];
    const void*  eidx      = d_in[1];
    const float* edge_attr = (const float*)d_in[2];
    const float* Wm        = (const float*)d_in[3];
    const float* Wn        = (const float*)d_in[4];
    const float* W1        = (const float*)d_in[5];
    const float* b1        = (const float*)d_in[6];
    const float* g1        = (const float*)d_in[7];
    const float* be1       = (const float*)d_in[8];
    const float* W2        = (const float*)d_in[9];
    const float* b2        = (const float*)d_in[10];
    const float* g2        = (const float*)d_in[11];
    const float* be2       = (const float*)d_in[12];
    const float* gf        = (const float*)d_in[13];
    const float* bef       = (const float*)d_in[14];
    float* out = (float*)d_out;

    const int smem1 = (D * WPAD + AD * WPAD + 2 * (8 * D + 8 * AD)) * sizeof(float);
    const int smem2 = (2 * D * WPAD + 2 * 16 * D) * sizeof(float);
    cudaFuncSetAttribute(stage1_kernel, cudaFuncAttributeMaxDynamicSharedMemorySize, smem1);
    cudaFuncSetAttribute(stage2_kernel, cudaFuncAttributeMaxDynamicSharedMemorySize, smem2);

    detect_idx_kernel<<<1, 256>>>((const unsigned int*)eidx);
    convert_idx_kernel<<<(2 * N_EDGES + 255) / 256, 256>>>(eidx);
    zero_agg_kernel<<<2048, 256>>>();
    fuse_w_kernel<<<(D * AD + 255) / 256, 256>>>(W1, Wm);
    edge_scatter_kernel<<<(N_EDGES + 255) / 256, 256>>>(
        (const float4*)nodes, (const float4*)edge_attr);
    stage1_kernel<<<152, 256, smem1>>>(nodes, W1, b1, g1, be1);
    stage2_kernel<<<152, 256, smem2>>>(nodes, W2, b2, g2, be2, Wn, gf, bef, out);
}

// round 2
// speedup vs baseline: 1.3877x; 1.3877x over previous
#include <cuda_runtime.h>
#include <cuda_bf16.h>
#include <cstdint>

// ---------------------------------------------------------------------------
// LinearMessagePassingLayer — GB300 sm_103a
//
// Math restructuring:
//   agg_msg = segment_sum(concat(nodes[s], edge_attr) @ Wm^T, recv)
//           = segment_sum(concat(nodes[s], edge_attr), recv) @ Wm^T   (linearity)
//   node_input @ W1^T = nodes @ W1a^T + AGG @ (W1b @ Wm)^T            (fuse)
//
// Round 2: CSR pull instead of atomic scatter; 512-thread stage blocks.
// Pipeline:
//   detect idx dtype -> convert -> fuse Wf
//   CSR build: zero counts -> histogram(recv) -> 2-level scan -> fill eids
//   pull: AGG[n] = sum_{e: recv=n} [nodes[send] | edge_attr[e]]
//   stage1: h = LN1(relu(nodes@W1a^T + AGG@Wf^T + b1))
//   stage2: out = LN(nodes@Wn^T + LN2(relu(h@W2^T + b2)))
// ---------------------------------------------------------------------------

#define N_NODES 100000
#define N_EDGES 800000
#define D       128
#define ED      32
#define AD      160   // D + ED
#define NGROUPS (N_NODES / 8)   // 12500
#define LN_EPS  1e-5f
#define NB_SCAN ((N_NODES + 255) / 256)   // 391

// --------------------------- device scratch -------------------------------
__device__ float g_agg[(size_t)N_NODES * AD];   // 64 MB
__device__ float g_h[(size_t)N_NODES * D];      // 51.2 MB
__device__ float g_wf[D * AD];                  // fused W1b @ Wm
__device__ int   g_sr[2 * N_EDGES];             // senders | receivers (int32)
__device__ int   g_idx64;
__device__ int   g_cnt[N_NODES];                // degree counts -> running cursor
__device__ int   g_off[N_NODES + 1];            // CSR offsets
__device__ int   g_eid[N_EDGES];                // edge ids sorted by receiver
__device__ int   g_bsum[NB_SCAN];               // per-block count sums
__device__ int   g_boff[NB_SCAN];               // scanned block offsets

// --------------------------- helpers ---------------------------------------
__device__ __forceinline__ void group_bar(int tg) {
    asm volatile("bar.sync %0, 128;" :: "r"(tg + 1) : "memory");
}

// --------------------------- dtype detect / convert ------------------------
__global__ void detect_idx_kernel(const unsigned int* __restrict__ w) {
    __shared__ int anynz;
    if (threadIdx.x == 0) anynz = 0;
    __syncthreads();
    if (w[2 * threadIdx.x + 1] != 0u) atomicOr(&anynz, 1);
    __syncthreads();
    if (threadIdx.x == 0) g_idx64 = anynz ? 0 : 1;
}

__global__ void convert_idx_kernel(const void* __restrict__ p) {
    int i = blockIdx.x * blockDim.x + threadIdx.x;
    if (i >= 2 * N_EDGES) return;
    if (g_idx64)
        g_sr[i] = (int)((const long long*)p)[i];
    else
        g_sr[i] = ((const int*)p)[i];
}

// --------------------------- weight fusion ---------------------------------
// Wf[j][c] = sum_k W1[j][128+k] * Wm[k][c];  block j, thread c.
__global__ void __launch_bounds__(AD)
fuse_w_kernel(const float* __restrict__ W1, const float* __restrict__ Wm) {
    __shared__ float sw[D];
    int j = blockIdx.x, c = threadIdx.x;
    if (c < D) sw[c] = W1[j * (2 * D) + D + c];
    __syncthreads();
    float s = 0.f;
    #pragma unroll 8
    for (int k = 0; k < D; k++)
        s += sw[k] * __ldg(&Wm[k * AD + c]);
    g_wf[j * AD + c] = s;
}

// --------------------------- CSR build --------------------------------------
__global__ void zero_cnt_kernel() {
    int i = blockIdx.x * blockDim.x + threadIdx.x;
    if (i < N_NODES) g_cnt[i] = 0;
}

__global__ void hist_kernel() {
    int e = blockIdx.x * blockDim.x + threadIdx.x;
    if (e < N_EDGES) atomicAdd(&g_cnt[g_sr[N_EDGES + e]], 1);
}

__global__ void blocksum_kernel() {
    __shared__ int s[256];
    int i = blockIdx.x * 256 + threadIdx.x;
    int v = (i < N_NODES) ? g_cnt[i] : 0;
    s[threadIdx.x] = v;
    __syncthreads();
    #pragma unroll
    for (int o = 128; o; o >>= 1) {
        if (threadIdx.x < o) s[threadIdx.x] += s[threadIdx.x + o];
        __syncthreads();
    }
    if (threadIdx.x == 0) g_bsum[blockIdx.x] = s[0];
}

__global__ void scan_bsum_kernel() {
    __shared__ int s[512];
    int t = threadIdx.x;
    int v = (t < NB_SCAN) ? g_bsum[t] : 0;
    s[t] = v;
    __syncthreads();
    for (int o = 1; o < 512; o <<= 1) {
        int x = (t >= o) ? s[t - o] : 0;
        __syncthreads();
        s[t] += x;
        __syncthreads();
    }
    if (t < NB_SCAN) g_boff[t] = s[t] - v;   // exclusive
    if (t == 0) g_off[N_NODES] = N_EDGES;
}

__global__ void scatter_off_kernel() {
    __shared__ int s[256];
    int i = blockIdx.x * 256 + threadIdx.x;
    int t = threadIdx.x;
    int v = (i < N_NODES) ? g_cnt[i] : 0;
    s[t] = v;
    __syncthreads();
    for (int o = 1; o < 256; o <<= 1) {
        int x = (t >= o) ? s[t - o] : 0;
        __syncthreads();
        s[t] += x;
        __syncthreads();
    }
    if (i < N_NODES) {
        int off = g_boff[blockIdx.x] + s[t] - v;   // exclusive within block
        g_off[i] = off;
        g_cnt[i] = off;                             // reuse as cursor
    }
}

__global__ void fill_kernel() {
    int e = blockIdx.x * blockDim.x + threadIdx.x;
    if (e >= N_EDGES) return;
    int r = g_sr[N_EDGES + e];
    int pos = atomicAdd(&g_cnt[r], 1);
    g_eid[pos] = e;
}

// --------------------------- pull aggregation -------------------------------
// One warp per node; lane l owns dims {l, l+32, l+64, l+96} of the node part
// and dim l of the edge part.
__global__ void __launch_bounds__(256)
pull_kernel(const float* __restrict__ nodes, const float* __restrict__ ea) {
    int n = blockIdx.x * 8 + (threadIdx.x >> 5);
    if (n >= N_NODES) return;
    int lane = threadIdx.x & 31;
    int beg = g_off[n], end = g_off[n + 1];
    float a0 = 0.f, a1 = 0.f, a2 = 0.f, a3 = 0.f, a4 = 0.f;
    for (int i = beg; i < end; i++) {
        int e = __ldg(&g_eid[i]);
        int s = __ldg(&g_sr[e]);
        const float* nr = nodes + (size_t)s * D;
        a0 += __ldg(nr + lane);
        a1 += __ldg(nr + lane + 32);
        a2 += __ldg(nr + lane + 64);
        a3 += __ldg(nr + lane + 96);
        a4 += __ldg(ea + (size_t)e * ED + lane);
    }
    float* dst = g_agg + (size_t)n * AD;
    dst[lane]       = a0;
    dst[lane + 32]  = a1;
    dst[lane + 64]  = a2;
    dst[lane + 96]  = a3;
    dst[lane + 128] = a4;
}

// --------------------------- stage 1 ----------------------------------------
// 512 threads = 4 independent 128-thread groups sharing one smem weight copy.
#define WPAD 129

__global__ void __launch_bounds__(512, 1)
stage1_kernel(const float* __restrict__ nodes,
              const float* __restrict__ W1,
              const float* __restrict__ b1,
              const float* __restrict__ g1,
              const float* __restrict__ be1) {
    extern __shared__ float sm[];
    float* sW1 = sm;                        // [128][WPAD]  sW1[k*WPAD+j] = W1[j][k]
    float* sWf = sW1 + D * WPAD;            // [160][WPAD]  sWf[c*WPAD+j] = Wf[j][c]
    float* sX  = sWf + AD * WPAD;           // per group: 8*128 + 8*160 floats

    __shared__ float sb1[D], sg1[D], sbe[D];
    __shared__ float sred[4][4][16];
    __shared__ float sfin[4][8][2];

    const int tid = threadIdx.x;
    if (tid < D) { sb1[tid] = b1[tid]; sg1[tid] = g1[tid]; sbe[tid] = be1[tid]; }
    for (int i = tid; i < D * D; i += 512) {
        int j = i >> 7, k = i & 127;
        sW1[k * WPAD + j] = W1[j * (2 * D) + k];
    }
    for (int i = tid; i < D * AD; i += 512) {
        int j = i / AD, c = i - j * AD;
        sWf[c * WPAD + j] = g_wf[i];
    }
    __syncthreads();

    const int tg   = tid >> 7;
    const int lj   = tid & 127;
    const int lane = tid & 31;
    const int w4   = (tid >> 5) & 3;

    float* xn = sX + tg * (8 * D + 8 * AD);
    float* xa = xn + 8 * D;
    float4* xn4 = reinterpret_cast<float4*>(xn);
    float4* xa4 = reinterpret_cast<float4*>(xa);

    const int g0   = blockIdx.x * 4 + tg;
    const int step = gridDim.x * 4;

    for (int g = g0; g < NGROUPS; g += step) {
        const int n0 = g * 8;
        group_bar(tg);
        {
            const float4* src = reinterpret_cast<const float4*>(nodes) + (size_t)n0 * (D / 4);
            #pragma unroll
            for (int i = 0; i < 2; i++)
                xn4[lj + i * 128] = __ldg(src + lj + i * 128);
            const float4* srca = reinterpret_cast<const float4*>(g_agg) + (size_t)n0 * (AD / 4);
            #pragma unroll
            for (int i = 0; i < 3; i++) {
                int idx = lj + i * 128;
                if (idx < 8 * AD / 4) xa4[idx] = srca[idx];
            }
        }
        group_bar(tg);

        float acc[8];
        #pragma unroll
        for (int r = 0; r < 8; r++) acc[r] = sb1[lj];

        for (int k = 0; k < D; k += 4) {
            float w0 = sW1[(k + 0) * WPAD + lj];
            float w1 = sW1[(k + 1) * WPAD + lj];
            float w2 = sW1[(k + 2) * WPAD + lj];
            float w3 = sW1[(k + 3) * WPAD + lj];
            #pragma unroll
            for (int r = 0; r < 8; r++) {
                float4 x = *reinterpret_cast<const float4*>(&xn[r * D + k]);
                acc[r] += x.x * w0 + x.y * w1 + x.z * w2 + x.w * w3;
            }
        }
        for (int c = 0; c < AD; c += 4) {
            float w0 = sWf[(c + 0) * WPAD + lj];
            float w1 = sWf[(c + 1) * WPAD + lj];
            float w2 = sWf[(c + 2) * WPAD + lj];
            float w3 = sWf[(c + 3) * WPAD + lj];
            #pragma unroll
            for (int r = 0; r < 8; r++) {
                float4 x = *reinterpret_cast<const float4*>(&xa[r * AD + c]);
                acc[r] += x.x * w0 + x.y * w1 + x.z * w2 + x.w * w3;
            }
        }

        float y[8];
        #pragma unroll
        for (int r = 0; r < 8; r++) y[r] = fmaxf(acc[r], 0.f);

        #pragma unroll
        for (int r = 0; r < 8; r++) {
            float s = y[r], q = y[r] * y[r];
            #pragma unroll
            for (int o = 16; o; o >>= 1) {
                s += __shfl_xor_sync(0xffffffffu, s, o);
                q += __shfl_xor_sync(0xffffffffu, q, o);
            }
            if (lane == 0) { sred[tg][w4][r * 2] = s; sred[tg][w4][r * 2 + 1] = q; }
        }
        group_bar(tg);
        if (lj < 16) {
            float t = sred[tg][0][lj] + sred[tg][1][lj] +
                      sred[tg][2][lj] + sred[tg][3][lj];
            sfin[tg][lj >> 1][lj & 1] = t;
        }
        group_bar(tg);
        #pragma unroll
        for (int r = 0; r < 8; r++) {
            float mu  = sfin[tg][r][0] * (1.f / 128.f);
            float var = sfin[tg][r][1] * (1.f / 128.f) - mu * mu;
            float rs  = rsqrtf(var + LN_EPS);
            g_h[(size_t)(n0 + r) * D + lj] = (y[r] - mu) * rs * sg1[lj] + sbe[lj];
        }
    }
}

// --------------------------- stage 2 ----------------------------------------
__global__ void __launch_bounds__(512, 1)
stage2_kernel(const float* __restrict__ nodes,
              const float* __restrict__ W2,
              const float* __restrict__ b2,
              const float* __restrict__ g2,
              const float* __restrict__ be2,
              const float* __restrict__ Wn,
              const float* __restrict__ gf,
              const float* __restrict__ bef,
              float* __restrict__ out) {
    extern __shared__ float sm[];
    float* sW2 = sm;                        // [128][WPAD]
    float* sWn = sW2 + D * WPAD;            // [128][WPAD]
    float* sX  = sWn + D * WPAD;            // per group: 16*128 floats

    __shared__ float sb2[D], sg2[D], sbe2[D], sgf[D], sbef[D];
    __shared__ float sred[4][4][16];
    __shared__ float sfin[4][8][2];

    const int tid = threadIdx.x;
    if (tid < D) {
        sb2[tid] = b2[tid]; sg2[tid] = g2[tid]; sbe2[tid] = be2[tid];
        sgf[tid] = gf[tid]; sbef[tid] = bef[tid];
    }
    for (int i = tid; i < D * D; i += 512) {
        int j = i >> 7, k = i & 127;
        sW2[k * WPAD + j] = W2[j * D + k];
        sWn[k * WPAD + j] = Wn[j * D + k];
    }
    __syncthreads();

    const int tg   = tid >> 7;
    const int lj   = tid & 127;
    const int lane = tid & 31;
    const int w4   = (tid >> 5) & 3;

    float* xh = sX + tg * (16 * D);
    float* xn = xh + 8 * D;
    float4* xh4 = reinterpret_cast<float4*>(xh);
    float4* xn4 = reinterpret_cast<float4*>(xn);

    const int g0   = blockIdx.x * 4 + tg;
    const int step = gridDim.x * 4;

    for (int g = g0; g < NGROUPS; g += step) {
        const int n0 = g * 8;
        group_bar(tg);
        {
            const float4* srch = reinterpret_cast<const float4*>(g_h) + (size_t)n0 * (D / 4);
            const float4* srcn = reinterpret_cast<const float4*>(nodes) + (size_t)n0 * (D / 4);
            #pragma unroll
            for (int i = 0; i < 2; i++) {
                xh4[lj + i * 128] = srch[lj + i * 128];
                xn4[lj + i * 128] = __ldg(srcn + lj + i * 128);
            }
        }
        group_bar(tg);

        // ---- t = relu(h @ W2^T + b2) ----
        float acc[8];
        #pragma unroll
        for (int r = 0; r < 8; r++) acc[r] = sb2[lj];
        for (int k = 0; k < D; k += 4) {
            float w0 = sW2[(k + 0) * WPAD + lj];
            float w1 = sW2[(k + 1) * WPAD + lj];
            float w2 = sW2[(k + 2) * WPAD + lj];
            float w3 = sW2[(k + 3) * WPAD + lj];
            #pragma unroll
            for (int r = 0; r < 8; r++) {
                float4 x = *reinterpret_cast<const float4*>(&xh[r * D + k]);
                acc[r] += x.x * w0 + x.y * w1 + x.z * w2 + x.w * w3;
            }
        }
        float u[8];
        #pragma unroll
        for (int r = 0; r < 8; r++) u[r] = fmaxf(acc[r], 0.f);

        // ---- LN2 ----
        #pragma unroll
        for (int r = 0; r < 8; r++) {
            float s = u[r], q = u[r] * u[r];
            #pragma unroll
            for (int o = 16; o; o >>= 1) {
                s += __shfl_xor_sync(0xffffffffu, s, o);
                q += __shfl_xor_sync(0xffffffffu, q, o);
            }
            if (lane == 0) { sred[tg][w4][r * 2] = s; sred[tg][w4][r * 2 + 1] = q; }
        }
        group_bar(tg);
        if (lj < 16) {
            float t = sred[tg][0][lj] + sred[tg][1][lj] +
                      sred[tg][2][lj] + sred[tg][3][lj];
            sfin[tg][lj >> 1][lj & 1] = t;
        }
        group_bar(tg);
        #pragma unroll
        for (int r = 0; r < 8; r++) {
            float mu  = sfin[tg][r][0] * (1.f / 128.f);
            float var = sfin[tg][r][1] * (1.f / 128.f) - mu * mu;
            float rs  = rsqrtf(var + LN_EPS);
            u[r] = (u[r] - mu) * rs * sg2[lj] + sbe2[lj];
        }

        // ---- v = nodes @ Wn^T + u;  out = LN(v) ----
        #pragma unroll
        for (int r = 0; r < 8; r++) acc[r] = 0.f;
        for (int k = 0; k < D; k += 4) {
            float w0 = sWn[(k + 0) * WPAD + lj];
            float w1 = sWn[(k + 1) * WPAD + lj];
            float w2 = sWn[(k + 2) * WPAD + lj];
            float w3 = sWn[(k + 3) * WPAD + lj];
            #pragma unroll
            for (int r = 0; r < 8; r++) {
                float4 x = *reinterpret_cast<const float4*>(&xn[r * D + k]);
                acc[r] += x.x * w0 + x.y * w1 + x.z * w2 + x.w * w3;
            }
        }
        float v[8];
        #pragma unroll
        for (int r = 0; r < 8; r++) v[r] = acc[r] + u[r];

        #pragma unroll
        for (int r = 0; r < 8; r++) {
            float s = v[r], q = v[r] * v[r];
            #pragma unroll
            for (int o = 16; o; o >>= 1) {
                s += __shfl_xor_sync(0xffffffffu, s, o);
                q += __shfl_xor_sync(0xffffffffu, q, o);
            }
            if (lane == 0) { sred[tg][w4][r * 2] = s; sred[tg][w4][r * 2 + 1] = q; }
        }
        group_bar(tg);
        if (lj < 16) {
            float t = sred[tg][0][lj] + sred[tg][1][lj] +
                      sred[tg][2][lj] + sred[tg][3][lj];
            sfin[tg][lj >> 1][lj & 1] = t;
        }
        group_bar(tg);
        #pragma unroll
        for (int r = 0; r < 8; r++) {
            float mu  = sfin[tg][r][0] * (1.f / 128.f);
            float var = sfin[tg][r][1] * (1.f / 128.f) - mu * mu;
            float rs  = rsqrtf(var + LN_EPS);
            out[(size_t)(n0 + r) * D + lj] = (v[r] - mu) * rs * sgf[lj] + sbef[lj];
        }
    }
}

// --------------------------- launch -----------------------------------------
extern "C" void kernel_launch(void* const* d_in, const int* in_sizes, int n_in,
                              void* d_out, int out_size) {
    const float* nodes     = (const float*)d_in[0];
    const void*  eidx      = d_in[1];
    const float* edge_attr = (const float*)d_in[2];
    const float* Wm        = (const float*)d_in[3];
    const float* Wn        = (const float*)d_in[4];
    const float* W1        = (const float*)d_in[5];
    const float* b1        = (const float*)d_in[6];
    const float* g1        = (const float*)d_in[7];
    const float* be1       = (const float*)d_in[8];
    const float* W2        = (const float*)d_in[9];
    const float* b2        = (const float*)d_in[10];
    const float* g2        = (const float*)d_in[11];
    const float* be2       = (const float*)d_in[12];
    const float* gf        = (const float*)d_in[13];
    const float* bef       = (const float*)d_in[14];
    float* out = (float*)d_out;

    const int smem1 = (D * WPAD + AD * WPAD + 4 * (8 * D + 8 * AD)) * sizeof(float);
    const int smem2 = (2 * D * WPAD + 4 * 16 * D) * sizeof(float);
    cudaFuncSetAttribute(stage1_kernel, cudaFuncAttributeMaxDynamicSharedMemorySize, smem1);
    cudaFuncSetAttribute(stage2_kernel, cudaFuncAttributeMaxDynamicSharedMemorySize, smem2);

    detect_idx_kernel<<<1, 256>>>((const unsigned int*)eidx);
    convert_idx_kernel<<<(2 * N_EDGES + 255) / 256, 256>>>(eidx);
    fuse_w_kernel<<<D, AD>>>(W1, Wm);

    // CSR build
    zero_cnt_kernel<<<(N_NODES + 1023) / 1024, 1024>>>();
    hist_kernel<<<(N_EDGES + 255) / 256, 256>>>();
    blocksum_kernel<<<NB_SCAN, 256>>>();
    scan_bsum_kernel<<<1, 512>>>();
    scatter_off_kernel<<<NB_SCAN, 256>>>();
    fill_kernel<<<(N_EDGES + 255) / 256, 256>>>();

    // pull aggregation (one warp per node)
    pull_kernel<<<(N_NODES + 7) / 8, 256>>>(nodes, edge_attr);

    stage1_kernel<<<152, 512, smem1>>>(nodes, W1, b1, g1, be1);
    stage2_kernel<<<152, 512, smem2>>>(nodes, W2, b2, g2, be2, Wn, gf, bef, out);
}

// round 3
// speedup vs baseline: 2.8898x; 2.0825x over previous
#include <cuda_runtime.h>
#include <cuda_bf16.h>
#include <cstdint>

// ---------------------------------------------------------------------------
// LinearMessagePassingLayer — GB300 sm_103a, round 3: tensor-core node phase.
//
//   agg = segment_sum(concat(nodes[s], edge_attr), recv)        (CSR pull)
//   h   = LN1(relu(nodes@W1a^T + agg@(W1b@Wm)^T + b1))          (GEMM K=288)
//   out = LN(nodes@Wn^T + LN2(relu(h@W2^T + b2)))               (GEMMs K=128+128)
//
// GEMMs use mma.sync.m16n8k16 bf16 with 3-term split (hi+lo) for ~1e-5 accuracy.
// ---------------------------------------------------------------------------

#define N_NODES 100000
#define N_EDGES 800000
#define D       128
#define ED      32
#define AD      160
#define LN_EPS  1e-5f
#define NB_SCAN ((N_NODES + 255) / 256)   // 391

#define K1    288          // stage1 GEMM K (128 nodes + 160 agg)
#define KS1   18           // k16 steps
#define KP1   296          // smem A row pad (u16 elems) — conflict-free
#define KS2   8            // stage2 GEMM k-steps (K=128)
#define KP2   136
#define NGRP  ((N_NODES + 127) / 128)     // 782

// --------------------------- device scratch -------------------------------
__device__ float    g_agg[(size_t)N_NODES * AD];
__device__ uint16_t g_hhi[(size_t)N_NODES * D];
__device__ uint16_t g_hlo[(size_t)N_NODES * D];
__device__ float    g_wf[D * AD];
__device__ uint16_t g_w1hi[KS1 * D * 16], g_w1lo[KS1 * D * 16];
__device__ uint16_t g_w2hi[KS2 * D * 16], g_w2lo[KS2 * D * 16];
__device__ uint16_t g_wnhi[KS2 * D * 16], g_wnlo[KS2 * D * 16];
__device__ int      g_sr[2 * N_EDGES];
__device__ int      g_idx64;
__device__ int      g_cnt[N_NODES];
__device__ int      g_off[N_NODES + 1];
__device__ int      g_eid[N_EDGES];
__device__ int      g_bsum[NB_SCAN];
__device__ int      g_boff[NB_SCAN];

// --------------------------- helpers ---------------------------------------
__device__ __forceinline__ uint16_t f2bf(float x) {
    __nv_bfloat16 h = __float2bfloat16(x);
    return *reinterpret_cast<uint16_t*>(&h);
}
__device__ __forceinline__ float bf2f(uint16_t b) {
    __nv_bfloat16 h = *reinterpret_cast<__nv_bfloat16*>(&b);
    return __bfloat162float(h);
}

__device__ __forceinline__ void mma_bf16(float (&c)[4], const uint32_t (&a)[4],
                                         const uint32_t (&b)[2]) {
    asm volatile(
        "mma.sync.aligned.m16n8k16.row.col.f32.bf16.bf16.f32 "
        "{%0,%1,%2,%3},{%4,%5,%6,%7},{%8,%9},{%0,%1,%2,%3};\n"
        : "+f"(c[0]), "+f"(c[1]), "+f"(c[2]), "+f"(c[3])
        : "r"(a[0]), "r"(a[1]), "r"(a[2]), "r"(a[3]), "r"(b[0]), "r"(b[1]));
}

// convert float4 -> bf16 hi/lo, store 4 consecutive k elems (u32-packed pairs)
__device__ __forceinline__ void cvt_store(uint16_t* hi, uint16_t* lo, int off, float4 v) {
    uint16_t h0 = f2bf(v.x), h1 = f2bf(v.y), h2 = f2bf(v.z), h3 = f2bf(v.w);
    uint16_t l0 = f2bf(v.x - bf2f(h0)), l1 = f2bf(v.y - bf2f(h1));
    uint16_t l2 = f2bf(v.z - bf2f(h2)), l3 = f2bf(v.w - bf2f(h3));
    *(uint32_t*)(hi + off)     = ((uint32_t)h1 << 16) | h0;
    *(uint32_t*)(hi + off + 2) = ((uint32_t)h3 << 16) | h2;
    *(uint32_t*)(lo + off)     = ((uint32_t)l1 << 16) | l0;
    *(uint32_t*)(lo + off + 2) = ((uint32_t)l3 << 16) | l2;
}

// B fragments for one k-step: 8 n-frags, hi+lo
__device__ __forceinline__ void load_bfrag(const uint16_t* __restrict__ whi,
                                           const uint16_t* __restrict__ wlo,
                                           int ks, int nbase, int qr, int qk,
                                           uint32_t (&bh)[8][2], uint32_t (&bl)[8][2]) {
#pragma unroll
    for (int nf = 0; nf < 8; nf++) {
        const uint16_t* p = whi + ((size_t)ks * D + nbase + nf * 8 + qr) * 16 + qk;
        bh[nf][0] = *(const uint32_t*)p;
        bh[nf][1] = *(const uint32_t*)(p + 8);
        const uint16_t* q = wlo + ((size_t)ks * D + nbase + nf * 8 + qr) * 16 + qk;
        bl[nf][0] = *(const uint32_t*)q;
        bl[nf][1] = *(const uint32_t*)(q + 8);
    }
}

__device__ __forceinline__ void load_afrag(const uint16_t* sA, int kp, int row0,
                                           int ks, int qk, uint32_t (&a)[4]) {
    const uint16_t* p = sA + row0 * kp + ks * 16 + qk;
    a[0] = *(const uint32_t*)p;
    a[1] = *(const uint32_t*)(p + 8 * kp);
    a[2] = *(const uint32_t*)(p + 8);
    a[3] = *(const uint32_t*)(p + 8 * kp + 8);
}

__device__ __forceinline__ void mma_step(float (&acc)[2][8][4],
                                         const uint16_t* sAhi, const uint16_t* sAlo,
                                         int kp, int rbase, int ks, int qk,
                                         const uint32_t (&bh)[8][2],
                                         const uint32_t (&bl)[8][2]) {
#pragma unroll
    for (int mf = 0; mf < 2; mf++) {
        uint32_t ah[4], al[4];
        load_afrag(sAhi, kp, rbase + mf * 16, ks, qk, ah);
        load_afrag(sAlo, kp, rbase + mf * 16, ks, qk, al);
#pragma unroll
        for (int nf = 0; nf < 8; nf++) {
            mma_bf16(acc[mf][nf], ah, bh[nf]);
            mma_bf16(acc[mf][nf], ah, bl[nf]);
            mma_bf16(acc[mf][nf], al, bh[nf]);
        }
    }
}

// --------------------------- dtype detect / convert ------------------------
__global__ void detect_idx_kernel(const unsigned int* __restrict__ w) {
    __shared__ int anynz;
    if (threadIdx.x == 0) anynz = 0;
    __syncthreads();
    if (w[2 * threadIdx.x + 1] != 0u) atomicOr(&anynz, 1);
    __syncthreads();
    if (threadIdx.x == 0) g_idx64 = anynz ? 0 : 1;
}

__global__ void convert_idx_kernel(const void* __restrict__ p) {
    int i = blockIdx.x * blockDim.x + threadIdx.x;
    if (i >= 2 * N_EDGES) return;
    if (g_idx64)
        g_sr[i] = (int)((const long long*)p)[i];
    else
        g_sr[i] = ((const int*)p)[i];
}

// --------------------------- weight fusion / prep --------------------------
__global__ void __launch_bounds__(AD)
fuse_w_kernel(const float* __restrict__ W1, const float* __restrict__ Wm) {
    __shared__ float sw[D];
    int j = blockIdx.x, c = threadIdx.x;
    if (c < D) sw[c] = W1[j * (2 * D) + D + c];
    __syncthreads();
    float s = 0.f;
    #pragma unroll 8
    for (int k = 0; k < D; k++)
        s += sw[k] * __ldg(&Wm[k * AD + c]);
    g_wf[j * AD + c] = s;
}

// pack Wcat = [W1a | Wf] (128 x 288) into frag layout [ks][n][16], hi/lo
__global__ void prep_w1_kernel(const float* __restrict__ W1) {
    int idx = blockIdx.x * 256 + threadIdx.x;
    if (idx >= KS1 * D * 16) return;
    int koff = idx & 15, n = (idx >> 4) & 127, ks = idx >> 11;
    int k = ks * 16 + koff;
    float v = (k < D) ? W1[n * (2 * D) + k] : g_wf[n * AD + (k - D)];
    uint16_t hi = f2bf(v);
    g_w1hi[idx] = hi;
    g_w1lo[idx] = f2bf(v - bf2f(hi));
}

__global__ void prep_w2_kernel(const float* __restrict__ W2,
                               const float* __restrict__ Wn) {
    int idx = blockIdx.x * 256 + threadIdx.x;
    if (idx >= KS2 * D * 16) return;
    int koff = idx & 15, n = (idx >> 4) & 127, ks = idx >> 11;
    int k = ks * 16 + koff;
    float v2 = W2[n * D + k];
    uint16_t h2 = f2bf(v2);
    g_w2hi[idx] = h2;
    g_w2lo[idx] = f2bf(v2 - bf2f(h2));
    float vn = Wn[n * D + k];
    uint16_t hn = f2bf(vn);
    g_wnhi[idx] = hn;
    g_wnlo[idx] = f2bf(vn - bf2f(hn));
}

// --------------------------- CSR build --------------------------------------
__global__ void zero_cnt_kernel() {
    int i = blockIdx.x * blockDim.x + threadIdx.x;
    if (i < N_NODES) g_cnt[i] = 0;
}

__global__ void hist_kernel() {
    int e = blockIdx.x * blockDim.x + threadIdx.x;
    if (e < N_EDGES) atomicAdd(&g_cnt[g_sr[N_EDGES + e]], 1);
}

__global__ void blocksum_kernel() {
    __shared__ int s[256];
    int i = blockIdx.x * 256 + threadIdx.x;
    int v = (i < N_NODES) ? g_cnt[i] : 0;
    s[threadIdx.x] = v;
    __syncthreads();
    #pragma unroll
    for (int o = 128; o; o >>= 1) {
        if (threadIdx.x < o) s[threadIdx.x] += s[threadIdx.x + o];
        __syncthreads();
    }
    if (threadIdx.x == 0) g_bsum[blockIdx.x] = s[0];
}

__global__ void scan_bsum_kernel() {
    __shared__ int s[512];
    int t = threadIdx.x;
    int v = (t < NB_SCAN) ? g_bsum[t] : 0;
    s[t] = v;
    __syncthreads();
    for (int o = 1; o < 512; o <<= 1) {
        int x = (t >= o) ? s[t - o] : 0;
        __syncthreads();
        s[t] += x;
        __syncthreads();
    }
    if (t < NB_SCAN) g_boff[t] = s[t] - v;
    if (t == 0) g_off[N_NODES] = N_EDGES;
}

__global__ void scatter_off_kernel() {
    __shared__ int s[256];
    int i = blockIdx.x * 256 + threadIdx.x;
    int t = threadIdx.x;
    int v = (i < N_NODES) ? g_cnt[i] : 0;
    s[t] = v;
    __syncthreads();
    for (int o = 1; o < 256; o <<= 1) {
        int x = (t >= o) ? s[t - o] : 0;
        __syncthreads();
        s[t] += x;
        __syncthreads();
    }
    if (i < N_NODES) {
        int off = g_boff[blockIdx.x] + s[t] - v;
        g_off[i] = off;
        g_cnt[i] = off;
    }
}

__global__ void fill_kernel() {
    int e = blockIdx.x * blockDim.x + threadIdx.x;
    if (e >= N_EDGES) return;
    int r = g_sr[N_EDGES + e];
    int pos = atomicAdd(&g_cnt[r], 1);
    g_eid[pos] = e;
}

// --------------------------- pull aggregation -------------------------------
__global__ void __launch_bounds__(256)
pull_kernel(const float* __restrict__ nodes, const float* __restrict__ ea) {
    int n = blockIdx.x * 8 + (threadIdx.x >> 5);
    if (n >= N_NODES) return;
    int lane = threadIdx.x & 31;
    int beg = g_off[n], end = g_off[n + 1];
    float a0 = 0.f, a1 = 0.f, a2 = 0.f, a3 = 0.f, a4 = 0.f;
    for (int i = beg; i < end; i++) {
        int e = __ldg(&g_eid[i]);
        int s = __ldg(&g_sr[e]);
        const float* nr = nodes + (size_t)s * D;
        a0 += __ldg(nr + lane);
        a1 += __ldg(nr + lane + 32);
        a2 += __ldg(nr + lane + 64);
        a3 += __ldg(nr + lane + 96);
        a4 += __ldg(ea + (size_t)e * ED + lane);
    }
    float* dst = g_agg + (size_t)n * AD;
    dst[lane]       = a0;
    dst[lane + 32]  = a1;
    dst[lane + 64]  = a2;
    dst[lane + 96]  = a3;
    dst[lane + 128] = a4;
}

// --------------------------- stage 1 (tensor) --------------------------------
// h = LN1(relu([nodes|agg] @ [W1a|Wf]^T + b1)); h written as bf16 hi/lo.
__global__ void __launch_bounds__(256, 1)
stage1_mma_kernel(const float* __restrict__ nodes,
                  const float* __restrict__ b1,
                  const float* __restrict__ g1,
                  const float* __restrict__ be1) {
    extern __shared__ uint16_t smu[];
    uint16_t* sAhi = smu;
    uint16_t* sAlo = smu + 128 * KP1;

    __shared__ float sb1[D], sg1[D], sbe1[D];
    __shared__ float sredS[D][2], sredQ[D][2];

    const int tid = threadIdx.x;
    const int n0 = blockIdx.x * 128;
    if (tid < D) { sb1[tid] = b1[tid]; sg1[tid] = g1[tid]; sbe1[tid] = be1[tid]; }

    // ---- load + convert A = [nodes | agg] ----
    const float4* nsrc = (const float4*)nodes;
    #pragma unroll
    for (int it = 0; it < 16; it++) {
        int idx = it * 256 + tid;
        int row = idx >> 5, c4 = idx & 31;
        float4 v = make_float4(0.f, 0.f, 0.f, 0.f);
        if (n0 + row < N_NODES) v = __ldg(nsrc + (size_t)(n0 + row) * 32 + c4);
        cvt_store(sAhi, sAlo, row * KP1 + c4 * 4, v);
    }
    const float4* asrc = (const float4*)g_agg;
    #pragma unroll
    for (int it = 0; it < 20; it++) {
        int idx = it * 256 + tid;
        int row = idx / 40, c4 = idx % 40;
        float4 v = make_float4(0.f, 0.f, 0.f, 0.f);
        if (n0 + row < N_NODES) v = asrc[(size_t)(n0 + row) * 40 + c4];
        cvt_store(sAhi, sAlo, row * KP1 + 128 + c4 * 4, v);
    }
    __syncthreads();

    // ---- GEMM ----
    const int lane = tid & 31;
    const int wid  = tid >> 5;
    const int wm   = wid >> 1, wn = wid & 1;
    const int qr   = lane >> 2;
    const int qk   = 2 * (lane & 3);
    const int rbase = wm * 32 + qr;
    const int nbase = wn * 64;

    float acc[2][8][4];
    #pragma unroll
    for (int mf = 0; mf < 2; mf++)
        #pragma unroll
        for (int nf = 0; nf < 8; nf++)
            #pragma unroll
            for (int i = 0; i < 4; i++) acc[mf][nf][i] = 0.f;

    uint32_t bh0[8][2], bl0[8][2], bh1[8][2], bl1[8][2];
    load_bfrag(g_w1hi, g_w1lo, 0, nbase, qr, qk, bh0, bl0);
    #pragma unroll 1
    for (int ks = 0; ks < KS1; ks += 2) {
        load_bfrag(g_w1hi, g_w1lo, ks + 1, nbase, qr, qk, bh1, bl1);
        mma_step(acc, sAhi, sAlo, KP1, rbase, ks, qk, bh0, bl0);
        if (ks + 2 < KS1)
            load_bfrag(g_w1hi, g_w1lo, ks + 2, nbase, qr, qk, bh0, bl0);
        mma_step(acc, sAhi, sAlo, KP1, rbase, ks + 1, qk, bh1, bl1);
    }

    // ---- bias + relu ----
    float vals[2][8][4];
    #pragma unroll
    for (int mf = 0; mf < 2; mf++)
        #pragma unroll
        for (int nf = 0; nf < 8; nf++) {
            int c = nbase + nf * 8 + qk;
            vals[mf][nf][0] = fmaxf(acc[mf][nf][0] + sb1[c], 0.f);
            vals[mf][nf][1] = fmaxf(acc[mf][nf][1] + sb1[c + 1], 0.f);
            vals[mf][nf][2] = fmaxf(acc[mf][nf][2] + sb1[c], 0.f);
            vals[mf][nf][3] = fmaxf(acc[mf][nf][3] + sb1[c + 1], 0.f);
        }

    // ---- row reductions (quad shfl + 2-warp smem combine) ----
    #pragma unroll
    for (int mf = 0; mf < 2; mf++)
        #pragma unroll
        for (int h = 0; h < 2; h++) {
            float s = 0.f, q = 0.f;
            #pragma unroll
            for (int nf = 0; nf < 8; nf++) {
                float v0 = vals[mf][nf][2 * h], v1 = vals[mf][nf][2 * h + 1];
                s += v0 + v1; q += v0 * v0 + v1 * v1;
            }
            s += __shfl_xor_sync(0xffffffffu, s, 1);
            s += __shfl_xor_sync(0xffffffffu, s, 2);
            q += __shfl_xor_sync(0xffffffffu, q, 1);
            q += __shfl_xor_sync(0xffffffffu, q, 2);
            int r = wm * 32 + mf * 16 + h * 8 + qr;
            if ((lane & 3) == 0) { sredS[r][wn] = s; sredQ[r][wn] = q; }
        }
    __syncthreads();

    // ---- LN1 + store h (bf16 hi/lo) ----
    #pragma unroll
    for (int mf = 0; mf < 2; mf++)
        #pragma unroll
        for (int h = 0; h < 2; h++) {
            int r = wm * 32 + mf * 16 + h * 8 + qr;
            int node = n0 + r;
            if (node >= N_NODES) continue;
            float S = sredS[r][0] + sredS[r][1];
            float Q = sredQ[r][0] + sredQ[r][1];
            float mu = S * (1.f / 128.f);
            float var = Q * (1.f / 128.f) - mu * mu;
            float rs = rsqrtf(var + LN_EPS);
            #pragma unroll
            for (int nf = 0; nf < 8; nf++) {
                int c = nbase + nf * 8 + qk;
                float y0 = (vals[mf][nf][2 * h] - mu) * rs * sg1[c] + sbe1[c];
                float y1 = (vals[mf][nf][2 * h + 1] - mu) * rs * sg1[c + 1] + sbe1[c + 1];
                uint16_t h0 = f2bf(y0), h1 = f2bf(y1);
                uint16_t l0 = f2bf(y0 - bf2f(h0)), l1 = f2bf(y1 - bf2f(h1));
                *(uint32_t*)(g_hhi + (size_t)node * D + c) = ((uint32_t)h1 << 16) | h0;
                *(uint32_t*)(g_hlo + (size_t)node * D + c) = ((uint32_t)l1 << 16) | l0;
            }
        }
}

// --------------------------- stage 2 (tensor) --------------------------------
// out = LN(nodes @ Wn^T + LN2(relu(h @ W2^T + b2)))
__global__ void __launch_bounds__(256, 1)
stage2_mma_kernel(const float* __restrict__ nodes,
                  const float* __restrict__ b2,
                  const float* __restrict__ g2,
                  const float* __restrict__ be2,
                  const float* __restrict__ gf,
                  const float* __restrict__ bef,
                  float* __restrict__ out) {
    extern __shared__ uint16_t smu[];
    uint16_t* sHhi = smu;
    uint16_t* sHlo = sHhi + 128 * KP2;
    uint16_t* sNhi = sHlo + 128 * KP2;
    uint16_t* sNlo = sNhi + 128 * KP2;

    __shared__ float sb2[D], sg2[D], sbe2[D], sgf[D], sbef[D];
    __shared__ float sredS[D][2], sredQ[D][2];

    const int tid = threadIdx.x;
    const int n0 = blockIdx.x * 128;
    if (tid < D) {
        sb2[tid] = b2[tid]; sg2[tid] = g2[tid]; sbe2[tid] = be2[tid];
        sgf[tid] = gf[tid]; sbef[tid] = bef[tid];
    }

    // ---- load h (already bf16 hi/lo) ----
    #pragma unroll
    for (int it = 0; it < 16; it++) {
        int idx = it * 256 + tid;                  // 0..4095
        int row = idx >> 5, j = idx & 31;          // 32 uint2 per row
        uint2 vh = make_uint2(0u, 0u), vl = make_uint2(0u, 0u);
        if (n0 + row < N_NODES) {
            vh = *(const uint2*)(g_hhi + (size_t)(n0 + row) * D + j * 4);
            vl = *(const uint2*)(g_hlo + (size_t)(n0 + row) * D + j * 4);
        }
        *(uint2*)(sHhi + row * KP2 + j * 4) = vh;
        *(uint2*)(sHlo + row * KP2 + j * 4) = vl;
    }
    // ---- load + convert nodes ----
    const float4* nsrc = (const float4*)nodes;
    #pragma unroll
    for (int it = 0; it < 16; it++) {
        int idx = it * 256 + tid;
        int row = idx >> 5, c4 = idx & 31;
        float4 v = make_float4(0.f, 0.f, 0.f, 0.f);
        if (n0 + row < N_NODES) v = __ldg(nsrc + (size_t)(n0 + row) * 32 + c4);
        cvt_store(sNhi, sNlo, row * KP2 + c4 * 4, v);
    }
    __syncthreads();

    const int lane = tid & 31;
    const int wid  = tid >> 5;
    const int wm   = wid >> 1, wn = wid & 1;
    const int qr   = lane >> 2;
    const int qk   = 2 * (lane & 3);
    const int rbase = wm * 32 + qr;
    const int nbase = wn * 64;

    // ---- GEMM 1: h @ W2^T ----
    float acc[2][8][4];
    #pragma unroll
    for (int mf = 0; mf < 2; mf++)
        #pragma unroll
        for (int nf = 0; nf < 8; nf++)
            #pragma unroll
            for (int i = 0; i < 4; i++) acc[mf][nf][i] = 0.f;

    {
        uint32_t bh[8][2], bl[8][2];
        #pragma unroll 1
        for (int ks = 0; ks < KS2; ks++) {
            load_bfrag(g_w2hi, g_w2lo, ks, nbase, qr, qk, bh, bl);
            mma_step(acc, sHhi, sHlo, KP2, rbase, ks, qk, bh, bl);
        }
    }

    // ---- bias + relu -> uvals ----
    float uvals[2][8][4];
    #pragma unroll
    for (int mf = 0; mf < 2; mf++)
        #pragma unroll
        for (int nf = 0; nf < 8; nf++) {
            int c = nbase + nf * 8 + qk;
            uvals[mf][nf][0] = fmaxf(acc[mf][nf][0] + sb2[c], 0.f);
            uvals[mf][nf][1] = fmaxf(acc[mf][nf][1] + sb2[c + 1], 0.f);
            uvals[mf][nf][2] = fmaxf(acc[mf][nf][2] + sb2[c], 0.f);
            uvals[mf][nf][3] = fmaxf(acc[mf][nf][3] + sb2[c + 1], 0.f);
        }

    // ---- LN2 reductions ----
    #pragma unroll
    for (int mf = 0; mf < 2; mf++)
        #pragma unroll
        for (int h = 0; h < 2; h++) {
            float s = 0.f, q = 0.f;
            #pragma unroll
            for (int nf = 0; nf < 8; nf++) {
                float v0 = uvals[mf][nf][2 * h], v1 = uvals[mf][nf][2 * h + 1];
                s += v0 + v1; q += v0 * v0 + v1 * v1;
            }
            s += __shfl_xor_sync(0xffffffffu, s, 1);
            s += __shfl_xor_sync(0xffffffffu, s, 2);
            q += __shfl_xor_sync(0xffffffffu, q, 1);
            q += __shfl_xor_sync(0xffffffffu, q, 2);
            int r = wm * 32 + mf * 16 + h * 8 + qr;
            if ((lane & 3) == 0) { sredS[r][wn] = s; sredQ[r][wn] = q; }
        }
    __syncthreads();

    #pragma unroll
    for (int mf = 0; mf < 2; mf++)
        #pragma unroll
        for (int h = 0; h < 2; h++) {
            int r = wm * 32 + mf * 16 + h * 8 + qr;
            float S = sredS[r][0] + sredS[r][1];
            float Q = sredQ[r][0] + sredQ[r][1];
            float mu = S * (1.f / 128.f);
            float var = Q * (1.f / 128.f) - mu * mu;
            float rs = rsqrtf(var + LN_EPS);
            #pragma unroll
            for (int nf = 0; nf < 8; nf++) {
                int c = nbase + nf * 8 + qk;
                uvals[mf][nf][2 * h]     = (uvals[mf][nf][2 * h] - mu) * rs * sg2[c] + sbe2[c];
                uvals[mf][nf][2 * h + 1] = (uvals[mf][nf][2 * h + 1] - mu) * rs * sg2[c + 1] + sbe2[c + 1];
            }
        }
    __syncthreads();   // protect sred reuse below

    // ---- GEMM 2: nodes @ Wn^T (reuse acc) ----
    #pragma unroll
    for (int mf = 0; mf < 2; mf++)
        #pragma unroll
        for (int nf = 0; nf < 8; nf++)
            #pragma unroll
            for (int i = 0; i < 4; i++) acc[mf][nf][i] = 0.f;
    {
        uint32_t bh[8][2], bl[8][2];
        #pragma unroll 1
        for (int ks = 0; ks < KS2; ks++) {
            load_bfrag(g_wnhi, g_wnlo, ks, nbase, qr, qk, bh, bl);
            mma_step(acc, sNhi, sNlo, KP2, rbase, ks, qk, bh, bl);
        }
    }

    // ---- v = acc + u; final LN reductions ----
    #pragma unroll
    for (int mf = 0; mf < 2; mf++)
        #pragma unroll
        for (int nf = 0; nf < 8; nf++)
            #pragma unroll
            for (int i = 0; i < 4; i++)
                uvals[mf][nf][i] += acc[mf][nf][i];

    #pragma unroll
    for (int mf = 0; mf < 2; mf++)
        #pragma unroll
        for (int h = 0; h < 2; h++) {
            float s = 0.f, q = 0.f;
            #pragma unroll
            for (int nf = 0; nf < 8; nf++) {
                float v0 = uvals[mf][nf][2 * h], v1 = uvals[mf][nf][2 * h + 1];
                s += v0 + v1; q += v0 * v0 + v1 * v1;
            }
            s += __shfl_xor_sync(0xffffffffu, s, 1);
            s += __shfl_xor_sync(0xffffffffu, s, 2);
            q += __shfl_xor_sync(0xffffffffu, q, 1);
            q += __shfl_xor_sync(0xffffffffu, q, 2);
            int r = wm * 32 + mf * 16 + h * 8 + qr;
            if ((lane & 3) == 0) { sredS[r][wn] = s; sredQ[r][wn] = q; }
        }
    __syncthreads();

    // ---- final LN + store f32 ----
    #pragma unroll
    for (int mf = 0; mf < 2; mf++)
        #pragma unroll
        for (int h = 0; h < 2; h++) {
            int r = wm * 32 + mf * 16 + h * 8 + qr;
            int node = n0 + r;
            if (node >= N_NODES) continue;
            float S = sredS[r][0] + sredS[r][1];
            float Q = sredQ[r][0] + sredQ[r][1];
            float mu = S * (1.f / 128.f);
            float var = Q * (1.f / 128.f) - mu * mu;
            float rs = rsqrtf(var + LN_EPS);
            #pragma unroll
            for (int nf = 0; nf < 8; nf++) {
                int c = nbase + nf * 8 + qk;
                float2 o;
                o.x = (uvals[mf][nf][2 * h] - mu) * rs * sgf[c] + sbef[c];
                o.y = (uvals[mf][nf][2 * h + 1] - mu) * rs * sgf[c + 1] + sbef[c + 1];
                *(float2*)(out + (size_t)node * D + c) = o;
            }
        }
}

// --------------------------- launch -----------------------------------------
extern "C" void kernel_launch(void* const* d_in, const int* in_sizes, int n_in,
                              void* d_out, int out_size) {
    const float* nodes     = (const float*)d_in[0];
    const void*  eidx      = d_in[1];
    const float* edge_attr = (const float*)d_in[2];
    const float* Wm        = (const float*)d_in[3];
    const float* Wn        = (const float*)d_in[4];
    const float* W1        = (const float*)d_in[5];
    const float* b1        = (const float*)d_in[6];
    const float* g1        = (const float*)d_in[7];
    const float* be1       = (const float*)d_in[8];
    const float* W2        = (const float*)d_in[9];
    const float* b2        = (const float*)d_in[10];
    const float* g2        = (const float*)d_in[11];
    const float* be2       = (const float*)d_in[12];
    const float* gf        = (const float*)d_in[13];
    const float* bef       = (const float*)d_in[14];
    float* out = (float*)d_out;

    const int smem1 = 128 * KP1 * 2 * (int)sizeof(uint16_t);   // 151552
    const int smem2 = 4 * 128 * KP2 * (int)sizeof(uint16_t);   // 139264
    cudaFuncSetAttribute(stage1_mma_kernel, cudaFuncAttributeMaxDynamicSharedMemorySize, smem1);
    cudaFuncSetAttribute(stage2_mma_kernel, cudaFuncAttributeMaxDynamicSharedMemorySize, smem2);

    detect_idx_kernel<<<1, 256>>>((const unsigned int*)eidx);
    convert_idx_kernel<<<(2 * N_EDGES + 255) / 256, 256>>>(eidx);
    fuse_w_kernel<<<D, AD>>>(W1, Wm);
    prep_w1_kernel<<<(KS1 * D * 16 + 255) / 256, 256>>>(W1);
    prep_w2_kernel<<<(KS2 * D * 16 + 255) / 256, 256>>>(W2, Wn);

    // CSR build
    zero_cnt_kernel<<<(N_NODES + 1023) / 1024, 1024>>>();
    hist_kernel<<<(N_EDGES + 255) / 256, 256>>>();
    blocksum_kernel<<<NB_SCAN, 256>>>();
    scan_bsum_kernel<<<1, 512>>>();
    scatter_off_kernel<<<NB_SCAN, 256>>>();
    fill_kernel<<<(N_EDGES + 255) / 256, 256>>>();

    // pull aggregation
    pull_kernel<<<(N_NODES + 7) / 8, 256>>>(nodes, edge_attr);

    // node phase on tensor cores
    stage1_mma_kernel<<<NGRP, 256, smem1>>>(nodes, b1, g1, be1);
    stage2_mma_kernel<<<NGRP, 256, smem2>>>(nodes, b2, g2, be2, gf, bef, out);
}

// round 4
// speedup vs baseline: 3.2538x; 1.1259x over previous
#include <cuda_runtime.h>
#include <cuda_bf16.h>
#include <cstdint>

// ---------------------------------------------------------------------------
// LinearMessagePassingLayer — GB300 sm_103a, round 4.
//
//   agg = segment_sum(concat(nodes[s], edge_attr), recv)       (CSR pull, f4)
//   node phase (single fused kernel, h stays in smem):
//     h   = LN1(relu([nodes|agg] @ [W1a|W1b@Wm]^T + b1))
//     out = LN(nodes@Wn^T + LN2(relu(h@W2^T + b2)))
//
// GEMMs: mma.sync.m16n8k16 bf16, 3-term hi/lo split (~1e-5 accuracy).
// ---------------------------------------------------------------------------

#define N_NODES 100000
#define N_EDGES 800000
#define D       128
#define ED      32
#define AD      160
#define LN_EPS  1e-5f
#define NB_SCAN ((N_NODES + 255) / 256)   // 391

#define KS1   18           // stage1 GEMM k16 steps (K=288)
#define KP1   296          // smem A row stride (u16) — conflict-free
#define KS2   8            // K=128 GEMM k-steps
#define NGRP  ((N_NODES + 127) / 128)     // 782

// --------------------------- device scratch -------------------------------
__device__ float    g_agg[(size_t)N_NODES * AD];
__device__ float    g_wf[D * AD];
__device__ uint16_t g_w1hi[KS1 * D * 16], g_w1lo[KS1 * D * 16];
__device__ uint16_t g_w2hi[KS2 * D * 16], g_w2lo[KS2 * D * 16];
__device__ uint16_t g_wnhi[KS2 * D * 16], g_wnlo[KS2 * D * 16];
__device__ int      g_sr[2 * N_EDGES];      // senders | receivers
__device__ int      g_cnt[N_NODES];
__device__ int      g_off[N_NODES + 1];
__device__ int      g_sid[N_EDGES];         // senders sorted by receiver
__device__ int      g_eix[N_EDGES];         // edge ids sorted by receiver
__device__ int      g_bsum[NB_SCAN];

// --------------------------- helpers ---------------------------------------
__device__ __forceinline__ uint16_t f2bf(float x) {
    __nv_bfloat16 h = __float2bfloat16(x);
    return *reinterpret_cast<uint16_t*>(&h);
}
__device__ __forceinline__ float bf2f(uint16_t b) {
    __nv_bfloat16 h = *reinterpret_cast<__nv_bfloat16*>(&b);
    return __bfloat162float(h);
}

__device__ __forceinline__ void mma_bf16(float (&c)[4], const uint32_t (&a)[4],
                                         const uint32_t (&b)[2]) {
    asm volatile(
        "mma.sync.aligned.m16n8k16.row.col.f32.bf16.bf16.f32 "
        "{%0,%1,%2,%3},{%4,%5,%6,%7},{%8,%9},{%0,%1,%2,%3};\n"
        : "+f"(c[0]), "+f"(c[1]), "+f"(c[2]), "+f"(c[3])
        : "r"(a[0]), "r"(a[1]), "r"(a[2]), "r"(a[3]), "r"(b[0]), "r"(b[1]));
}

__device__ __forceinline__ void cvt_store(uint16_t* hi, uint16_t* lo, int off, float4 v) {
    uint16_t h0 = f2bf(v.x), h1 = f2bf(v.y), h2 = f2bf(v.z), h3 = f2bf(v.w);
    uint16_t l0 = f2bf(v.x - bf2f(h0)), l1 = f2bf(v.y - bf2f(h1));
    uint16_t l2 = f2bf(v.z - bf2f(h2)), l3 = f2bf(v.w - bf2f(h3));
    *(uint32_t*)(hi + off)     = ((uint32_t)h1 << 16) | h0;
    *(uint32_t*)(hi + off + 2) = ((uint32_t)h3 << 16) | h2;
    *(uint32_t*)(lo + off)     = ((uint32_t)l1 << 16) | l0;
    *(uint32_t*)(lo + off + 2) = ((uint32_t)l3 << 16) | l2;
}

__device__ __forceinline__ void load_bfrag(const uint16_t* __restrict__ whi,
                                           const uint16_t* __restrict__ wlo,
                                           int ks, int nbase, int qr, int qk,
                                           uint32_t (&bh)[8][2], uint32_t (&bl)[8][2]) {
#pragma unroll
    for (int nf = 0; nf < 8; nf++) {
        const uint16_t* p = whi + ((size_t)ks * D + nbase + nf * 8 + qr) * 16 + qk;
        bh[nf][0] = *(const uint32_t*)p;
        bh[nf][1] = *(const uint32_t*)(p + 8);
        const uint16_t* q = wlo + ((size_t)ks * D + nbase + nf * 8 + qr) * 16 + qk;
        bl[nf][0] = *(const uint32_t*)q;
        bl[nf][1] = *(const uint32_t*)(q + 8);
    }
}

__device__ __forceinline__ void load_afrag(const uint16_t* sA, int kp, int row0,
                                           int ks, int qk, uint32_t (&a)[4]) {
    const uint16_t* p = sA + row0 * kp + ks * 16 + qk;
    a[0] = *(const uint32_t*)p;
    a[1] = *(const uint32_t*)(p + 8 * kp);
    a[2] = *(const uint32_t*)(p + 8);
    a[3] = *(const uint32_t*)(p + 8 * kp + 8);
}

__device__ __forceinline__ void mma_step(float (&acc)[2][8][4],
                                         const uint16_t* sAhi, const uint16_t* sAlo,
                                         int kp, int rbase, int ks, int qk,
                                         const uint32_t (&bh)[8][2],
                                         const uint32_t (&bl)[8][2]) {
#pragma unroll
    for (int mf = 0; mf < 2; mf++) {
        uint32_t ah[4], al[4];
        load_afrag(sAhi, kp, rbase + mf * 16, ks, qk, ah);
        load_afrag(sAlo, kp, rbase + mf * 16, ks, qk, al);
#pragma unroll
        for (int nf = 0; nf < 8; nf++) {
            mma_bf16(acc[mf][nf], ah, bh[nf]);
            mma_bf16(acc[mf][nf], ah, bl[nf]);
            mma_bf16(acc[mf][nf], al, bh[nf]);
        }
    }
}

// --------------------------- convert + zero ---------------------------------
__global__ void convert_zero_kernel(const void* __restrict__ p) {
    __shared__ int anynz;
    if (threadIdx.x == 0) anynz = 0;
    __syncthreads();
    if (threadIdx.x < 64) {
        // per-block dtype detect: int64 => odd 32-bit words (high halves) all 0
        if (((const unsigned int*)p)[2 * threadIdx.x + 1] != 0u) atomicOr(&anynz, 1);
    }
    __syncthreads();
    const int is64 = (anynz == 0);
    const int gstride = gridDim.x * blockDim.x;
    for (int i = blockIdx.x * blockDim.x + threadIdx.x; i < 2 * N_EDGES; i += gstride)
        g_sr[i] = is64 ? (int)((const long long*)p)[i] : ((const int*)p)[i];
    for (int i = blockIdx.x * blockDim.x + threadIdx.x; i < N_NODES; i += gstride)
        g_cnt[i] = 0;
}

// --------------------------- CSR build --------------------------------------
__global__ void hist_kernel() {
    int e = blockIdx.x * blockDim.x + threadIdx.x;
    if (e < N_EDGES) atomicAdd(&g_cnt[g_sr[N_EDGES + e]], 1);
}

__global__ void blocksum_kernel() {
    __shared__ int s[256];
    int i = blockIdx.x * 256 + threadIdx.x;
    s[threadIdx.x] = (i < N_NODES) ? g_cnt[i] : 0;
    __syncthreads();
    #pragma unroll
    for (int o = 128; o; o >>= 1) {
        if (threadIdx.x < o) s[threadIdx.x] += s[threadIdx.x + o];
        __syncthreads();
    }
    if (threadIdx.x == 0) g_bsum[blockIdx.x] = s[0];
}

// scatter offsets; inline scan of block sums (each block sums bsum[0..bid-1])
__global__ void scatter_off_kernel() {
    __shared__ int s[256];
    __shared__ int base;
    const int t = threadIdx.x;
    int acc = 0;
    for (int i = t; i < blockIdx.x; i += 256) acc += g_bsum[i];
    s[t] = acc;
    __syncthreads();
    #pragma unroll
    for (int o = 128; o; o >>= 1) {
        if (t < o) s[t] += s[t + o];
        __syncthreads();
    }
    if (t == 0) base = s[0];
    __syncthreads();

    const int i = blockIdx.x * 256 + t;
    int v = (i < N_NODES) ? g_cnt[i] : 0;
    s[t] = v;
    __syncthreads();
    for (int o = 1; o < 256; o <<= 1) {
        int x = (t >= o) ? s[t - o] : 0;
        __syncthreads();
        s[t] += x;
        __syncthreads();
    }
    if (i < N_NODES) {
        int off = base + s[t] - v;   // exclusive
        g_off[i] = off;
        g_cnt[i] = off;              // reuse as cursor
    }
    if (blockIdx.x == 0 && t == 0) g_off[N_NODES] = N_EDGES;
}

__global__ void fill_kernel() {
    int e = blockIdx.x * blockDim.x + threadIdx.x;
    if (e >= N_EDGES) return;
    int r = g_sr[N_EDGES + e];
    int pos = atomicAdd(&g_cnt[r], 1);
    g_sid[pos] = g_sr[e];
    g_eix[pos] = e;
}

// --------------------------- pull aggregation -------------------------------
// One warp per node; lane owns one float4 of the node row; lanes 0-7 own ea.
__global__ void __launch_bounds__(256)
pull_kernel(const float4* __restrict__ nodes4, const float4* __restrict__ ea4) {
    int n = blockIdx.x * 8 + (threadIdx.x >> 5);
    if (n >= N_NODES) return;
    const int lane = threadIdx.x & 31;
    const int beg = g_off[n], end = g_off[n + 1];
    float4 an = make_float4(0.f, 0.f, 0.f, 0.f);
    float4 ae = make_float4(0.f, 0.f, 0.f, 0.f);
    for (int i = beg; i < end; i++) {
        int s = __ldg(&g_sid[i]);
        float4 v = __ldg(nodes4 + (size_t)s * 32 + lane);
        an.x += v.x; an.y += v.y; an.z += v.z; an.w += v.w;
        if (lane < 8) {
            int e = __ldg(&g_eix[i]);
            float4 w = __ldg(ea4 + (size_t)e * 8 + lane);
            ae.x += w.x; ae.y += w.y; ae.z += w.z; ae.w += w.w;
        }
    }
    float4* dst = reinterpret_cast<float4*>(g_agg) + (size_t)n * 40;
    dst[lane] = an;
    if (lane < 8) dst[32 + lane] = ae;
}

// --------------------------- weight fusion / prep --------------------------
__global__ void __launch_bounds__(AD)
fuse_w_kernel(const float* __restrict__ W1, const float* __restrict__ Wm) {
    __shared__ float sw[D];
    int j = blockIdx.x, c = threadIdx.x;
    if (c < D) sw[c] = W1[j * (2 * D) + D + c];
    __syncthreads();
    float s = 0.f;
    #pragma unroll 8
    for (int k = 0; k < D; k++)
        s += sw[k] * __ldg(&Wm[k * AD + c]);
    g_wf[j * AD + c] = s;
}

__global__ void prep_w1_kernel(const float* __restrict__ W1) {
    int idx = blockIdx.x * 256 + threadIdx.x;
    if (idx >= KS1 * D * 16) return;
    int koff = idx & 15, n = (idx >> 4) & 127, ks = idx >> 11;
    int k = ks * 16 + koff;
    float v = (k < D) ? W1[n * (2 * D) + k] : g_wf[n * AD + (k - D)];
    uint16_t hi = f2bf(v);
    g_w1hi[idx] = hi;
    g_w1lo[idx] = f2bf(v - bf2f(hi));
}

__global__ void prep_w2_kernel(const float* __restrict__ W2,
                               const float* __restrict__ Wn) {
    int idx = blockIdx.x * 256 + threadIdx.x;
    if (idx >= KS2 * D * 16) return;
    int koff = idx & 15, n = (idx >> 4) & 127, ks = idx >> 11;
    int k = ks * 16 + koff;
    float v2 = W2[n * D + k];
    uint16_t h2 = f2bf(v2);
    g_w2hi[idx] = h2;
    g_w2lo[idx] = f2bf(v2 - bf2f(h2));
    float vn = Wn[n * D + k];
    uint16_t hn = f2bf(vn);
    g_wnhi[idx] = hn;
    g_wnlo[idx] = f2bf(vn - bf2f(hn));
}

// --------------------------- fused node phase --------------------------------
// Per block: 128-node tile through the whole MLP; h never leaves smem.
// smem A layout: rows of KP1=296 u16: cols [0,128) = nodes, [128,288) = agg;
// after GEMM1 the agg columns are rewritten with h (bank-pattern identical).
__global__ void __launch_bounds__(256, 1)
node_phase_kernel(const float* __restrict__ nodes,
                  const float* __restrict__ b1,
                  const float* __restrict__ g1,
                  const float* __restrict__ be1,
                  const float* __restrict__ b2,
                  const float* __restrict__ g2,
                  const float* __restrict__ be2,
                  const float* __restrict__ gf,
                  const float* __restrict__ bef,
                  float* __restrict__ out) {
    extern __shared__ uint16_t smu[];
    uint16_t* sAhi = smu;
    uint16_t* sAlo = smu + 128 * KP1;

    __shared__ float sb1[D], sg1[D], sbe1[D];
    __shared__ float sb2[D], sg2[D], sbe2[D], sgf[D], sbef[D];
    __shared__ float sredS[D][2], sredQ[D][2];

    const int tid = threadIdx.x;
    const int n0 = blockIdx.x * 128;
    if (tid < D) {
        sb1[tid] = b1[tid]; sg1[tid] = g1[tid]; sbe1[tid] = be1[tid];
        sb2[tid] = b2[tid]; sg2[tid] = g2[tid]; sbe2[tid] = be2[tid];
        sgf[tid] = gf[tid]; sbef[tid] = bef[tid];
    }

    // ---- load + convert A = [nodes | agg] ----
    const float4* nsrc = (const float4*)nodes;
    #pragma unroll
    for (int it = 0; it < 16; it++) {
        int idx = it * 256 + tid;
        int row = idx >> 5, c4 = idx & 31;
        float4 v = make_float4(0.f, 0.f, 0.f, 0.f);
        if (n0 + row < N_NODES) v = __ldg(nsrc + (size_t)(n0 + row) * 32 + c4);
        cvt_store(sAhi, sAlo, row * KP1 + c4 * 4, v);
    }
    const float4* asrc = (const float4*)g_agg;
    #pragma unroll
    for (int it = 0; it < 20; it++) {
        int idx = it * 256 + tid;
        int row = idx / 40, c4 = idx % 40;
        float4 v = make_float4(0.f, 0.f, 0.f, 0.f);
        if (n0 + row < N_NODES) v = asrc[(size_t)(n0 + row) * 40 + c4];
        cvt_store(sAhi, sAlo, row * KP1 + 128 + c4 * 4, v);
    }
    __syncthreads();

    const int lane = tid & 31;
    const int wid  = tid >> 5;
    const int wm   = wid >> 1, wn = wid & 1;
    const int qr   = lane >> 2;
    const int qk   = 2 * (lane & 3);
    const int rbase = wm * 32 + qr;
    const int nbase = wn * 64;

    // =================== GEMM 1: [nodes|agg] @ Wcat^T (K=288) ===============
    float acc[2][8][4];
    #pragma unroll
    for (int mf = 0; mf < 2; mf++)
        #pragma unroll
        for (int nf = 0; nf < 8; nf++)
            #pragma unroll
            for (int i = 0; i < 4; i++) acc[mf][nf][i] = 0.f;

    {
        uint32_t bh0[8][2], bl0[8][2], bh1[8][2], bl1[8][2];
        load_bfrag(g_w1hi, g_w1lo, 0, nbase, qr, qk, bh0, bl0);
        #pragma unroll 1
        for (int ks = 0; ks < KS1; ks += 2) {
            load_bfrag(g_w1hi, g_w1lo, ks + 1, nbase, qr, qk, bh1, bl1);
            mma_step(acc, sAhi, sAlo, KP1, rbase, ks, qk, bh0, bl0);
            if (ks + 2 < KS1)
                load_bfrag(g_w1hi, g_w1lo, ks + 2, nbase, qr, qk, bh0, bl0);
            mma_step(acc, sAhi, sAlo, KP1, rbase, ks + 1, qk, bh1, bl1);
        }
    }

    // ---- bias + relu ----
    float vals[2][8][4];
    #pragma unroll
    for (int mf = 0; mf < 2; mf++)
        #pragma unroll
        for (int nf = 0; nf < 8; nf++) {
            int c = nbase + nf * 8 + qk;
            vals[mf][nf][0] = fmaxf(acc[mf][nf][0] + sb1[c], 0.f);
            vals[mf][nf][1] = fmaxf(acc[mf][nf][1] + sb1[c + 1], 0.f);
            vals[mf][nf][2] = fmaxf(acc[mf][nf][2] + sb1[c], 0.f);
            vals[mf][nf][3] = fmaxf(acc[mf][nf][3] + sb1[c + 1], 0.f);
        }

    // ---- LN1 reductions ----
    #pragma unroll
    for (int mf = 0; mf < 2; mf++)
        #pragma unroll
        for (int h = 0; h < 2; h++) {
            float s = 0.f, q = 0.f;
            #pragma unroll
            for (int nf = 0; nf < 8; nf++) {
                float v0 = vals[mf][nf][2 * h], v1 = vals[mf][nf][2 * h + 1];
                s += v0 + v1; q += v0 * v0 + v1 * v1;
            }
            s += __shfl_xor_sync(0xffffffffu, s, 1);
            s += __shfl_xor_sync(0xffffffffu, s, 2);
            q += __shfl_xor_sync(0xffffffffu, q, 1);
            q += __shfl_xor_sync(0xffffffffu, q, 2);
            int r = wm * 32 + mf * 16 + h * 8 + qr;
            if ((lane & 3) == 0) { sredS[r][wn] = s; sredQ[r][wn] = q; }
        }
    __syncthreads();   // also: all GEMM1 smem reads complete past this point

    // ---- LN1 apply; write h (bf16 hi/lo) into the agg columns of sA ----
    #pragma unroll
    for (int mf = 0; mf < 2; mf++)
        #pragma unroll
        for (int h = 0; h < 2; h++) {
            int r = wm * 32 + mf * 16 + h * 8 + qr;
            float S = sredS[r][0] + sredS[r][1];
            float Q = sredQ[r][0] + sredQ[r][1];
            float mu = S * (1.f / 128.f);
            float var = Q * (1.f / 128.f) - mu * mu;
            float rs = rsqrtf(var + LN_EPS);
            #pragma unroll
            for (int nf = 0; nf < 8; nf++) {
                int c = nbase + nf * 8 + qk;
                float y0 = (vals[mf][nf][2 * h] - mu) * rs * sg1[c] + sbe1[c];
                float y1 = (vals[mf][nf][2 * h + 1] - mu) * rs * sg1[c + 1] + sbe1[c + 1];
                uint16_t h0 = f2bf(y0), h1 = f2bf(y1);
                uint16_t l0 = f2bf(y0 - bf2f(h0)), l1 = f2bf(y1 - bf2f(h1));
                *(uint32_t*)(sAhi + r * KP1 + 128 + c) = ((uint32_t)h1 << 16) | h0;
                *(uint32_t*)(sAlo + r * KP1 + 128 + c) = ((uint32_t)l1 << 16) | l0;
            }
        }
    __syncthreads();

    // =================== GEMM 2: h @ W2^T (K=128) ===========================
    #pragma unroll
    for (int mf = 0; mf < 2; mf++)
        #pragma unroll
        for (int nf = 0; nf < 8; nf++)
            #pragma unroll
            for (int i = 0; i < 4; i++) acc[mf][nf][i] = 0.f;
    {
        uint32_t bh[8][2], bl[8][2];
        #pragma unroll 1
        for (int ks = 0; ks < KS2; ks++) {
            load_bfrag(g_w2hi, g_w2lo, ks, nbase, qr, qk, bh, bl);
            mma_step(acc, sAhi + 128, sAlo + 128, KP1, rbase, ks, qk, bh, bl);
        }
    }

    // ---- bias + relu -> uvals ----
    float uvals[2][8][4];
    #pragma unroll
    for (int mf = 0; mf < 2; mf++)
        #pragma unroll
        for (int nf = 0; nf < 8; nf++) {
            int c = nbase + nf * 8 + qk;
            uvals[mf][nf][0] = fmaxf(acc[mf][nf][0] + sb2[c], 0.f);
            uvals[mf][nf][1] = fmaxf(acc[mf][nf][1] + sb2[c + 1], 0.f);
            uvals[mf][nf][2] = fmaxf(acc[mf][nf][2] + sb2[c], 0.f);
            uvals[mf][nf][3] = fmaxf(acc[mf][nf][3] + sb2[c + 1], 0.f);
        }

    // ---- LN2 reductions ----
    __syncthreads();   // sred reuse
    #pragma unroll
    for (int mf = 0; mf < 2; mf++)
        #pragma unroll
        for (int h = 0; h < 2; h++) {
            float s = 0.f, q = 0.f;
            #pragma unroll
            for (int nf = 0; nf < 8; nf++) {
                float v0 = uvals[mf][nf][2 * h], v1 = uvals[mf][nf][2 * h + 1];
                s += v0 + v1; q += v0 * v0 + v1 * v1;
            }
            s += __shfl_xor_sync(0xffffffffu, s, 1);
            s += __shfl_xor_sync(0xffffffffu, s, 2);
            q += __shfl_xor_sync(0xffffffffu, q, 1);
            q += __shfl_xor_sync(0xffffffffu, q, 2);
            int r = wm * 32 + mf * 16 + h * 8 + qr;
            if ((lane & 3) == 0) { sredS[r][wn] = s; sredQ[r][wn] = q; }
        }
    __syncthreads();

    #pragma unroll
    for (int mf = 0; mf < 2; mf++)
        #pragma unroll
        for (int h = 0; h < 2; h++) {
            int r = wm * 32 + mf * 16 + h * 8 + qr;
            float S = sredS[r][0] + sredS[r][1];
            float Q = sredQ[r][0] + sredQ[r][1];
            float mu = S * (1.f / 128.f);
            float var = Q * (1.f / 128.f) - mu * mu;
            float rs = rsqrtf(var + LN_EPS);
            #pragma unroll
            for (int nf = 0; nf < 8; nf++) {
                int c = nbase + nf * 8 + qk;
                uvals[mf][nf][2 * h]     = (uvals[mf][nf][2 * h] - mu) * rs * sg2[c] + sbe2[c];
                uvals[mf][nf][2 * h + 1] = (uvals[mf][nf][2 * h + 1] - mu) * rs * sg2[c + 1] + sbe2[c + 1];
            }
        }
    __syncthreads();

    // =================== GEMM 3: nodes @ Wn^T (K=128) =======================
    #pragma unroll
    for (int mf = 0; mf < 2; mf++)
        #pragma unroll
        for (int nf = 0; nf < 8; nf++)
            #pragma unroll
            for (int i = 0; i < 4; i++) acc[mf][nf][i] = 0.f;
    {
        uint32_t bh[8][2], bl[8][2];
        #pragma unroll 1
        for (int ks = 0; ks < KS2; ks++) {
            load_bfrag(g_wnhi, g_wnlo, ks, nbase, qr, qk, bh, bl);
            mma_step(acc, sAhi, sAlo, KP1, rbase, ks, qk, bh, bl);
        }
    }

    // ---- v = acc + u; final LN ----
    #pragma unroll
    for (int mf = 0; mf < 2; mf++)
        #pragma unroll
        for (int nf = 0; nf < 8; nf++)
            #pragma unroll
            for (int i = 0; i < 4; i++)
                uvals[mf][nf][i] += acc[mf][nf][i];

    #pragma unroll
    for (int mf = 0; mf < 2; mf++)
        #pragma unroll
        for (int h = 0; h < 2; h++) {
            float s = 0.f, q = 0.f;
            #pragma unroll
            for (int nf = 0; nf < 8; nf++) {
                float v0 = uvals[mf][nf][2 * h], v1 = uvals[mf][nf][2 * h + 1];
                s += v0 + v1; q += v0 * v0 + v1 * v1;
            }
            s += __shfl_xor_sync(0xffffffffu, s, 1);
            s += __shfl_xor_sync(0xffffffffu, s, 2);
            q += __shfl_xor_sync(0xffffffffu, q, 1);
            q += __shfl_xor_sync(0xffffffffu, q, 2);
            int r = wm * 32 + mf * 16 + h * 8 + qr;
            if ((lane & 3) == 0) { sredS[r][wn] = s; sredQ[r][wn] = q; }
        }
    __syncthreads();

    #pragma unroll
    for (int mf = 0; mf < 2; mf++)
        #pragma unroll
        for (int h = 0; h < 2; h++) {
            int r = wm * 32 + mf * 16 + h * 8 + qr;
            int node = n0 + r;
            if (node >= N_NODES) continue;
            float S = sredS[r][0] + sredS[r][1];
            float Q = sredQ[r][0] + sredQ[r][1];
            float mu = S * (1.f / 128.f);
            float var = Q * (1.f / 128.f) - mu * mu;
            float rs = rsqrtf(var + LN_EPS);
            #pragma unroll
            for (int nf = 0; nf < 8; nf++) {
                int c = nbase + nf * 8 + qk;
                float2 o;
                o.x = (uvals[mf][nf][2 * h] - mu) * rs * sgf[c] + sbef[c];
                o.y = (uvals[mf][nf][2 * h + 1] - mu) * rs * sgf[c + 1] + sbef[c + 1];
                *(float2*)(out + (size_t)node * D + c) = o;
            }
        }
}

// --------------------------- launch -----------------------------------------
extern "C" void kernel_launch(void* const* d_in, const int* in_sizes, int n_in,
                              void* d_out, int out_size) {
    const float* nodes     = (const float*)d_in[0];
    const void*  eidx      = d_in[1];
    const float* edge_attr = (const float*)d_in[2];
    const float* Wm        = (const float*)d_in[3];
    const float* Wn        = (const float*)d_in[4];
    const float* W1        = (const float*)d_in[5];
    const float* b1        = (const float*)d_in[6];
    const float* g1        = (const float*)d_in[7];
    const float* be1       = (const float*)d_in[8];
    const float* W2        = (const float*)d_in[9];
    const float* b2        = (const float*)d_in[10];
    const float* g2        = (const float*)d_in[11];
    const float* be2       = (const float*)d_in[12];
    const float* gf        = (const float*)d_in[13];
    const float* bef       = (const float*)d_in[14];
    float* out = (float*)d_out;

    const int smem = 128 * KP1 * 2 * (int)sizeof(uint16_t);   // 151552
    cudaFuncSetAttribute(node_phase_kernel, cudaFuncAttributeMaxDynamicSharedMemorySize, smem);

    // CSR + pull first (pull is launch #6 → captured by ncu -s 5 -c 1)
    convert_zero_kernel<<<1024, 256>>>(eidx);
    hist_kernel<<<(N_EDGES + 255) / 256, 256>>>();
    blocksum_kernel<<<NB_SCAN, 256>>>();
    scatter_off_kernel<<<NB_SCAN, 256>>>();
    fill_kernel<<<(N_EDGES + 255) / 256, 256>>>();
    pull_kernel<<<(N_NODES + 7) / 8, 256>>>(
        (const float4*)nodes, (const float4*)edge_attr);

    // weight prep
    fuse_w_kernel<<<D, AD>>>(W1, Wm);
    prep_w1_kernel<<<(KS1 * D * 16 + 255) / 256, 256>>>(W1);
    prep_w2_kernel<<<(KS2 * D * 16 + 255) / 256, 256>>>(W2, Wn);

    // fused node phase
    node_phase_kernel<<<NGRP, 256, smem>>>(nodes, b1, g1, be1,
                                           b2, g2, be2, gf, bef, out);
}

// round 5
// speedup vs baseline: 3.3354x; 1.0251x over previous
#include <cuda_runtime.h>
#include <cuda_bf16.h>
#include <cstdint>

// ---------------------------------------------------------------------------
// LinearMessagePassingLayer — GB300 sm_103a, round 5.
//
//   agg = segment_sum(concat(nodes[s], edge_attr), recv)       (CSR pull, x4 unroll)
//   node phase (single fused kernel, h stays in smem):
//     h   = LN1(relu([nodes|agg] @ [W1a|W1b@Wm]^T + b1))
//     out = LN(nodes@Wn^T + LN2(relu(h@W2^T + b2)))
//
// GEMMs: mma.sync.m16n8k16 bf16, 3-term hi/lo split; all B-fragment streams
// register double-buffered, first fragment prefetched behind LN epilogues.
// ---------------------------------------------------------------------------

#define N_NODES 100000
#define N_EDGES 800000
#define D       128
#define ED      32
#define AD      160
#define LN_EPS  1e-5f
#define NB_SCAN ((N_NODES + 255) / 256)   // 391

#define KS1   18           // stage1 GEMM k16 steps (K=288)
#define KP1   296          // smem A row stride (u16) — conflict-free
#define KS2   8            // K=128 GEMM k-steps
#define NGRP  ((N_NODES + 127) / 128)     // 782

// --------------------------- device scratch -------------------------------
__device__ float    g_agg[(size_t)N_NODES * AD];
__device__ float    g_wf[D * AD];
__device__ uint16_t g_w1hi[KS1 * D * 16], g_w1lo[KS1 * D * 16];
__device__ uint16_t g_w2hi[KS2 * D * 16], g_w2lo[KS2 * D * 16];
__device__ uint16_t g_wnhi[KS2 * D * 16], g_wnlo[KS2 * D * 16];
__device__ int      g_sr[2 * N_EDGES];      // senders | receivers
__device__ int      g_cnt[N_NODES];
__device__ int      g_off[N_NODES + 1];
__device__ int      g_sid[N_EDGES];         // senders sorted by receiver
__device__ int      g_eix[N_EDGES];         // edge ids sorted by receiver
__device__ int      g_bsum[NB_SCAN];

// --------------------------- helpers ---------------------------------------
__device__ __forceinline__ uint16_t f2bf(float x) {
    __nv_bfloat16 h = __float2bfloat16(x);
    return *reinterpret_cast<uint16_t*>(&h);
}
__device__ __forceinline__ float bf2f(uint16_t b) {
    __nv_bfloat16 h = *reinterpret_cast<__nv_bfloat16*>(&b);
    return __bfloat162float(h);
}

__device__ __forceinline__ void mma_bf16(float (&c)[4], const uint32_t (&a)[4],
                                         const uint32_t (&b)[2]) {
    asm volatile(
        "mma.sync.aligned.m16n8k16.row.col.f32.bf16.bf16.f32 "
        "{%0,%1,%2,%3},{%4,%5,%6,%7},{%8,%9},{%0,%1,%2,%3};\n"
        : "+f"(c[0]), "+f"(c[1]), "+f"(c[2]), "+f"(c[3])
        : "r"(a[0]), "r"(a[1]), "r"(a[2]), "r"(a[3]), "r"(b[0]), "r"(b[1]));
}

__device__ __forceinline__ void cvt_store(uint16_t* hi, uint16_t* lo, int off, float4 v) {
    uint16_t h0 = f2bf(v.x), h1 = f2bf(v.y), h2 = f2bf(v.z), h3 = f2bf(v.w);
    uint16_t l0 = f2bf(v.x - bf2f(h0)), l1 = f2bf(v.y - bf2f(h1));
    uint16_t l2 = f2bf(v.z - bf2f(h2)), l3 = f2bf(v.w - bf2f(h3));
    *(uint32_t*)(hi + off)     = ((uint32_t)h1 << 16) | h0;
    *(uint32_t*)(hi + off + 2) = ((uint32_t)h3 << 16) | h2;
    *(uint32_t*)(lo + off)     = ((uint32_t)l1 << 16) | l0;
    *(uint32_t*)(lo + off + 2) = ((uint32_t)l3 << 16) | l2;
}

__device__ __forceinline__ void load_bfrag(const uint16_t* __restrict__ whi,
                                           const uint16_t* __restrict__ wlo,
                                           int ks, int nbase, int qr, int qk,
                                           uint32_t (&bh)[8][2], uint32_t (&bl)[8][2]) {
#pragma unroll
    for (int nf = 0; nf < 8; nf++) {
        const uint16_t* p = whi + ((size_t)ks * D + nbase + nf * 8 + qr) * 16 + qk;
        bh[nf][0] = *(const uint32_t*)p;
        bh[nf][1] = *(const uint32_t*)(p + 8);
        const uint16_t* q = wlo + ((size_t)ks * D + nbase + nf * 8 + qr) * 16 + qk;
        bl[nf][0] = *(const uint32_t*)q;
        bl[nf][1] = *(const uint32_t*)(q + 8);
    }
}

__device__ __forceinline__ void load_afrag(const uint16_t* sA, int kp, int row0,
                                           int ks, int qk, uint32_t (&a)[4]) {
    const uint16_t* p = sA + row0 * kp + ks * 16 + qk;
    a[0] = *(const uint32_t*)p;
    a[1] = *(const uint32_t*)(p + 8 * kp);
    a[2] = *(const uint32_t*)(p + 8);
    a[3] = *(const uint32_t*)(p + 8 * kp + 8);
}

__device__ __forceinline__ void mma_step(float (&acc)[2][8][4],
                                         const uint16_t* sAhi, const uint16_t* sAlo,
                                         int kp, int rbase, int ks, int qk,
                                         const uint32_t (&bh)[8][2],
                                         const uint32_t (&bl)[8][2]) {
#pragma unroll
    for (int mf = 0; mf < 2; mf++) {
        uint32_t ah[4], al[4];
        load_afrag(sAhi, kp, rbase + mf * 16, ks, qk, ah);
        load_afrag(sAlo, kp, rbase + mf * 16, ks, qk, al);
#pragma unroll
        for (int nf = 0; nf < 8; nf++) {
            mma_bf16(acc[mf][nf], ah, bh[nf]);
            mma_bf16(acc[mf][nf], ah, bl[nf]);
            mma_bf16(acc[mf][nf], al, bh[nf]);
        }
    }
}

// --------------------------- CSR build --------------------------------------
__global__ void zero_cnt_kernel() {
    int i = blockIdx.x * blockDim.x + threadIdx.x;
    if (i < N_NODES) g_cnt[i] = 0;
}

// convert indices to i32 AND histogram receivers in the same pass
__global__ void convert_hist_kernel(const void* __restrict__ p) {
    __shared__ int anynz;
    if (threadIdx.x == 0) anynz = 0;
    __syncthreads();
    if (threadIdx.x < 64) {
        if (((const unsigned int*)p)[2 * threadIdx.x + 1] != 0u) atomicOr(&anynz, 1);
    }
    __syncthreads();
    const int is64 = (anynz == 0);
    const int gstride = gridDim.x * blockDim.x;
    for (int i = blockIdx.x * blockDim.x + threadIdx.x; i < 2 * N_EDGES; i += gstride) {
        int v = is64 ? (int)((const long long*)p)[i] : ((const int*)p)[i];
        g_sr[i] = v;
        if (i >= N_EDGES) atomicAdd(&g_cnt[v], 1);
    }
}

__global__ void blocksum_kernel() {
    __shared__ int s[256];
    int i = blockIdx.x * 256 + threadIdx.x;
    s[threadIdx.x] = (i < N_NODES) ? g_cnt[i] : 0;
    __syncthreads();
    #pragma unroll
    for (int o = 128; o; o >>= 1) {
        if (threadIdx.x < o) s[threadIdx.x] += s[threadIdx.x + o];
        __syncthreads();
    }
    if (threadIdx.x == 0) g_bsum[blockIdx.x] = s[0];
}

__global__ void scatter_off_kernel() {
    __shared__ int s[256];
    __shared__ int base;
    const int t = threadIdx.x;
    int acc = 0;
    for (int i = t; i < blockIdx.x; i += 256) acc += g_bsum[i];
    s[t] = acc;
    __syncthreads();
    #pragma unroll
    for (int o = 128; o; o >>= 1) {
        if (t < o) s[t] += s[t + o];
        __syncthreads();
    }
    if (t == 0) base = s[0];
    __syncthreads();

    const int i = blockIdx.x * 256 + t;
    int v = (i < N_NODES) ? g_cnt[i] : 0;
    s[t] = v;
    __syncthreads();
    for (int o = 1; o < 256; o <<= 1) {
        int x = (t >= o) ? s[t - o] : 0;
        __syncthreads();
        s[t] += x;
        __syncthreads();
    }
    if (i < N_NODES) {
        int off = base + s[t] - v;
        g_off[i] = off;
        g_cnt[i] = off;
    }
    if (blockIdx.x == 0 && t == 0) g_off[N_NODES] = N_EDGES;
}

__global__ void fill_kernel() {
    int e = blockIdx.x * blockDim.x + threadIdx.x;
    if (e >= N_EDGES) return;
    int r = g_sr[N_EDGES + e];
    int pos = atomicAdd(&g_cnt[r], 1);
    g_sid[pos] = g_sr[e];
    g_eix[pos] = e;
}

// --------------------------- pull aggregation -------------------------------
// One warp per node; lane owns one float4 of the node row; lanes 0-7 own ea.
// 4x unrolled over edges for memory-level parallelism.
__global__ void __launch_bounds__(256)
pull_kernel(const float4* __restrict__ nodes4, const float4* __restrict__ ea4) {
    int n = blockIdx.x * 8 + (threadIdx.x >> 5);
    if (n >= N_NODES) return;
    const int lane = threadIdx.x & 31;
    const int beg = g_off[n], end = g_off[n + 1];
    float4 an = make_float4(0.f, 0.f, 0.f, 0.f);
    float4 ae = make_float4(0.f, 0.f, 0.f, 0.f);
    int i = beg;
    for (; i + 4 <= end; i += 4) {
        int s0 = __ldg(&g_sid[i]),     s1 = __ldg(&g_sid[i + 1]);
        int s2 = __ldg(&g_sid[i + 2]), s3 = __ldg(&g_sid[i + 3]);
        float4 v0 = __ldg(nodes4 + (size_t)s0 * 32 + lane);
        float4 v1 = __ldg(nodes4 + (size_t)s1 * 32 + lane);
        float4 v2 = __ldg(nodes4 + (size_t)s2 * 32 + lane);
        float4 v3 = __ldg(nodes4 + (size_t)s3 * 32 + lane);
        an.x += v0.x + v1.x + v2.x + v3.x;
        an.y += v0.y + v1.y + v2.y + v3.y;
        an.z += v0.z + v1.z + v2.z + v3.z;
        an.w += v0.w + v1.w + v2.w + v3.w;
        if (lane < 8) {
            int e0 = __ldg(&g_eix[i]),     e1 = __ldg(&g_eix[i + 1]);
            int e2 = __ldg(&g_eix[i + 2]), e3 = __ldg(&g_eix[i + 3]);
            float4 w0 = __ldg(ea4 + (size_t)e0 * 8 + lane);
            float4 w1 = __ldg(ea4 + (size_t)e1 * 8 + lane);
            float4 w2 = __ldg(ea4 + (size_t)e2 * 8 + lane);
            float4 w3 = __ldg(ea4 + (size_t)e3 * 8 + lane);
            ae.x += w0.x + w1.x + w2.x + w3.x;
            ae.y += w0.y + w1.y + w2.y + w3.y;
            ae.z += w0.z + w1.z + w2.z + w3.z;
            ae.w += w0.w + w1.w + w2.w + w3.w;
        }
    }
    for (; i < end; i++) {
        int s = __ldg(&g_sid[i]);
        float4 v = __ldg(nodes4 + (size_t)s * 32 + lane);
        an.x += v.x; an.y += v.y; an.z += v.z; an.w += v.w;
        if (lane < 8) {
            int e = __ldg(&g_eix[i]);
            float4 w = __ldg(ea4 + (size_t)e * 8 + lane);
            ae.x += w.x; ae.y += w.y; ae.z += w.z; ae.w += w.w;
        }
    }
    float4* dst = reinterpret_cast<float4*>(g_agg) + (size_t)n * 40;
    dst[lane] = an;
    if (lane < 8) dst[32 + lane] = ae;
}

// --------------------------- weight fusion / prep --------------------------
__global__ void __launch_bounds__(AD)
fuse_w_kernel(const float* __restrict__ W1, const float* __restrict__ Wm) {
    __shared__ float sw[D];
    int j = blockIdx.x, c = threadIdx.x;
    if (c < D) sw[c] = W1[j * (2 * D) + D + c];
    __syncthreads();
    float s = 0.f;
    #pragma unroll 8
    for (int k = 0; k < D; k++)
        s += sw[k] * __ldg(&Wm[k * AD + c]);
    g_wf[j * AD + c] = s;
}

__global__ void prep_w1_kernel(const float* __restrict__ W1) {
    int idx = blockIdx.x * 256 + threadIdx.x;
    if (idx >= KS1 * D * 16) return;
    int koff = idx & 15, n = (idx >> 4) & 127, ks = idx >> 11;
    int k = ks * 16 + koff;
    float v = (k < D) ? W1[n * (2 * D) + k] : g_wf[n * AD + (k - D)];
    uint16_t hi = f2bf(v);
    g_w1hi[idx] = hi;
    g_w1lo[idx] = f2bf(v - bf2f(hi));
}

__global__ void prep_w2_kernel(const float* __restrict__ W2,
                               const float* __restrict__ Wn) {
    int idx = blockIdx.x * 256 + threadIdx.x;
    if (idx >= KS2 * D * 16) return;
    int koff = idx & 15, n = (idx >> 4) & 127, ks = idx >> 11;
    int k = ks * 16 + koff;
    float v2 = W2[n * D + k];
    uint16_t h2 = f2bf(v2);
    g_w2hi[idx] = h2;
    g_w2lo[idx] = f2bf(v2 - bf2f(h2));
    float vn = Wn[n * D + k];
    uint16_t hn = f2bf(vn);
    g_wnhi[idx] = hn;
    g_wnlo[idx] = f2bf(vn - bf2f(hn));
}

// --------------------------- fused node phase --------------------------------
__global__ void __launch_bounds__(256, 1)
node_phase_kernel(const float* __restrict__ nodes,
                  const float* __restrict__ b1,
                  const float* __restrict__ g1,
                  const float* __restrict__ be1,
                  const float* __restrict__ b2,
                  const float* __restrict__ g2,
                  const float* __restrict__ be2,
                  const float* __restrict__ gf,
                  const float* __restrict__ bef,
                  float* __restrict__ out) {
    extern __shared__ uint16_t smu[];
    uint16_t* sAhi = smu;
    uint16_t* sAlo = smu + 128 * KP1;

    __shared__ float sb1[D], sg1[D], sbe1[D];
    __shared__ float sb2[D], sg2[D], sbe2[D], sgf[D], sbef[D];
    __shared__ float sredS[D][2], sredQ[D][2];

    const int tid = threadIdx.x;
    const int n0 = blockIdx.x * 128;
    if (tid < D) {
        sb1[tid] = b1[tid]; sg1[tid] = g1[tid]; sbe1[tid] = be1[tid];
        sb2[tid] = b2[tid]; sg2[tid] = g2[tid]; sbe2[tid] = be2[tid];
        sgf[tid] = gf[tid]; sbef[tid] = bef[tid];
    }

    // ---- load + convert A = [nodes | agg] ----
    const float4* nsrc = (const float4*)nodes;
    #pragma unroll
    for (int it = 0; it < 16; it++) {
        int idx = it * 256 + tid;
        int row = idx >> 5, c4 = idx & 31;
        float4 v = make_float4(0.f, 0.f, 0.f, 0.f);
        if (n0 + row < N_NODES) v = __ldg(nsrc + (size_t)(n0 + row) * 32 + c4);
        cvt_store(sAhi, sAlo, row * KP1 + c4 * 4, v);
    }
    const float4* asrc = (const float4*)g_agg;
    #pragma unroll
    for (int it = 0; it < 20; it++) {
        int idx = it * 256 + tid;
        int row = idx / 40, c4 = idx % 40;
        float4 v = make_float4(0.f, 0.f, 0.f, 0.f);
        if (n0 + row < N_NODES) v = asrc[(size_t)(n0 + row) * 40 + c4];
        cvt_store(sAhi, sAlo, row * KP1 + 128 + c4 * 4, v);
    }
    __syncthreads();

    const int lane = tid & 31;
    const int wid  = tid >> 5;
    const int wm   = wid >> 1, wn = wid & 1;
    const int qr   = lane >> 2;
    const int qk   = 2 * (lane & 3);
    const int rbase = wm * 32 + qr;
    const int nbase = wn * 64;

    uint32_t bh0[8][2], bl0[8][2], bh1[8][2], bl1[8][2];

    // =================== GEMM 1: [nodes|agg] @ Wcat^T (K=288) ===============
    float acc[2][8][4];
    #pragma unroll
    for (int mf = 0; mf < 2; mf++)
        #pragma unroll
        for (int nf = 0; nf < 8; nf++)
            #pragma unroll
            for (int i = 0; i < 4; i++) acc[mf][nf][i] = 0.f;

    load_bfrag(g_w1hi, g_w1lo, 0, nbase, qr, qk, bh0, bl0);
    #pragma unroll 1
    for (int ks = 0; ks < KS1; ks += 2) {
        load_bfrag(g_w1hi, g_w1lo, ks + 1, nbase, qr, qk, bh1, bl1);
        mma_step(acc, sAhi, sAlo, KP1, rbase, ks, qk, bh0, bl0);
        if (ks + 2 < KS1)
            load_bfrag(g_w1hi, g_w1lo, ks + 2, nbase, qr, qk, bh0, bl0);
        mma_step(acc, sAhi, sAlo, KP1, rbase, ks + 1, qk, bh1, bl1);
    }

    // prefetch GEMM2's first B fragment — hidden behind the LN1 epilogue
    load_bfrag(g_w2hi, g_w2lo, 0, nbase, qr, qk, bh0, bl0);

    // ---- bias + relu ----
    float vals[2][8][4];
    #pragma unroll
    for (int mf = 0; mf < 2; mf++)
        #pragma unroll
        for (int nf = 0; nf < 8; nf++) {
            int c = nbase + nf * 8 + qk;
            vals[mf][nf][0] = fmaxf(acc[mf][nf][0] + sb1[c], 0.f);
            vals[mf][nf][1] = fmaxf(acc[mf][nf][1] + sb1[c + 1], 0.f);
            vals[mf][nf][2] = fmaxf(acc[mf][nf][2] + sb1[c], 0.f);
            vals[mf][nf][3] = fmaxf(acc[mf][nf][3] + sb1[c + 1], 0.f);
        }

    // ---- LN1 reductions ----
    #pragma unroll
    for (int mf = 0; mf < 2; mf++)
        #pragma unroll
        for (int h = 0; h < 2; h++) {
            float s = 0.f, q = 0.f;
            #pragma unroll
            for (int nf = 0; nf < 8; nf++) {
                float v0 = vals[mf][nf][2 * h], v1 = vals[mf][nf][2 * h + 1];
                s += v0 + v1; q += v0 * v0 + v1 * v1;
            }
            s += __shfl_xor_sync(0xffffffffu, s, 1);
            s += __shfl_xor_sync(0xffffffffu, s, 2);
            q += __shfl_xor_sync(0xffffffffu, q, 1);
            q += __shfl_xor_sync(0xffffffffu, q, 2);
            int r = wm * 32 + mf * 16 + h * 8 + qr;
            if ((lane & 3) == 0) { sredS[r][wn] = s; sredQ[r][wn] = q; }
        }
    __syncthreads();   // all GEMM1 smem reads complete past this point

    // ---- LN1 apply; write h (bf16 hi/lo) into the agg columns of sA ----
    #pragma unroll
    for (int mf = 0; mf < 2; mf++)
        #pragma unroll
        for (int h = 0; h < 2; h++) {
            int r = wm * 32 + mf * 16 + h * 8 + qr;
            float S = sredS[r][0] + sredS[r][1];
            float Q = sredQ[r][0] + sredQ[r][1];
            float mu = S * (1.f / 128.f);
            float var = Q * (1.f / 128.f) - mu * mu;
            float rs = rsqrtf(var + LN_EPS);
            #pragma unroll
            for (int nf = 0; nf < 8; nf++) {
                int c = nbase + nf * 8 + qk;
                float y0 = (vals[mf][nf][2 * h] - mu) * rs * sg1[c] + sbe1[c];
                float y1 = (vals[mf][nf][2 * h + 1] - mu) * rs * sg1[c + 1] + sbe1[c + 1];
                uint16_t h0 = f2bf(y0), h1 = f2bf(y1);
                uint16_t l0 = f2bf(y0 - bf2f(h0)), l1 = f2bf(y1 - bf2f(h1));
                *(uint32_t*)(sAhi + r * KP1 + 128 + c) = ((uint32_t)h1 << 16) | h0;
                *(uint32_t*)(sAlo + r * KP1 + 128 + c) = ((uint32_t)l1 << 16) | l0;
            }
        }
    __syncthreads();

    // =================== GEMM 2: h @ W2^T (K=128, double-buffered) ==========
    #pragma unroll
    for (int mf = 0; mf < 2; mf++)
        #pragma unroll
        for (int nf = 0; nf < 8; nf++)
            #pragma unroll
            for (int i = 0; i < 4; i++) acc[mf][nf][i] = 0.f;
    #pragma unroll 1
    for (int ks = 0; ks < KS2; ks += 2) {
        load_bfrag(g_w2hi, g_w2lo, ks + 1, nbase, qr, qk, bh1, bl1);
        mma_step(acc, sAhi + 128, sAlo + 128, KP1, rbase, ks, qk, bh0, bl0);
        if (ks + 2 < KS2)
            load_bfrag(g_w2hi, g_w2lo, ks + 2, nbase, qr, qk, bh0, bl0);
        mma_step(acc, sAhi + 128, sAlo + 128, KP1, rbase, ks + 1, qk, bh1, bl1);
    }

    // prefetch GEMM3's first B fragment — hidden behind the LN2 epilogue
    load_bfrag(g_wnhi, g_wnlo, 0, nbase, qr, qk, bh0, bl0);

    // ---- bias + relu -> uvals ----
    float uvals[2][8][4];
    #pragma unroll
    for (int mf = 0; mf < 2; mf++)
        #pragma unroll
        for (int nf = 0; nf < 8; nf++) {
            int c = nbase + nf * 8 + qk;
            uvals[mf][nf][0] = fmaxf(acc[mf][nf][0] + sb2[c], 0.f);
            uvals[mf][nf][1] = fmaxf(acc[mf][nf][1] + sb2[c + 1], 0.f);
            uvals[mf][nf][2] = fmaxf(acc[mf][nf][2] + sb2[c], 0.f);
            uvals[mf][nf][3] = fmaxf(acc[mf][nf][3] + sb2[c + 1], 0.f);
        }

    // ---- LN2 reductions ----
    __syncthreads();   // sred reuse
    #pragma unroll
    for (int mf = 0; mf < 2; mf++)
        #pragma unroll
        for (int h = 0; h < 2; h++) {
            float s = 0.f, q = 0.f;
            #pragma unroll
            for (int nf = 0; nf < 8; nf++) {
                float v0 = uvals[mf][nf][2 * h], v1 = uvals[mf][nf][2 * h + 1];
                s += v0 + v1; q += v0 * v0 + v1 * v1;
            }
            s += __shfl_xor_sync(0xffffffffu, s, 1);
            s += __shfl_xor_sync(0xffffffffu, s, 2);
            q += __shfl_xor_sync(0xffffffffu, q, 1);
            q += __shfl_xor_sync(0xffffffffu, q, 2);
            int r = wm * 32 + mf * 16 + h * 8 + qr;
            if ((lane & 3) == 0) { sredS[r][wn] = s; sredQ[r][wn] = q; }
        }
    __syncthreads();

    #pragma unroll
    for (int mf = 0; mf < 2; mf++)
        #pragma unroll
        for (int h = 0; h < 2; h++) {
            int r = wm * 32 + mf * 16 + h * 8 + qr;
            float S = sredS[r][0] + sredS[r][1];
            float Q = sredQ[r][0] + sredQ[r][1];
            float mu = S * (1.f / 128.f);
            float var = Q * (1.f / 128.f) - mu * mu;
            float rs = rsqrtf(var + LN_EPS);
            #pragma unroll
            for (int nf = 0; nf < 8; nf++) {
                int c = nbase + nf * 8 + qk;
                uvals[mf][nf][2 * h]     = (uvals[mf][nf][2 * h] - mu) * rs * sg2[c] + sbe2[c];
                uvals[mf][nf][2 * h + 1] = (uvals[mf][nf][2 * h + 1] - mu) * rs * sg2[c + 1] + sbe2[c + 1];
            }
        }
    __syncthreads();

    // =================== GEMM 3: nodes @ Wn^T (K=128, double-buffered) ======
    #pragma unroll
    for (int mf = 0; mf < 2; mf++)
        #pragma unroll
        for (int nf = 0; nf < 8; nf++)
            #pragma unroll
            for (int i = 0; i < 4; i++) acc[mf][nf][i] = 0.f;
    #pragma unroll 1
    for (int ks = 0; ks < KS2; ks += 2) {
        load_bfrag(g_wnhi, g_wnlo, ks + 1, nbase, qr, qk, bh1, bl1);
        mma_step(acc, sAhi, sAlo, KP1, rbase, ks, qk, bh0, bl0);
        if (ks + 2 < KS2)
            load_bfrag(g_wnhi, g_wnlo, ks + 2, nbase, qr, qk, bh0, bl0);
        mma_step(acc, sAhi, sAlo, KP1, rbase, ks + 1, qk, bh1, bl1);
    }

    // ---- v = acc + u; final LN ----
    #pragma unroll
    for (int mf = 0; mf < 2; mf++)
        #pragma unroll
        for (int nf = 0; nf < 8; nf++)
            #pragma unroll
            for (int i = 0; i < 4; i++)
                uvals[mf][nf][i] += acc[mf][nf][i];

    #pragma unroll
    for (int mf = 0; mf < 2; mf++)
        #pragma unroll
        for (int h = 0; h < 2; h++) {
            float s = 0.f, q = 0.f;
            #pragma unroll
            for (int nf = 0; nf < 8; nf++) {
                float v0 = uvals[mf][nf][2 * h], v1 = uvals[mf][nf][2 * h + 1];
                s += v0 + v1; q += v0 * v0 + v1 * v1;
            }
            s += __shfl_xor_sync(0xffffffffu, s, 1);
            s += __shfl_xor_sync(0xffffffffu, s, 2);
            q += __shfl_xor_sync(0xffffffffu, q, 1);
            q += __shfl_xor_sync(0xffffffffu, q, 2);
            int r = wm * 32 + mf * 16 + h * 8 + qr;
            if ((lane & 3) == 0) { sredS[r][wn] = s; sredQ[r][wn] = q; }
        }
    __syncthreads();

    #pragma unroll
    for (int mf = 0; mf < 2; mf++)
        #pragma unroll
        for (int h = 0; h < 2; h++) {
            int r = wm * 32 + mf * 16 + h * 8 + qr;
            int node = n0 + r;
            if (node >= N_NODES) continue;
            float S = sredS[r][0] + sredS[r][1];
            float Q = sredQ[r][0] + sredQ[r][1];
            float mu = S * (1.f / 128.f);
            float var = Q * (1.f / 128.f) - mu * mu;
            float rs = rsqrtf(var + LN_EPS);
            #pragma unroll
            for (int nf = 0; nf < 8; nf++) {
                int c = nbase + nf * 8 + qk;
                float2 o;
                o.x = (uvals[mf][nf][2 * h] - mu) * rs * sgf[c] + sbef[c];
                o.y = (uvals[mf][nf][2 * h + 1] - mu) * rs * sgf[c + 1] + sbef[c + 1];
                *(float2*)(out + (size_t)node * D + c) = o;
            }
        }
}

// --------------------------- launch -----------------------------------------
extern "C" void kernel_launch(void* const* d_in, const int* in_sizes, int n_in,
                              void* d_out, int out_size) {
    const float* nodes     = (const float*)d_in[0];
    const void*  eidx      = d_in[1];
    const float* edge_attr = (const float*)d_in[2];
    const float* Wm        = (const float*)d_in[3];
    const float* Wn        = (const float*)d_in[4];
    const float* W1        = (const float*)d_in[5];
    const float* b1        = (const float*)d_in[6];
    const float* g1        = (const float*)d_in[7];
    const float* be1       = (const float*)d_in[8];
    const float* W2        = (const float*)d_in[9];
    const float* b2        = (const float*)d_in[10];
    const float* g2        = (const float*)d_in[11];
    const float* be2       = (const float*)d_in[12];
    const float* gf        = (const float*)d_in[13];
    const float* bef       = (const float*)d_in[14];
    float* out = (float*)d_out;

    const int smem = 128 * KP1 * 2 * (int)sizeof(uint16_t);   // 151552
    cudaFuncSetAttribute(node_phase_kernel, cudaFuncAttributeMaxDynamicSharedMemorySize, smem);

    zero_cnt_kernel<<<(N_NODES + 1023) / 1024, 1024>>>();
    convert_hist_kernel<<<1024, 256>>>(eidx);
    blocksum_kernel<<<NB_SCAN, 256>>>();
    scatter_off_kernel<<<NB_SCAN, 256>>>();
    fill_kernel<<<(N_EDGES + 255) / 256, 256>>>();
    pull_kernel<<<(N_NODES + 7) / 8, 256>>>(
        (const float4*)nodes, (const float4*)edge_attr);

    // weight prep
    fuse_w_kernel<<<D, AD>>>(W1, Wm);
    prep_w1_kernel<<<(KS1 * D * 16 + 255) / 256, 256>>>(W1);
    prep_w2_kernel<<<(KS2 * D * 16 + 255) / 256, 256>>>(W2, Wn);

    // fused node phase
    node_phase_kernel<<<NGRP, 256, smem>>>(nodes, b1, g1, be1,
                                           b2, g2, be2, gf, bef, out);
}

// round 6
// speedup vs baseline: 3.3437x; 1.0025x over previous
#include <cuda_runtime.h>
#include <cuda_bf16.h>
#include <cstdint>

// ---------------------------------------------------------------------------
// LinearMessagePassingLayer — GB300 sm_103a, round 6.
//   csr_build: ONE persistent kernel (software grid barrier)
//   pull:      CSR gather-sum (x4 unroll)
//   node:      fused MLP, 512 threads / 128-node tile, bf16 3-term MMA
// ---------------------------------------------------------------------------

#define N_NODES 100000
#define N_EDGES 800000
#define D       128
#define ED      32
#define AD      160
#define LN_EPS  1e-5f
#define NB_SCAN ((N_NODES + 255) / 256)   // 391

#define KS1   18
#define KP1   296
#define KS2   8
#define NGRP  ((N_NODES + 127) / 128)     // 782
#define CSRB  128                          // csr persistent blocks

// --------------------------- device scratch -------------------------------
__device__ float    g_agg[(size_t)N_NODES * AD];
__device__ float    g_wf[D * AD];
__device__ uint16_t g_w1hi[KS1 * D * 16], g_w1lo[KS1 * D * 16];
__device__ uint16_t g_w2hi[KS2 * D * 16], g_w2lo[KS2 * D * 16];
__device__ uint16_t g_wnhi[KS2 * D * 16], g_wnlo[KS2 * D * 16];
__device__ int      g_sr[2 * N_EDGES];
__device__ int      g_cnt[N_NODES];
__device__ int      g_off[N_NODES + 1];
__device__ int      g_sid[N_EDGES];
__device__ int      g_eix[N_EDGES];
__device__ int      g_bsum[NB_SCAN];
__device__ int      g_boff[NB_SCAN];
__device__ unsigned g_bar;                 // grid barrier counter (reset by fuse_w)

// --------------------------- helpers ---------------------------------------
__device__ __forceinline__ uint16_t f2bf(float x) {
    __nv_bfloat16 h = __float2bfloat16(x);
    return *reinterpret_cast<uint16_t*>(&h);
}
__device__ __forceinline__ float bf2f(uint16_t b) {
    __nv_bfloat16 h = *reinterpret_cast<__nv_bfloat16*>(&b);
    return __bfloat162float(h);
}

__device__ __forceinline__ void mma_bf16(float (&c)[4], const uint32_t (&a)[4],
                                         const uint32_t (&b)[2]) {
    asm volatile(
        "mma.sync.aligned.m16n8k16.row.col.f32.bf16.bf16.f32 "
        "{%0,%1,%2,%3},{%4,%5,%6,%7},{%8,%9},{%0,%1,%2,%3};\n"
        : "+f"(c[0]), "+f"(c[1]), "+f"(c[2]), "+f"(c[3])
        : "r"(a[0]), "r"(a[1]), "r"(a[2]), "r"(a[3]), "r"(b[0]), "r"(b[1]));
}

__device__ __forceinline__ void cvt_store(uint16_t* hi, uint16_t* lo, int off, float4 v) {
    uint16_t h0 = f2bf(v.x), h1 = f2bf(v.y), h2 = f2bf(v.z), h3 = f2bf(v.w);
    uint16_t l0 = f2bf(v.x - bf2f(h0)), l1 = f2bf(v.y - bf2f(h1));
    uint16_t l2 = f2bf(v.z - bf2f(h2)), l3 = f2bf(v.w - bf2f(h3));
    *(uint32_t*)(hi + off)     = ((uint32_t)h1 << 16) | h0;
    *(uint32_t*)(hi + off + 2) = ((uint32_t)h3 << 16) | h2;
    *(uint32_t*)(lo + off)     = ((uint32_t)l1 << 16) | l0;
    *(uint32_t*)(lo + off + 2) = ((uint32_t)l3 << 16) | l2;
}

// B fragments for one k-step: 4 n-frags (32 cols), hi+lo
__device__ __forceinline__ void load_bfrag(const uint16_t* __restrict__ whi,
                                           const uint16_t* __restrict__ wlo,
                                           int ks, int nbase, int qr, int qk,
                                           uint32_t (&bh)[4][2], uint32_t (&bl)[4][2]) {
#pragma unroll
    for (int nf = 0; nf < 4; nf++) {
        const uint16_t* p = whi + ((size_t)ks * D + nbase + nf * 8 + qr) * 16 + qk;
        bh[nf][0] = *(const uint32_t*)p;
        bh[nf][1] = *(const uint32_t*)(p + 8);
        const uint16_t* q = wlo + ((size_t)ks * D + nbase + nf * 8 + qr) * 16 + qk;
        bl[nf][0] = *(const uint32_t*)q;
        bl[nf][1] = *(const uint32_t*)(q + 8);
    }
}

__device__ __forceinline__ void load_afrag(const uint16_t* sA, int kp, int row0,
                                           int ks, int qk, uint32_t (&a)[4]) {
    const uint16_t* p = sA + row0 * kp + ks * 16 + qk;
    a[0] = *(const uint32_t*)p;
    a[1] = *(const uint32_t*)(p + 8 * kp);
    a[2] = *(const uint32_t*)(p + 8);
    a[3] = *(const uint32_t*)(p + 8 * kp + 8);
}

__device__ __forceinline__ void mma_step(float (&acc)[2][4][4],
                                         const uint16_t* sAhi, const uint16_t* sAlo,
                                         int kp, int rbase, int ks, int qk,
                                         const uint32_t (&bh)[4][2],
                                         const uint32_t (&bl)[4][2]) {
#pragma unroll
    for (int mf = 0; mf < 2; mf++) {
        uint32_t ah[4], al[4];
        load_afrag(sAhi, kp, rbase + mf * 16, ks, qk, ah);
        load_afrag(sAlo, kp, rbase + mf * 16, ks, qk, al);
#pragma unroll
        for (int nf = 0; nf < 4; nf++) {
            mma_bf16(acc[mf][nf], ah, bh[nf]);
            mma_bf16(acc[mf][nf], ah, bl[nf]);
            mma_bf16(acc[mf][nf], al, bh[nf]);
        }
    }
}

// --------------------------- CSR build (one persistent kernel) -------------
__device__ __forceinline__ void grid_bar(unsigned target) {
    __syncthreads();
    if (threadIdx.x == 0) {
        __threadfence();
        atomicAdd(&g_bar, 1u);
        while (*(volatile unsigned*)&g_bar < target) { }
        __threadfence();
    }
    __syncthreads();
}

__global__ void __launch_bounds__(256)
csr_build_kernel(const void* __restrict__ p) {
    __shared__ int s[256];
    __shared__ int sh_base;
    __shared__ int anynz;
    const int t   = threadIdx.x;
    const int gid = blockIdx.x * 256 + t;
    const int gs  = CSRB * 256;

    // ---- P0: zero counts ----
    for (int i = gid; i < N_NODES; i += gs) g_cnt[i] = 0;
    grid_bar(1 * CSRB);

    // ---- P1: convert indices + histogram receivers ----
    if (t == 0) anynz = 0;
    __syncthreads();
    if (t < 64) {
        if (((const unsigned int*)p)[2 * t + 1] != 0u) atomicOr(&anynz, 1);
    }
    __syncthreads();
    const int is64 = (anynz == 0);
    for (int i = gid; i < 2 * N_EDGES; i += gs) {
        int v = is64 ? (int)((const long long*)p)[i] : ((const int*)p)[i];
        g_sr[i] = v;
        if (i >= N_EDGES) atomicAdd(&g_cnt[v], 1);
    }
    grid_bar(2 * CSRB);

    // ---- P2: per-chunk sums (one warp per 256-chunk) ----
    {
        int w = gid >> 5, lane = t & 31;
        if (w < NB_SCAN) {
            int sum = 0;
            int base = w * 256 + lane * 8;
            #pragma unroll
            for (int j = 0; j < 8; j++) {
                int idx = base + j;
                if (idx < N_NODES) sum += __ldcg(&g_cnt[idx]);
            }
            #pragma unroll
            for (int o = 16; o; o >>= 1) sum += __shfl_xor_sync(0xffffffffu, sum, o);
            if (lane == 0) g_bsum[w] = sum;
        }
    }
    grid_bar(3 * CSRB);

    // ---- P3: scan chunk sums (block 0 only) ----
    if (blockIdx.x == 0) {
        int a = (2 * t < NB_SCAN)     ? __ldcg(&g_bsum[2 * t])     : 0;
        int b = (2 * t + 1 < NB_SCAN) ? __ldcg(&g_bsum[2 * t + 1]) : 0;
        int c = a + b;
        s[t] = c;
        __syncthreads();
        for (int o = 1; o < 256; o <<= 1) {
            int x = (t >= o) ? s[t - o] : 0;
            __syncthreads();
            s[t] += x;
            __syncthreads();
        }
        int excl = s[t] - c;
        if (2 * t < NB_SCAN)     g_boff[2 * t]     = excl;
        if (2 * t + 1 < NB_SCAN) g_boff[2 * t + 1] = excl + a;
    }
    grid_bar(4 * CSRB);

    // ---- P4: scatter offsets (block-per-chunk, grid-stride) ----
    for (int c = blockIdx.x; c < NB_SCAN; c += CSRB) {
        const int i = c * 256 + t;
        int v = (i < N_NODES) ? __ldcg(&g_cnt[i]) : 0;
        s[t] = v;
        if (t == 0) sh_base = __ldcg(&g_boff[c]);
        __syncthreads();
        for (int o = 1; o < 256; o <<= 1) {
            int x = (t >= o) ? s[t - o] : 0;
            __syncthreads();
            s[t] += x;
            __syncthreads();
        }
        if (i < N_NODES) {
            int off = sh_base + s[t] - v;
            g_off[i] = off;
            g_cnt[i] = off;      // cursor
        }
        __syncthreads();
    }
    if (blockIdx.x == 0 && t == 0) g_off[N_NODES] = N_EDGES;
    grid_bar(5 * CSRB);

    // ---- P5: fill (sorted sender/edge ids) ----
    for (int e = gid; e < N_EDGES; e += gs) {
        int r = __ldcg(&g_sr[N_EDGES + e]);
        int pos = atomicAdd(&g_cnt[r], 1);
        g_sid[pos] = __ldcg(&g_sr[e]);
        g_eix[pos] = e;
    }
}

// --------------------------- weight fusion / prep --------------------------
__global__ void __launch_bounds__(AD)
fuse_w_kernel(const float* __restrict__ W1, const float* __restrict__ Wm) {
    __shared__ float sw[D];
    int j = blockIdx.x, c = threadIdx.x;
    if (j == 0 && c == 0) g_bar = 0u;   // reset grid barrier for next replay
    if (c < D) sw[c] = W1[j * (2 * D) + D + c];
    __syncthreads();
    float s = 0.f;
    #pragma unroll 8
    for (int k = 0; k < D; k++)
        s += sw[k] * __ldg(&Wm[k * AD + c]);
    g_wf[j * AD + c] = s;
}

__global__ void prep_all_kernel(const float* __restrict__ W1,
                                const float* __restrict__ W2,
                                const float* __restrict__ Wn) {
    int idx = blockIdx.x * 256 + threadIdx.x;
    if (idx < KS1 * D * 16) {
        int koff = idx & 15, n = (idx >> 4) & 127, ks = idx >> 11;
        int k = ks * 16 + koff;
        float v = (k < D) ? W1[n * (2 * D) + k] : g_wf[n * AD + (k - D)];
        uint16_t hi = f2bf(v);
        g_w1hi[idx] = hi;
        g_w1lo[idx] = f2bf(v - bf2f(hi));
    }
    if (idx < KS2 * D * 16) {
        int koff = idx & 15, n = (idx >> 4) & 127, ks = idx >> 11;
        int k = ks * 16 + koff;
        float v2 = W2[n * D + k];
        uint16_t h2 = f2bf(v2);
        g_w2hi[idx] = h2;
        g_w2lo[idx] = f2bf(v2 - bf2f(h2));
        float vn = Wn[n * D + k];
        uint16_t hn = f2bf(vn);
        g_wnhi[idx] = hn;
        g_wnlo[idx] = f2bf(vn - bf2f(hn));
    }
}

// --------------------------- pull aggregation -------------------------------
__global__ void __launch_bounds__(256)
pull_kernel(const float4* __restrict__ nodes4, const float4* __restrict__ ea4) {
    int n = blockIdx.x * 8 + (threadIdx.x >> 5);
    if (n >= N_NODES) return;
    const int lane = threadIdx.x & 31;
    const int beg = g_off[n], end = g_off[n + 1];
    float4 an = make_float4(0.f, 0.f, 0.f, 0.f);
    float4 ae = make_float4(0.f, 0.f, 0.f, 0.f);
    int i = beg;
    for (; i + 4 <= end; i += 4) {
        int s0 = __ldg(&g_sid[i]),     s1 = __ldg(&g_sid[i + 1]);
        int s2 = __ldg(&g_sid[i + 2]), s3 = __ldg(&g_sid[i + 3]);
        float4 v0 = __ldg(nodes4 + (size_t)s0 * 32 + lane);
        float4 v1 = __ldg(nodes4 + (size_t)s1 * 32 + lane);
        float4 v2 = __ldg(nodes4 + (size_t)s2 * 32 + lane);
        float4 v3 = __ldg(nodes4 + (size_t)s3 * 32 + lane);
        an.x += v0.x + v1.x + v2.x + v3.x;
        an.y += v0.y + v1.y + v2.y + v3.y;
        an.z += v0.z + v1.z + v2.z + v3.z;
        an.w += v0.w + v1.w + v2.w + v3.w;
        if (lane < 8) {
            int e0 = __ldg(&g_eix[i]),     e1 = __ldg(&g_eix[i + 1]);
            int e2 = __ldg(&g_eix[i + 2]), e3 = __ldg(&g_eix[i + 3]);
            float4 w0 = __ldg(ea4 + (size_t)e0 * 8 + lane);
            float4 w1 = __ldg(ea4 + (size_t)e1 * 8 + lane);
            float4 w2 = __ldg(ea4 + (size_t)e2 * 8 + lane);
            float4 w3 = __ldg(ea4 + (size_t)e3 * 8 + lane);
            ae.x += w0.x + w1.x + w2.x + w3.x;
            ae.y += w0.y + w1.y + w2.y + w3.y;
            ae.z += w0.z + w1.z + w2.z + w3.z;
            ae.w += w0.w + w1.w + w2.w + w3.w;
        }
    }
    for (; i < end; i++) {
        int s = __ldg(&g_sid[i]);
        float4 v = __ldg(nodes4 + (size_t)s * 32 + lane);
        an.x += v.x; an.y += v.y; an.z += v.z; an.w += v.w;
        if (lane < 8) {
            int e = __ldg(&g_eix[i]);
            float4 w = __ldg(ea4 + (size_t)e * 8 + lane);
            ae.x += w.x; ae.y += w.y; ae.z += w.z; ae.w += w.w;
        }
    }
    float4* dst = reinterpret_cast<float4*>(g_agg) + (size_t)n * 40;
    dst[lane] = an;
    if (lane < 8) dst[32 + lane] = ae;
}

// --------------------------- fused node phase (512 thr) ---------------------
__global__ void __launch_bounds__(512, 1)
node_phase_kernel(const float* __restrict__ nodes,
                  const float* __restrict__ b1,
                  const float* __restrict__ g1,
                  const float* __restrict__ be1,
                  const float* __restrict__ b2,
                  const float* __restrict__ g2,
                  const float* __restrict__ be2,
                  const float* __restrict__ gf,
                  const float* __restrict__ bef,
                  float* __restrict__ out) {
    extern __shared__ uint16_t smu[];
    uint16_t* sAhi = smu;
    uint16_t* sAlo = smu + 128 * KP1;

    __shared__ float sb1[D], sg1[D], sbe1[D];
    __shared__ float sb2[D], sg2[D], sbe2[D], sgf[D], sbef[D];
    __shared__ float sredS[D][4], sredQ[D][4];

    const int tid = threadIdx.x;
    const int n0 = blockIdx.x * 128;
    if (tid < D) {
        sb1[tid] = b1[tid]; sg1[tid] = g1[tid]; sbe1[tid] = be1[tid];
        sb2[tid] = b2[tid]; sg2[tid] = g2[tid]; sbe2[tid] = be2[tid];
        sgf[tid] = gf[tid]; sbef[tid] = bef[tid];
    }

    // ---- load + convert A = [nodes | agg] ----
    const float4* nsrc = (const float4*)nodes;
    #pragma unroll
    for (int it = 0; it < 8; it++) {
        int idx = it * 512 + tid;
        int row = idx >> 5, c4 = idx & 31;
        float4 v = make_float4(0.f, 0.f, 0.f, 0.f);
        if (n0 + row < N_NODES) v = __ldg(nsrc + (size_t)(n0 + row) * 32 + c4);
        cvt_store(sAhi, sAlo, row * KP1 + c4 * 4, v);
    }
    const float4* asrc = (const float4*)g_agg;
    #pragma unroll
    for (int it = 0; it < 10; it++) {
        int idx = it * 512 + tid;
        int row = idx / 40, c4 = idx % 40;
        float4 v = make_float4(0.f, 0.f, 0.f, 0.f);
        if (n0 + row < N_NODES) v = asrc[(size_t)(n0 + row) * 40 + c4];
        cvt_store(sAhi, sAlo, row * KP1 + 128 + c4 * 4, v);
    }
    __syncthreads();

    const int lane = tid & 31;
    const int wid  = tid >> 5;        // 0..15
    const int wm   = wid >> 2;        // 0..3 (32 rows each)
    const int wn   = wid & 3;         // 0..3 (32 cols each)
    const int qr   = lane >> 2;
    const int qk   = 2 * (lane & 3);
    const int rbase = wm * 32 + qr;
    const int nbase = wn * 32;

    uint32_t bh0[4][2], bl0[4][2], bh1[4][2], bl1[4][2];

    // =================== GEMM 1: [nodes|agg] @ Wcat^T (K=288) ===============
    float acc[2][4][4];
    #pragma unroll
    for (int mf = 0; mf < 2; mf++)
        #pragma unroll
        for (int nf = 0; nf < 4; nf++)
            #pragma unroll
            for (int i = 0; i < 4; i++) acc[mf][nf][i] = 0.f;

    load_bfrag(g_w1hi, g_w1lo, 0, nbase, qr, qk, bh0, bl0);
    #pragma unroll 1
    for (int ks = 0; ks < KS1; ks += 2) {
        load_bfrag(g_w1hi, g_w1lo, ks + 1, nbase, qr, qk, bh1, bl1);
        mma_step(acc, sAhi, sAlo, KP1, rbase, ks, qk, bh0, bl0);
        if (ks + 2 < KS1)
            load_bfrag(g_w1hi, g_w1lo, ks + 2, nbase, qr, qk, bh0, bl0);
        mma_step(acc, sAhi, sAlo, KP1, rbase, ks + 1, qk, bh1, bl1);
    }

    // prefetch GEMM2's first B fragment behind the LN1 epilogue
    load_bfrag(g_w2hi, g_w2lo, 0, nbase, qr, qk, bh0, bl0);

    // ---- bias + relu ----
    float vals[2][4][4];
    #pragma unroll
    for (int mf = 0; mf < 2; mf++)
        #pragma unroll
        for (int nf = 0; nf < 4; nf++) {
            int c = nbase + nf * 8 + qk;
            vals[mf][nf][0] = fmaxf(acc[mf][nf][0] + sb1[c], 0.f);
            vals[mf][nf][1] = fmaxf(acc[mf][nf][1] + sb1[c + 1], 0.f);
            vals[mf][nf][2] = fmaxf(acc[mf][nf][2] + sb1[c], 0.f);
            vals[mf][nf][3] = fmaxf(acc[mf][nf][3] + sb1[c + 1], 0.f);
        }

    // ---- LN1 reductions ----
    #pragma unroll
    for (int mf = 0; mf < 2; mf++)
        #pragma unroll
        for (int h = 0; h < 2; h++) {
            float s = 0.f, q = 0.f;
            #pragma unroll
            for (int nf = 0; nf < 4; nf++) {
                float v0 = vals[mf][nf][2 * h], v1 = vals[mf][nf][2 * h + 1];
                s += v0 + v1; q += v0 * v0 + v1 * v1;
            }
            s += __shfl_xor_sync(0xffffffffu, s, 1);
            s += __shfl_xor_sync(0xffffffffu, s, 2);
            q += __shfl_xor_sync(0xffffffffu, q, 1);
            q += __shfl_xor_sync(0xffffffffu, q, 2);
            int r = wm * 32 + mf * 16 + h * 8 + qr;
            if ((lane & 3) == 0) { sredS[r][wn] = s; sredQ[r][wn] = q; }
        }
    __syncthreads();

    // ---- LN1 apply; write h into the agg columns of sA ----
    #pragma unroll
    for (int mf = 0; mf < 2; mf++)
        #pragma unroll
        for (int h = 0; h < 2; h++) {
            int r = wm * 32 + mf * 16 + h * 8 + qr;
            float S = sredS[r][0] + sredS[r][1] + sredS[r][2] + sredS[r][3];
            float Q = sredQ[r][0] + sredQ[r][1] + sredQ[r][2] + sredQ[r][3];
            float mu = S * (1.f / 128.f);
            float var = Q * (1.f / 128.f) - mu * mu;
            float rs = rsqrtf(var + LN_EPS);
            #pragma unroll
            for (int nf = 0; nf < 4; nf++) {
                int c = nbase + nf * 8 + qk;
                float y0 = (vals[mf][nf][2 * h] - mu) * rs * sg1[c] + sbe1[c];
                float y1 = (vals[mf][nf][2 * h + 1] - mu) * rs * sg1[c + 1] + sbe1[c + 1];
                uint16_t h0 = f2bf(y0), h1 = f2bf(y1);
                uint16_t l0 = f2bf(y0 - bf2f(h0)), l1 = f2bf(y1 - bf2f(h1));
                *(uint32_t*)(sAhi + r * KP1 + 128 + c) = ((uint32_t)h1 << 16) | h0;
                *(uint32_t*)(sAlo + r * KP1 + 128 + c) = ((uint32_t)l1 << 16) | l0;
            }
        }
    __syncthreads();

    // =================== GEMM 2: h @ W2^T (K=128) ===========================
    #pragma unroll
    for (int mf = 0; mf < 2; mf++)
        #pragma unroll
        for (int nf = 0; nf < 4; nf++)
            #pragma unroll
            for (int i = 0; i < 4; i++) acc[mf][nf][i] = 0.f;
    #pragma unroll 1
    for (int ks = 0; ks < KS2; ks += 2) {
        load_bfrag(g_w2hi, g_w2lo, ks + 1, nbase, qr, qk, bh1, bl1);
        mma_step(acc, sAhi + 128, sAlo + 128, KP1, rbase, ks, qk, bh0, bl0);
        if (ks + 2 < KS2)
            load_bfrag(g_w2hi, g_w2lo, ks + 2, nbase, qr, qk, bh0, bl0);
        mma_step(acc, sAhi + 128, sAlo + 128, KP1, rbase, ks + 1, qk, bh1, bl1);
    }

    // prefetch GEMM3's first B fragment behind the LN2 epilogue
    load_bfrag(g_wnhi, g_wnlo, 0, nbase, qr, qk, bh0, bl0);

    // ---- bias + relu -> uvals ----
    float uvals[2][4][4];
    #pragma unroll
    for (int mf = 0; mf < 2; mf++)
        #pragma unroll
        for (int nf = 0; nf < 4; nf++) {
            int c = nbase + nf * 8 + qk;
            uvals[mf][nf][0] = fmaxf(acc[mf][nf][0] + sb2[c], 0.f);
            uvals[mf][nf][1] = fmaxf(acc[mf][nf][1] + sb2[c + 1], 0.f);
            uvals[mf][nf][2] = fmaxf(acc[mf][nf][2] + sb2[c], 0.f);
            uvals[mf][nf][3] = fmaxf(acc[mf][nf][3] + sb2[c + 1], 0.f);
        }

    // ---- LN2 ----
    __syncthreads();
    #pragma unroll
    for (int mf = 0; mf < 2; mf++)
        #pragma unroll
        for (int h = 0; h < 2; h++) {
            float s = 0.f, q = 0.f;
            #pragma unroll
            for (int nf = 0; nf < 4; nf++) {
                float v0 = uvals[mf][nf][2 * h], v1 = uvals[mf][nf][2 * h + 1];
                s += v0 + v1; q += v0 * v0 + v1 * v1;
            }
            s += __shfl_xor_sync(0xffffffffu, s, 1);
            s += __shfl_xor_sync(0xffffffffu, s, 2);
            q += __shfl_xor_sync(0xffffffffu, q, 1);
            q += __shfl_xor_sync(0xffffffffu, q, 2);
            int r = wm * 32 + mf * 16 + h * 8 + qr;
            if ((lane & 3) == 0) { sredS[r][wn] = s; sredQ[r][wn] = q; }
        }
    __syncthreads();

    #pragma unroll
    for (int mf = 0; mf < 2; mf++)
        #pragma unroll
        for (int h = 0; h < 2; h++) {
            int r = wm * 32 + mf * 16 + h * 8 + qr;
            float S = sredS[r][0] + sredS[r][1] + sredS[r][2] + sredS[r][3];
            float Q = sredQ[r][0] + sredQ[r][1] + sredQ[r][2] + sredQ[r][3];
            float mu = S * (1.f / 128.f);
            float var = Q * (1.f / 128.f) - mu * mu;
            float rs = rsqrtf(var + LN_EPS);
            #pragma unroll
            for (int nf = 0; nf < 4; nf++) {
                int c = nbase + nf * 8 + qk;
                uvals[mf][nf][2 * h]     = (uvals[mf][nf][2 * h] - mu) * rs * sg2[c] + sbe2[c];
                uvals[mf][nf][2 * h + 1] = (uvals[mf][nf][2 * h + 1] - mu) * rs * sg2[c + 1] + sbe2[c + 1];
            }
        }
    __syncthreads();

    // =================== GEMM 3: nodes @ Wn^T (K=128) =======================
    #pragma unroll
    for (int mf = 0; mf < 2; mf++)
        #pragma unroll
        for (int nf = 0; nf < 4; nf++)
            #pragma unroll
            for (int i = 0; i < 4; i++) acc[mf][nf][i] = 0.f;
    #pragma unroll 1
    for (int ks = 0; ks < KS2; ks += 2) {
        load_bfrag(g_wnhi, g_wnlo, ks + 1, nbase, qr, qk, bh1, bl1);
        mma_step(acc, sAhi, sAlo, KP1, rbase, ks, qk, bh0, bl0);
        if (ks + 2 < KS2)
            load_bfrag(g_wnhi, g_wnlo, ks + 2, nbase, qr, qk, bh0, bl0);
        mma_step(acc, sAhi, sAlo, KP1, rbase, ks + 1, qk, bh1, bl1);
    }

    // ---- v = acc + u; final LN ----
    #pragma unroll
    for (int mf = 0; mf < 2; mf++)
        #pragma unroll
        for (int nf = 0; nf < 4; nf++)
            #pragma unroll
            for (int i = 0; i < 4; i++)
                uvals[mf][nf][i] += acc[mf][nf][i];

    #pragma unroll
    for (int mf = 0; mf < 2; mf++)
        #pragma unroll
        for (int h = 0; h < 2; h++) {
            float s = 0.f, q = 0.f;
            #pragma unroll
            for (int nf = 0; nf < 4; nf++) {
                float v0 = uvals[mf][nf][2 * h], v1 = uvals[mf][nf][2 * h + 1];
                s += v0 + v1; q += v0 * v0 + v1 * v1;
            }
            s += __shfl_xor_sync(0xffffffffu, s, 1);
            s += __shfl_xor_sync(0xffffffffu, s, 2);
            q += __shfl_xor_sync(0xffffffffu, q, 1);
            q += __shfl_xor_sync(0xffffffffu, q, 2);
            int r = wm * 32 + mf * 16 + h * 8 + qr;
            if ((lane & 3) == 0) { sredS[r][wn] = s; sredQ[r][wn] = q; }
        }
    __syncthreads();

    #pragma unroll
    for (int mf = 0; mf < 2; mf++)
        #pragma unroll
        for (int h = 0; h < 2; h++) {
            int r = wm * 32 + mf * 16 + h * 8 + qr;
            int node = n0 + r;
            if (node >= N_NODES) continue;
            float S = sredS[r][0] + sredS[r][1] + sredS[r][2] + sredS[r][3];
            float Q = sredQ[r][0] + sredQ[r][1] + sredQ[r][2] + sredQ[r][3];
            float mu = S * (1.f / 128.f);
            float var = Q * (1.f / 128.f) - mu * mu;
            float rs = rsqrtf(var + LN_EPS);
            #pragma unroll
            for (int nf = 0; nf < 4; nf++) {
                int c = nbase + nf * 8 + qk;
                float2 o;
                o.x = (uvals[mf][nf][2 * h] - mu) * rs * sgf[c] + sbef[c];
                o.y = (uvals[mf][nf][2 * h + 1] - mu) * rs * sgf[c + 1] + sbef[c + 1];
                *(float2*)(out + (size_t)node * D + c) = o;
            }
        }
}

// --------------------------- launch -----------------------------------------
extern "C" void kernel_launch(void* const* d_in, const int* in_sizes, int n_in,
                              void* d_out, int out_size) {
    const float* nodes     = (const float*)d_in[0];
    const void*  eidx      = d_in[1];
    const float* edge_attr = (const float*)d_in[2];
    const float* Wm        = (const float*)d_in[3];
    const float* Wn        = (const float*)d_in[4];
    const float* W1        = (const float*)d_in[5];
    const float* b1        = (const float*)d_in[6];
    const float* g1        = (const float*)d_in[7];
    const float* be1       = (const float*)d_in[8];
    const float* W2        = (const float*)d_in[9];
    const float* b2        = (const float*)d_in[10];
    const float* g2        = (const float*)d_in[11];
    const float* be2       = (const float*)d_in[12];
    const float* gf        = (const float*)d_in[13];
    const float* bef       = (const float*)d_in[14];
    float* out = (float*)d_out;

    const int smem = 128 * KP1 * 2 * (int)sizeof(uint16_t);   // 151552
    cudaFuncSetAttribute(node_phase_kernel, cudaFuncAttributeMaxDynamicSharedMemorySize, smem);

    csr_build_kernel<<<CSRB, 256>>>(eidx);                                   // 1
    fuse_w_kernel<<<D, AD>>>(W1, Wm);                                        // 2 (+bar reset)
    prep_all_kernel<<<(KS1 * D * 16 + 255) / 256, 256>>>(W1, W2, Wn);        // 3
    pull_kernel<<<(N_NODES + 7) / 8, 256>>>(                                 // 4
        (const float4*)nodes, (const float4*)edge_attr);
    node_phase_kernel<<<NGRP, 512, smem>>>(nodes, b1, g1, be1,               // 5
                                           b2, g2, be2, gf, bef, out);
}

// round 7
// speedup vs baseline: 3.4947x; 1.0452x over previous
#include <cuda_runtime.h>
#include <cuda_bf16.h>
#include <cstdint>

// ---------------------------------------------------------------------------
// LinearMessagePassingLayer — GB300 sm_103a, round 7.
//   csr_build: persistent kernel (software grid barrier)
//   pull:      CSR gather-sum (x4 unroll)   [~78us, at DRAM floor]
//   node:      fused MLP, 512 thr / 128-node tile, bf16 3-term MMA
//              NEW: B weights prepacked per-lane (LDG.128), A via ldmatrix.x4
// ---------------------------------------------------------------------------

#define N_NODES 100000
#define N_EDGES 800000
#define D       128
#define ED      32
#define AD      160
#define LN_EPS  1e-5f
#define NB_SCAN ((N_NODES + 255) / 256)   // 391

#define KS1   18
#define KP1   296
#define KS2   8
#define NGRP  ((N_NODES + 127) / 128)     // 782
#define CSRB  128

// --------------------------- device scratch -------------------------------
__device__ float    g_agg[(size_t)N_NODES * AD];
__device__ float    g_wf[D * AD];
// prepacked fragment weights: [ks][ngrp(16)][lane(32)] uint4 {hi0,hi1,lo0,lo1}
__device__ uint4    g_w1p[KS1 * 16 * 32];
__device__ uint4    g_w2p[KS2 * 16 * 32];
__device__ uint4    g_wnp[KS2 * 16 * 32];
__device__ int      g_sr[2 * N_EDGES];
__device__ int      g_cnt[N_NODES];
__device__ int      g_off[N_NODES + 1];
__device__ int      g_sid[N_EDGES];
__device__ int      g_eix[N_EDGES];
__device__ int      g_bsum[NB_SCAN];
__device__ int      g_boff[NB_SCAN];
__device__ unsigned g_bar;

// --------------------------- helpers ---------------------------------------
__device__ __forceinline__ uint16_t f2bf(float x) {
    __nv_bfloat16 h = __float2bfloat16(x);
    return *reinterpret_cast<uint16_t*>(&h);
}
__device__ __forceinline__ float bf2f(uint16_t b) {
    __nv_bfloat16 h = *reinterpret_cast<__nv_bfloat16*>(&b);
    return __bfloat162float(h);
}

__device__ __forceinline__ uint32_t smem_u32(const void* p) {
    uint32_t a;
    asm("{ .reg .u64 t; cvta.to.shared.u64 t, %1; cvt.u32.u64 %0, t; }"
        : "=r"(a) : "l"(p));
    return a;
}

__device__ __forceinline__ void mma_bf16(float (&c)[4], const uint32_t (&a)[4],
                                         uint32_t b0, uint32_t b1) {
    asm volatile(
        "mma.sync.aligned.m16n8k16.row.col.f32.bf16.bf16.f32 "
        "{%0,%1,%2,%3},{%4,%5,%6,%7},{%8,%9},{%0,%1,%2,%3};\n"
        : "+f"(c[0]), "+f"(c[1]), "+f"(c[2]), "+f"(c[3])
        : "r"(a[0]), "r"(a[1]), "r"(a[2]), "r"(a[3]), "r"(b0), "r"(b1));
}

__device__ __forceinline__ void ldsm_x4(uint32_t (&a)[4], uint32_t addr) {
    asm volatile("ldmatrix.sync.aligned.m8n8.x4.shared.b16 {%0,%1,%2,%3}, [%4];"
                 : "=r"(a[0]), "=r"(a[1]), "=r"(a[2]), "=r"(a[3]) : "r"(addr));
}

__device__ __forceinline__ void cvt_store(uint16_t* hi, uint16_t* lo, int off, float4 v) {
    uint16_t h0 = f2bf(v.x), h1 = f2bf(v.y), h2 = f2bf(v.z), h3 = f2bf(v.w);
    uint16_t l0 = f2bf(v.x - bf2f(h0)), l1 = f2bf(v.y - bf2f(h1));
    uint16_t l2 = f2bf(v.z - bf2f(h2)), l3 = f2bf(v.w - bf2f(h3));
    *(uint32_t*)(hi + off)     = ((uint32_t)h1 << 16) | h0;
    *(uint32_t*)(hi + off + 2) = ((uint32_t)h3 << 16) | h2;
    *(uint32_t*)(lo + off)     = ((uint32_t)l1 << 16) | l0;
    *(uint32_t*)(lo + off + 2) = ((uint32_t)l3 << 16) | l2;
}

// one MMA k-step: A frags via ldmatrix (hi/lo, 2 m-frags), B from uint4 regs
__device__ __forceinline__ void mma_step_lm(float (&acc)[2][4][4],
                                            uint32_t aHi0, uint32_t aHi1,
                                            uint32_t aLo0, uint32_t aLo1,
                                            const uint4 (&B)[4]) {
    uint32_t ah0[4], ah1[4], al0[4], al1[4];
    ldsm_x4(ah0, aHi0);
    ldsm_x4(ah1, aHi1);
    ldsm_x4(al0, aLo0);
    ldsm_x4(al1, aLo1);
#pragma unroll
    for (int nf = 0; nf < 4; nf++) {
        mma_bf16(acc[0][nf], ah0, B[nf].x, B[nf].y);
        mma_bf16(acc[0][nf], ah0, B[nf].z, B[nf].w);
        mma_bf16(acc[0][nf], al0, B[nf].x, B[nf].y);
        mma_bf16(acc[1][nf], ah1, B[nf].x, B[nf].y);
        mma_bf16(acc[1][nf], ah1, B[nf].z, B[nf].w);
        mma_bf16(acc[1][nf], al1, B[nf].x, B[nf].y);
    }
}

__device__ __forceinline__ void load_bp(const uint4* __restrict__ wp, int ks,
                                        int wn, int lane, uint4 (&B)[4]) {
#pragma unroll
    for (int nf = 0; nf < 4; nf++)
        B[nf] = __ldg(wp + ((size_t)ks * 16 + wn * 4 + nf) * 32 + lane);
}

// --------------------------- CSR build (persistent) ------------------------
__device__ __forceinline__ void grid_bar(unsigned target) {
    __syncthreads();
    if (threadIdx.x == 0) {
        __threadfence();
        atomicAdd(&g_bar, 1u);
        while (*(volatile unsigned*)&g_bar < target) { }
        __threadfence();
    }
    __syncthreads();
}

__global__ void __launch_bounds__(256)
csr_build_kernel(const void* __restrict__ p) {
    __shared__ int s[256];
    __shared__ int sh_base;
    __shared__ int anynz;
    const int t   = threadIdx.x;
    const int gid = blockIdx.x * 256 + t;
    const int gs  = CSRB * 256;

    for (int i = gid; i < N_NODES; i += gs) g_cnt[i] = 0;
    grid_bar(1 * CSRB);

    if (t == 0) anynz = 0;
    __syncthreads();
    if (t < 64) {
        if (((const unsigned int*)p)[2 * t + 1] != 0u) atomicOr(&anynz, 1);
    }
    __syncthreads();
    const int is64 = (anynz == 0);
    for (int i = gid; i < 2 * N_EDGES; i += gs) {
        int v = is64 ? (int)((const long long*)p)[i] : ((const int*)p)[i];
        g_sr[i] = v;
        if (i >= N_EDGES) atomicAdd(&g_cnt[v], 1);
    }
    grid_bar(2 * CSRB);

    {
        int w = gid >> 5, lane = t & 31;
        if (w < NB_SCAN) {
            int sum = 0;
            int base = w * 256 + lane * 8;
            #pragma unroll
            for (int j = 0; j < 8; j++) {
                int idx = base + j;
                if (idx < N_NODES) sum += __ldcg(&g_cnt[idx]);
            }
            #pragma unroll
            for (int o = 16; o; o >>= 1) sum += __shfl_xor_sync(0xffffffffu, sum, o);
            if (lane == 0) g_bsum[w] = sum;
        }
    }
    grid_bar(3 * CSRB);

    if (blockIdx.x == 0) {
        int a = (2 * t < NB_SCAN)     ? __ldcg(&g_bsum[2 * t])     : 0;
        int b = (2 * t + 1 < NB_SCAN) ? __ldcg(&g_bsum[2 * t + 1]) : 0;
        int c = a + b;
        s[t] = c;
        __syncthreads();
        for (int o = 1; o < 256; o <<= 1) {
            int x = (t >= o) ? s[t - o] : 0;
            __syncthreads();
            s[t] += x;
            __syncthreads();
        }
        int excl = s[t] - c;
        if (2 * t < NB_SCAN)     g_boff[2 * t]     = excl;
        if (2 * t + 1 < NB_SCAN) g_boff[2 * t + 1] = excl + a;
    }
    grid_bar(4 * CSRB);

    for (int c = blockIdx.x; c < NB_SCAN; c += CSRB) {
        const int i = c * 256 + t;
        int v = (i < N_NODES) ? __ldcg(&g_cnt[i]) : 0;
        s[t] = v;
        if (t == 0) sh_base = __ldcg(&g_boff[c]);
        __syncthreads();
        for (int o = 1; o < 256; o <<= 1) {
            int x = (t >= o) ? s[t - o] : 0;
            __syncthreads();
            s[t] += x;
            __syncthreads();
        }
        if (i < N_NODES) {
            int off = sh_base + s[t] - v;
            g_off[i] = off;
            g_cnt[i] = off;
        }
        __syncthreads();
    }
    if (blockIdx.x == 0 && t == 0) g_off[N_NODES] = N_EDGES;
    grid_bar(5 * CSRB);

    for (int e = gid; e < N_EDGES; e += gs) {
        int r = __ldcg(&g_sr[N_EDGES + e]);
        int pos = atomicAdd(&g_cnt[r], 1);
        g_sid[pos] = __ldcg(&g_sr[e]);
        g_eix[pos] = e;
    }
}

// --------------------------- weight fusion / prep --------------------------
__global__ void __launch_bounds__(AD)
fuse_w_kernel(const float* __restrict__ W1, const float* __restrict__ Wm) {
    __shared__ float sw[D];
    int j = blockIdx.x, c = threadIdx.x;
    if (j == 0 && c == 0) g_bar = 0u;   // reset grid barrier for next replay
    if (c < D) sw[c] = W1[j * (2 * D) + D + c];
    __syncthreads();
    float s = 0.f;
    #pragma unroll 8
    for (int k = 0; k < D; k++)
        s += sw[k] * __ldg(&Wm[k * AD + c]);
    g_wf[j * AD + c] = s;
}

__device__ __forceinline__ uint4 pack_frag(float v0, float v1, float v2, float v3) {
    uint16_t h0 = f2bf(v0), h1 = f2bf(v1), h2 = f2bf(v2), h3 = f2bf(v3);
    uint16_t l0 = f2bf(v0 - bf2f(h0)), l1 = f2bf(v1 - bf2f(h1));
    uint16_t l2 = f2bf(v2 - bf2f(h2)), l3 = f2bf(v3 - bf2f(h3));
    uint4 r;
    r.x = ((uint32_t)h1 << 16) | h0;
    r.y = ((uint32_t)h3 << 16) | h2;
    r.z = ((uint32_t)l1 << 16) | l0;
    r.w = ((uint32_t)l3 << 16) | l2;
    return r;
}

__global__ void prep_all_kernel(const float* __restrict__ W1,
                                const float* __restrict__ W2,
                                const float* __restrict__ Wn) {
    int idx = blockIdx.x * 256 + threadIdx.x;
    int lane = idx & 31, ngrp = (idx >> 5) & 15, ks = idx >> 9;
    int qr = lane >> 2, qkq = lane & 3;
    int n = ngrp * 8 + qr;
    int k0 = ks * 16 + 2 * qkq;
    if (idx < KS1 * 16 * 32) {
        float v[4];
        #pragma unroll
        for (int j = 0; j < 4; j++) {
            int k = k0 + (j >> 1) * 8 + (j & 1);
            v[j] = (k < D) ? W1[n * (2 * D) + k] : g_wf[n * AD + (k - D)];
        }
        g_w1p[idx] = pack_frag(v[0], v[1], v[2], v[3]);
    }
    if (idx < KS2 * 16 * 32) {
        g_w2p[idx] = pack_frag(W2[n * D + k0],     W2[n * D + k0 + 1],
                               W2[n * D + k0 + 8], W2[n * D + k0 + 9]);
        g_wnp[idx] = pack_frag(Wn[n * D + k0],     Wn[n * D + k0 + 1],
                               Wn[n * D + k0 + 8], Wn[n * D + k0 + 9]);
    }
}

// --------------------------- pull aggregation -------------------------------
__global__ void __launch_bounds__(256)
pull_kernel(const float4* __restrict__ nodes4, const float4* __restrict__ ea4) {
    int n = blockIdx.x * 8 + (threadIdx.x >> 5);
    if (n >= N_NODES) return;
    const int lane = threadIdx.x & 31;
    const int beg = g_off[n], end = g_off[n + 1];
    float4 an = make_float4(0.f, 0.f, 0.f, 0.f);
    float4 ae = make_float4(0.f, 0.f, 0.f, 0.f);
    int i = beg;
    for (; i + 4 <= end; i += 4) {
        int s0 = __ldg(&g_sid[i]),     s1 = __ldg(&g_sid[i + 1]);
        int s2 = __ldg(&g_sid[i + 2]), s3 = __ldg(&g_sid[i + 3]);
        float4 v0 = __ldg(nodes4 + (size_t)s0 * 32 + lane);
        float4 v1 = __ldg(nodes4 + (size_t)s1 * 32 + lane);
        float4 v2 = __ldg(nodes4 + (size_t)s2 * 32 + lane);
        float4 v3 = __ldg(nodes4 + (size_t)s3 * 32 + lane);
        an.x += v0.x + v1.x + v2.x + v3.x;
        an.y += v0.y + v1.y + v2.y + v3.y;
        an.z += v0.z + v1.z + v2.z + v3.z;
        an.w += v0.w + v1.w + v2.w + v3.w;
        if (lane < 8) {
            int e0 = __ldg(&g_eix[i]),     e1 = __ldg(&g_eix[i + 1]);
            int e2 = __ldg(&g_eix[i + 2]), e3 = __ldg(&g_eix[i + 3]);
            float4 w0 = __ldg(ea4 + (size_t)e0 * 8 + lane);
            float4 w1 = __ldg(ea4 + (size_t)e1 * 8 + lane);
            float4 w2 = __ldg(ea4 + (size_t)e2 * 8 + lane);
            float4 w3 = __ldg(ea4 + (size_t)e3 * 8 + lane);
            ae.x += w0.x + w1.x + w2.x + w3.x;
            ae.y += w0.y + w1.y + w2.y + w3.y;
            ae.z += w0.z + w1.z + w2.z + w3.z;
            ae.w += w0.w + w1.w + w2.w + w3.w;
        }
    }
    for (; i < end; i++) {
        int s = __ldg(&g_sid[i]);
        float4 v = __ldg(nodes4 + (size_t)s * 32 + lane);
        an.x += v.x; an.y += v.y; an.z += v.z; an.w += v.w;
        if (lane < 8) {
            int e = __ldg(&g_eix[i]);
            float4 w = __ldg(ea4 + (size_t)e * 8 + lane);
            ae.x += w.x; ae.y += w.y; ae.z += w.z; ae.w += w.w;
        }
    }
    float4* dst = reinterpret_cast<float4*>(g_agg) + (size_t)n * 40;
    dst[lane] = an;
    if (lane < 8) dst[32 + lane] = ae;
}

// --------------------------- fused node phase (512 thr) ---------------------
__global__ void __launch_bounds__(512, 1)
node_phase_kernel(const float* __restrict__ nodes,
                  const float* __restrict__ b1,
                  const float* __restrict__ g1,
                  const float* __restrict__ be1,
                  const float* __restrict__ b2,
                  const float* __restrict__ g2,
                  const float* __restrict__ be2,
                  const float* __restrict__ gf,
                  const float* __restrict__ bef,
                  float* __restrict__ out) {
    extern __shared__ uint16_t smu[];
    uint16_t* sAhi = smu;
    uint16_t* sAlo = smu + 128 * KP1;

    __shared__ float sb1[D], sg1[D], sbe1[D];
    __shared__ float sb2[D], sg2[D], sbe2[D], sgf[D], sbef[D];
    __shared__ float sredS[D][4], sredQ[D][4];

    const int tid = threadIdx.x;
    const int n0 = blockIdx.x * 128;
    if (tid < D) {
        sb1[tid] = b1[tid]; sg1[tid] = g1[tid]; sbe1[tid] = be1[tid];
        sb2[tid] = b2[tid]; sg2[tid] = g2[tid]; sbe2[tid] = be2[tid];
        sgf[tid] = gf[tid]; sbef[tid] = bef[tid];
    }

    // ---- load + convert A = [nodes | agg] ----
    const float4* nsrc = (const float4*)nodes;
    #pragma unroll
    for (int it = 0; it < 8; it++) {
        int idx = it * 512 + tid;
        int row = idx >> 5, c4 = idx & 31;
        float4 v = make_float4(0.f, 0.f, 0.f, 0.f);
        if (n0 + row < N_NODES) v = __ldg(nsrc + (size_t)(n0 + row) * 32 + c4);
        cvt_store(sAhi, sAlo, row * KP1 + c4 * 4, v);
    }
    const float4* asrc = (const float4*)g_agg;
    #pragma unroll
    for (int it = 0; it < 10; it++) {
        int idx = it * 512 + tid;
        int row = idx / 40, c4 = idx % 40;
        float4 v = make_float4(0.f, 0.f, 0.f, 0.f);
        if (n0 + row < N_NODES) v = asrc[(size_t)(n0 + row) * 40 + c4];
        cvt_store(sAhi, sAlo, row * KP1 + 128 + c4 * 4, v);
    }
    __syncthreads();

    const int lane = tid & 31;
    const int wid  = tid >> 5;        // 0..15
    const int wm   = wid >> 2;        // m-tile (32 rows)
    const int wn   = wid & 3;         // n-tile (32 cols)
    const int qr   = lane >> 2;
    const int qk   = 2 * (lane & 3);
    const int nbase = wn * 32;

    // ldmatrix per-lane addressing: lanes 0-7 M0(rows 0-7,k 0-7),
    // 8-15 M1(rows 8-15,k 0-7), 16-23 M2(rows 0-7,k 8-15), 24-31 M3(rows 8-15,k 8-15)
    const int mrow = ((lane >> 3) & 1) * 8 + (lane & 7);
    const int kof  = (lane >> 4) * 8;                   // u16 units
    const uint32_t sbase = smem_u32(smu);
    const uint32_t aHi0 = sbase + ((wm * 32 + mrow) * KP1 + kof) * 2;
    const uint32_t aHi1 = aHi0 + 16 * KP1 * 2;
    const uint32_t aLo0 = aHi0 + 128 * KP1 * 2;
    const uint32_t aLo1 = aHi1 + 128 * KP1 * 2;

    const uint4* wp1 = (const uint4*)g_w1p;
    const uint4* wp2 = (const uint4*)g_w2p;
    const uint4* wpn = (const uint4*)g_wnp;
    uint4 B0[4], B1[4];

    // =================== GEMM 1: [nodes|agg] @ Wcat^T (K=288) ===============
    float acc[2][4][4];
    #pragma unroll
    for (int mf = 0; mf < 2; mf++)
        #pragma unroll
        for (int nf = 0; nf < 4; nf++)
            #pragma unroll
            for (int i = 0; i < 4; i++) acc[mf][nf][i] = 0.f;

    load_bp(wp1, 0, wn, lane, B0);
    #pragma unroll 1
    for (int ks = 0; ks < KS1; ks += 2) {
        load_bp(wp1, ks + 1, wn, lane, B1);
        mma_step_lm(acc, aHi0 + ks * 32, aHi1 + ks * 32,
                    aLo0 + ks * 32, aLo1 + ks * 32, B0);
        if (ks + 2 < KS1) load_bp(wp1, ks + 2, wn, lane, B0);
        mma_step_lm(acc, aHi0 + (ks + 1) * 32, aHi1 + (ks + 1) * 32,
                    aLo0 + (ks + 1) * 32, aLo1 + (ks + 1) * 32, B1);
    }

    // prefetch GEMM2's first B fragment behind the LN1 epilogue
    load_bp(wp2, 0, wn, lane, B0);

    // ---- bias + relu ----
    float vals[2][4][4];
    #pragma unroll
    for (int mf = 0; mf < 2; mf++)
        #pragma unroll
        for (int nf = 0; nf < 4; nf++) {
            int c = nbase + nf * 8 + qk;
            vals[mf][nf][0] = fmaxf(acc[mf][nf][0] + sb1[c], 0.f);
            vals[mf][nf][1] = fmaxf(acc[mf][nf][1] + sb1[c + 1], 0.f);
            vals[mf][nf][2] = fmaxf(acc[mf][nf][2] + sb1[c], 0.f);
            vals[mf][nf][3] = fmaxf(acc[mf][nf][3] + sb1[c + 1], 0.f);
        }

    // ---- LN1 reductions ----
    #pragma unroll
    for (int mf = 0; mf < 2; mf++)
        #pragma unroll
        for (int h = 0; h < 2; h++) {
            float s = 0.f, q = 0.f;
            #pragma unroll
            for (int nf = 0; nf < 4; nf++) {
                float v0 = vals[mf][nf][2 * h], v1 = vals[mf][nf][2 * h + 1];
                s += v0 + v1; q += v0 * v0 + v1 * v1;
            }
            s += __shfl_xor_sync(0xffffffffu, s, 1);
            s += __shfl_xor_sync(0xffffffffu, s, 2);
            q += __shfl_xor_sync(0xffffffffu, q, 1);
            q += __shfl_xor_sync(0xffffffffu, q, 2);
            int r = wm * 32 + mf * 16 + h * 8 + qr;
            if ((lane & 3) == 0) { sredS[r][wn] = s; sredQ[r][wn] = q; }
        }
    __syncthreads();

    // ---- LN1 apply; write h into the agg columns of sA ----
    #pragma unroll
    for (int mf = 0; mf < 2; mf++)
        #pragma unroll
        for (int h = 0; h < 2; h++) {
            int r = wm * 32 + mf * 16 + h * 8 + qr;
            float S = sredS[r][0] + sredS[r][1] + sredS[r][2] + sredS[r][3];
            float Q = sredQ[r][0] + sredQ[r][1] + sredQ[r][2] + sredQ[r][3];
            float mu = S * (1.f / 128.f);
            float var = Q * (1.f / 128.f) - mu * mu;
            float rs = rsqrtf(var + LN_EPS);
            #pragma unroll
            for (int nf = 0; nf < 4; nf++) {
                int c = nbase + nf * 8 + qk;
                float y0 = (vals[mf][nf][2 * h] - mu) * rs * sg1[c] + sbe1[c];
                float y1 = (vals[mf][nf][2 * h + 1] - mu) * rs * sg1[c + 1] + sbe1[c + 1];
                uint16_t h0 = f2bf(y0), h1 = f2bf(y1);
                uint16_t l0 = f2bf(y0 - bf2f(h0)), l1 = f2bf(y1 - bf2f(h1));
                *(uint32_t*)(sAhi + r * KP1 + 128 + c) = ((uint32_t)h1 << 16) | h0;
                *(uint32_t*)(sAlo + r * KP1 + 128 + c) = ((uint32_t)l1 << 16) | l0;
            }
        }
    __syncthreads();

    // =================== GEMM 2: h @ W2^T (K=128) ===========================
    #pragma unroll
    for (int mf = 0; mf < 2; mf++)
        #pragma unroll
        for (int nf = 0; nf < 4; nf++)
            #pragma unroll
            for (int i = 0; i < 4; i++) acc[mf][nf][i] = 0.f;
    // A = h at column offset 128 u16 = +256 bytes
    #pragma unroll 1
    for (int ks = 0; ks < KS2; ks += 2) {
        load_bp(wp2, ks + 1, wn, lane, B1);
        mma_step_lm(acc, aHi0 + 256 + ks * 32, aHi1 + 256 + ks * 32,
                    aLo0 + 256 + ks * 32, aLo1 + 256 + ks * 32, B0);
        if (ks + 2 < KS2) load_bp(wp2, ks + 2, wn, lane, B0);
        mma_step_lm(acc, aHi0 + 256 + (ks + 1) * 32, aHi1 + 256 + (ks + 1) * 32,
                    aLo0 + 256 + (ks + 1) * 32, aLo1 + 256 + (ks + 1) * 32, B1);
    }

    // prefetch GEMM3's first B fragment behind the LN2 epilogue
    load_bp(wpn, 0, wn, lane, B0);

    // ---- bias + relu -> uvals ----
    float uvals[2][4][4];
    #pragma unroll
    for (int mf = 0; mf < 2; mf++)
        #pragma unroll
        for (int nf = 0; nf < 4; nf++) {
            int c = nbase + nf * 8 + qk;
            uvals[mf][nf][0] = fmaxf(acc[mf][nf][0] + sb2[c], 0.f);
            uvals[mf][nf][1] = fmaxf(acc[mf][nf][1] + sb2[c + 1], 0.f);
            uvals[mf][nf][2] = fmaxf(acc[mf][nf][2] + sb2[c], 0.f);
            uvals[mf][nf][3] = fmaxf(acc[mf][nf][3] + sb2[c + 1], 0.f);
        }

    // ---- LN2 ----
    __syncthreads();
    #pragma unroll
    for (int mf = 0; mf < 2; mf++)
        #pragma unroll
        for (int h = 0; h < 2; h++) {
            float s = 0.f, q = 0.f;
            #pragma unroll
            for (int nf = 0; nf < 4; nf++) {
                float v0 = uvals[mf][nf][2 * h], v1 = uvals[mf][nf][2 * h + 1];
                s += v0 + v1; q += v0 * v0 + v1 * v1;
            }
            s += __shfl_xor_sync(0xffffffffu, s, 1);
            s += __shfl_xor_sync(0xffffffffu, s, 2);
            q += __shfl_xor_sync(0xffffffffu, q, 1);
            q += __shfl_xor_sync(0xffffffffu, q, 2);
            int r = wm * 32 + mf * 16 + h * 8 + qr;
            if ((lane & 3) == 0) { sredS[r][wn] = s; sredQ[r][wn] = q; }
        }
    __syncthreads();

    #pragma unroll
    for (int mf = 0; mf < 2; mf++)
        #pragma unroll
        for (int h = 0; h < 2; h++) {
            int r = wm * 32 + mf * 16 + h * 8 + qr;
            float S = sredS[r][0] + sredS[r][1] + sredS[r][2] + sredS[r][3];
            float Q = sredQ[r][0] + sredQ[r][1] + sredQ[r][2] + sredQ[r][3];
            float mu = S * (1.f / 128.f);
            float var = Q * (1.f / 128.f) - mu * mu;
            float rs = rsqrtf(var + LN_EPS);
            #pragma unroll
            for (int nf = 0; nf < 4; nf++) {
                int c = nbase + nf * 8 + qk;
                uvals[mf][nf][2 * h]     = (uvals[mf][nf][2 * h] - mu) * rs * sg2[c] + sbe2[c];
                uvals[mf][nf][2 * h + 1] = (uvals[mf][nf][2 * h + 1] - mu) * rs * sg2[c + 1] + sbe2[c + 1];
            }
        }
    __syncthreads();

    // =================== GEMM 3: nodes @ Wn^T (K=128) =======================
    #pragma unroll
    for (int mf = 0; mf < 2; mf++)
        #pragma unroll
        for (int nf = 0; nf < 4; nf++)
            #pragma unroll
            for (int i = 0; i < 4; i++) acc[mf][nf][i] = 0.f;
    #pragma unroll 1
    for (int ks = 0; ks < KS2; ks += 2) {
        load_bp(wpn, ks + 1, wn, lane, B1);
        mma_step_lm(acc, aHi0 + ks * 32, aHi1 + ks * 32,
                    aLo0 + ks * 32, aLo1 + ks * 32, B0);
        if (ks + 2 < KS2) load_bp(wpn, ks + 2, wn, lane, B0);
        mma_step_lm(acc, aHi0 + (ks + 1) * 32, aHi1 + (ks + 1) * 32,
                    aLo0 + (ks + 1) * 32, aLo1 + (ks + 1) * 32, B1);
    }

    // ---- v = acc + u; final LN ----
    #pragma unroll
    for (int mf = 0; mf < 2; mf++)
        #pragma unroll
        for (int nf = 0; nf < 4; nf++)
            #pragma unroll
            for (int i = 0; i < 4; i++)
                uvals[mf][nf][i] += acc[mf][nf][i];

    #pragma unroll
    for (int mf = 0; mf < 2; mf++)
        #pragma unroll
        for (int h = 0; h < 2; h++) {
            float s = 0.f, q = 0.f;
            #pragma unroll
            for (int nf = 0; nf < 4; nf++) {
                float v0 = uvals[mf][nf][2 * h], v1 = uvals[mf][nf][2 * h + 1];
                s += v0 + v1; q += v0 * v0 + v1 * v1;
            }
            s += __shfl_xor_sync(0xffffffffu, s, 1);
            s += __shfl_xor_sync(0xffffffffu, s, 2);
            q += __shfl_xor_sync(0xffffffffu, q, 1);
            q += __shfl_xor_sync(0xffffffffu, q, 2);
            int r = wm * 32 + mf * 16 + h * 8 + qr;
            if ((lane & 3) == 0) { sredS[r][wn] = s; sredQ[r][wn] = q; }
        }
    __syncthreads();

    #pragma unroll
    for (int mf = 0; mf < 2; mf++)
        #pragma unroll
        for (int h = 0; h < 2; h++) {
            int r = wm * 32 + mf * 16 + h * 8 + qr;
            int node = n0 + r;
            if (node >= N_NODES) continue;
            float S = sredS[r][0] + sredS[r][1] + sredS[r][2] + sredS[r][3];
            float Q = sredQ[r][0] + sredQ[r][1] + sredQ[r][2] + sredQ[r][3];
            float mu = S * (1.f / 128.f);
            float var = Q * (1.f / 128.f) - mu * mu;
            float rs = rsqrtf(var + LN_EPS);
            #pragma unroll
            for (int nf = 0; nf < 4; nf++) {
                int c = nbase + nf * 8 + qk;
                float2 o;
                o.x = (uvals[mf][nf][2 * h] - mu) * rs * sgf[c] + sbef[c];
                o.y = (uvals[mf][nf][2 * h + 1] - mu) * rs * sgf[c + 1] + sbef[c + 1];
                *(float2*)(out + (size_t)node * D + c) = o;
            }
        }
}

// --------------------------- launch -----------------------------------------
extern "C" void kernel_launch(void* const* d_in, const int* in_sizes, int n_in,
                              void* d_out, int out_size) {
    const float* nodes     = (const float*)d_in[0];
    const void*  eidx      = d_in[1];
    const float* edge_attr = (const float*)d_in[2];
    const float* Wm        = (const float*)d_in[3];
    const float* Wn        = (const float*)d_in[4];
    const float* W1        = (const float*)d_in[5];
    const float* b1        = (const float*)d_in[6];
    const float* g1        = (const float*)d_in[7];
    const float* be1       = (const float*)d_in[8];
    const float* W2        = (const float*)d_in[9];
    const float* b2        = (const float*)d_in[10];
    const float* g2        = (const float*)d_in[11];
    const float* be2       = (const float*)d_in[12];
    const float* gf        = (const float*)d_in[13];
    const float* bef       = (const float*)d_in[14];
    float* out = (float*)d_out;

    const int smem = 128 * KP1 * 2 * (int)sizeof(uint16_t);   // 151552
    cudaFuncSetAttribute(node_phase_kernel, cudaFuncAttributeMaxDynamicSharedMemorySize, smem);

    csr_build_kernel<<<CSRB, 256>>>(eidx);                                   // 1
    fuse_w_kernel<<<D, AD>>>(W1, Wm);                                        // 2 (+bar reset)
    prep_all_kernel<<<(KS1 * 16 * 32 + 255) / 256, 256>>>(W1, W2, Wn);       // 3
    pull_kernel<<<(N_NODES + 7) / 8, 256>>>(                                 // 4
        (const float4*)nodes, (const float4*)edge_attr);
    node_phase_kernel<<<NGRP, 512, smem>>>(nodes, b1, g1, be1,               // 5
                                           b2, g2, be2, gf, bef, out);
}

// round 8
// speedup vs baseline: 3.9465x; 1.1293x over previous
#include <cuda_runtime.h>
#include <cuda_bf16.h>
#include <cstdint>

// ---------------------------------------------------------------------------
// LinearMessagePassingLayer — GB300 sm_103a, round 8.
//   prep:  ONE kernel (Wf + all fragment packing)
//   csr:   persistent kernel (software grid barrier)
//   pull:  CSR gather-sum (x4 unroll)   [~78us, DRAM floor]
//   node:  fused MLP, M=64 tiles, 256 thr, 2 blocks/SM (epilogue overlap)
// ---------------------------------------------------------------------------

#define N_NODES 100000
#define N_EDGES 800000
#define D       128
#define ED      32
#define AD      160
#define LN_EPS  1e-5f
#define NB_SCAN ((N_NODES + 255) / 256)   // 391

#define KS1   18
#define KP1   296
#define KS2   8
#define MROWS 64
#define NGRP  ((N_NODES + MROWS - 1) / MROWS)   // 1563
#define CSRB  128

// --------------------------- device scratch -------------------------------
__device__ float    g_agg[(size_t)N_NODES * AD];
// prepacked fragment weights: [ks][ngrp(16)][lane(32)] uint4 {hi0,hi1,lo0,lo1}
__device__ uint4    g_w1p[KS1 * 16 * 32];
__device__ uint4    g_w2p[KS2 * 16 * 32];
__device__ uint4    g_wnp[KS2 * 16 * 32];
__device__ int      g_sr[2 * N_EDGES];
__device__ int      g_cnt[N_NODES];
__device__ int      g_off[N_NODES + 1];
__device__ int      g_sid[N_EDGES];
__device__ int      g_eix[N_EDGES];
__device__ int      g_bsum[NB_SCAN];
__device__ int      g_boff[NB_SCAN];
__device__ unsigned g_bar;

// --------------------------- helpers ---------------------------------------
__device__ __forceinline__ uint16_t f2bf(float x) {
    __nv_bfloat16 h = __float2bfloat16(x);
    return *reinterpret_cast<uint16_t*>(&h);
}
__device__ __forceinline__ float bf2f(uint16_t b) {
    __nv_bfloat16 h = *reinterpret_cast<__nv_bfloat16*>(&b);
    return __bfloat162float(h);
}

__device__ __forceinline__ uint32_t smem_u32(const void* p) {
    uint32_t a;
    asm("{ .reg .u64 t; cvta.to.shared.u64 t, %1; cvt.u32.u64 %0, t; }"
        : "=r"(a) : "l"(p));
    return a;
}

__device__ __forceinline__ void mma_bf16(float (&c)[4], const uint32_t (&a)[4],
                                         uint32_t b0, uint32_t b1) {
    asm volatile(
        "mma.sync.aligned.m16n8k16.row.col.f32.bf16.bf16.f32 "
        "{%0,%1,%2,%3},{%4,%5,%6,%7},{%8,%9},{%0,%1,%2,%3};\n"
        : "+f"(c[0]), "+f"(c[1]), "+f"(c[2]), "+f"(c[3])
        : "r"(a[0]), "r"(a[1]), "r"(a[2]), "r"(a[3]), "r"(b0), "r"(b1));
}

__device__ __forceinline__ void ldsm_x4(uint32_t (&a)[4], uint32_t addr) {
    asm volatile("ldmatrix.sync.aligned.m8n8.x4.shared.b16 {%0,%1,%2,%3}, [%4];"
                 : "=r"(a[0]), "=r"(a[1]), "=r"(a[2]), "=r"(a[3]) : "r"(addr));
}

__device__ __forceinline__ void cvt_store(uint16_t* hi, uint16_t* lo, int off, float4 v) {
    uint16_t h0 = f2bf(v.x), h1 = f2bf(v.y), h2 = f2bf(v.z), h3 = f2bf(v.w);
    uint16_t l0 = f2bf(v.x - bf2f(h0)), l1 = f2bf(v.y - bf2f(h1));
    uint16_t l2 = f2bf(v.z - bf2f(h2)), l3 = f2bf(v.w - bf2f(h3));
    *(uint32_t*)(hi + off)     = ((uint32_t)h1 << 16) | h0;
    *(uint32_t*)(hi + off + 2) = ((uint32_t)h3 << 16) | h2;
    *(uint32_t*)(lo + off)     = ((uint32_t)l1 << 16) | l0;
    *(uint32_t*)(lo + off + 2) = ((uint32_t)l3 << 16) | l2;
}

__device__ __forceinline__ void mma_step_lm(float (&acc)[2][4][4],
                                            uint32_t aHi0, uint32_t aHi1,
                                            uint32_t aLo0, uint32_t aLo1,
                                            const uint4 (&B)[4]) {
    uint32_t ah0[4], ah1[4], al0[4], al1[4];
    ldsm_x4(ah0, aHi0);
    ldsm_x4(ah1, aHi1);
    ldsm_x4(al0, aLo0);
    ldsm_x4(al1, aLo1);
#pragma unroll
    for (int nf = 0; nf < 4; nf++) {
        mma_bf16(acc[0][nf], ah0, B[nf].x, B[nf].y);
        mma_bf16(acc[0][nf], ah0, B[nf].z, B[nf].w);
        mma_bf16(acc[0][nf], al0, B[nf].x, B[nf].y);
        mma_bf16(acc[1][nf], ah1, B[nf].x, B[nf].y);
        mma_bf16(acc[1][nf], ah1, B[nf].z, B[nf].w);
        mma_bf16(acc[1][nf], al1, B[nf].x, B[nf].y);
    }
}

__device__ __forceinline__ void load_bp(const uint4* __restrict__ wp, int ks,
                                        int wn, int lane, uint4 (&B)[4]) {
#pragma unroll
    for (int nf = 0; nf < 4; nf++)
        B[nf] = __ldg(wp + ((size_t)ks * 16 + wn * 4 + nf) * 32 + lane);
}

__device__ __forceinline__ uint4 pack_frag(float v0, float v1, float v2, float v3) {
    uint16_t h0 = f2bf(v0), h1 = f2bf(v1), h2 = f2bf(v2), h3 = f2bf(v3);
    uint16_t l0 = f2bf(v0 - bf2f(h0)), l1 = f2bf(v1 - bf2f(h1));
    uint16_t l2 = f2bf(v2 - bf2f(h2)), l3 = f2bf(v3 - bf2f(h3));
    uint4 r;
    r.x = ((uint32_t)h1 << 16) | h0;
    r.y = ((uint32_t)h3 << 16) | h2;
    r.z = ((uint32_t)l1 << 16) | l0;
    r.w = ((uint32_t)l3 << 16) | l2;
    return r;
}

// --------------------------- prep (fuse + pack, one kernel) -----------------
// Block j handles output row n=j: computes Wf[j][*] in smem, packs w1/w2/wn frags.
__global__ void __launch_bounds__(AD)
prep_kernel(const float* __restrict__ W1, const float* __restrict__ Wm,
            const float* __restrict__ W2, const float* __restrict__ Wn) {
    __shared__ float sw[D];
    __shared__ float swf[AD];
    const int j = blockIdx.x, c = threadIdx.x;
    if (j == 0 && c == 0) g_bar = 0u;       // reset csr grid barrier per replay
    if (c < D) sw[c] = W1[j * (2 * D) + D + c];
    __syncthreads();
    {
        float s = 0.f;
        #pragma unroll 8
        for (int k = 0; k < D; k++)
            s += sw[k] * __ldg(&Wm[k * AD + c]);
        swf[c] = s;
    }
    __syncthreads();

    const int ngrp = j >> 3, qr = j & 7;
    if (c < KS1 * 4) {
        int ks = c >> 2, qkq = c & 3;
        int lane = qr * 4 + qkq;
        int k0 = ks * 16 + 2 * qkq;
        float v[4];
        #pragma unroll
        for (int jj = 0; jj < 4; jj++) {
            int k = k0 + (jj >> 1) * 8 + (jj & 1);
            v[jj] = (k < D) ? W1[j * (2 * D) + k] : swf[k - D];
        }
        g_w1p[ks * 512 + ngrp * 32 + lane] = pack_frag(v[0], v[1], v[2], v[3]);
    } else if (c < KS1 * 4 + KS2 * 4) {
        int t = c - KS1 * 4;
        int ks = t >> 2, qkq = t & 3;
        int lane = qr * 4 + qkq;
        int k0 = ks * 16 + 2 * qkq;
        g_w2p[ks * 512 + ngrp * 32 + lane] =
            pack_frag(W2[j * D + k0], W2[j * D + k0 + 1],
                      W2[j * D + k0 + 8], W2[j * D + k0 + 9]);
    } else if (c < KS1 * 4 + 2 * KS2 * 4) {
        int t = c - KS1 * 4 - KS2 * 4;
        int ks = t >> 2, qkq = t & 3;
        int lane = qr * 4 + qkq;
        int k0 = ks * 16 + 2 * qkq;
        g_wnp[ks * 512 + ngrp * 32 + lane] =
            pack_frag(Wn[j * D + k0], Wn[j * D + k0 + 1],
                      Wn[j * D + k0 + 8], Wn[j * D + k0 + 9]);
    }
}

// --------------------------- CSR build (persistent) ------------------------
__device__ __forceinline__ void grid_bar(unsigned target) {
    __syncthreads();
    if (threadIdx.x == 0) {
        __threadfence();
        atomicAdd(&g_bar, 1u);
        while (*(volatile unsigned*)&g_bar < target) { }
        __threadfence();
    }
    __syncthreads();
}

__global__ void __launch_bounds__(256)
csr_build_kernel(const void* __restrict__ p) {
    __shared__ int s[256];
    __shared__ int sh_base;
    __shared__ int anynz;
    const int t   = threadIdx.x;
    const int gid = blockIdx.x * 256 + t;
    const int gs  = CSRB * 256;

    for (int i = gid; i < N_NODES; i += gs) g_cnt[i] = 0;
    grid_bar(1 * CSRB);

    if (t == 0) anynz = 0;
    __syncthreads();
    if (t < 64) {
        if (((const unsigned int*)p)[2 * t + 1] != 0u) atomicOr(&anynz, 1);
    }
    __syncthreads();
    const int is64 = (anynz == 0);
    for (int i = gid; i < 2 * N_EDGES; i += gs) {
        int v = is64 ? (int)((const long long*)p)[i] : ((const int*)p)[i];
        g_sr[i] = v;
        if (i >= N_EDGES) atomicAdd(&g_cnt[v], 1);
    }
    grid_bar(2 * CSRB);

    {
        int w = gid >> 5, lane = t & 31;
        if (w < NB_SCAN) {
            int sum = 0;
            int base = w * 256 + lane * 8;
            #pragma unroll
            for (int j = 0; j < 8; j++) {
                int idx = base + j;
                if (idx < N_NODES) sum += __ldcg(&g_cnt[idx]);
            }
            #pragma unroll
            for (int o = 16; o; o >>= 1) sum += __shfl_xor_sync(0xffffffffu, sum, o);
            if (lane == 0) g_bsum[w] = sum;
        }
    }
    grid_bar(3 * CSRB);

    if (blockIdx.x == 0) {
        int a = (2 * t < NB_SCAN)     ? __ldcg(&g_bsum[2 * t])     : 0;
        int b = (2 * t + 1 < NB_SCAN) ? __ldcg(&g_bsum[2 * t + 1]) : 0;
        int c = a + b;
        s[t] = c;
        __syncthreads();
        for (int o = 1; o < 256; o <<= 1) {
            int x = (t >= o) ? s[t - o] : 0;
            __syncthreads();
            s[t] += x;
            __syncthreads();
        }
        int excl = s[t] - c;
        if (2 * t < NB_SCAN)     g_boff[2 * t]     = excl;
        if (2 * t + 1 < NB_SCAN) g_boff[2 * t + 1] = excl + a;
    }
    grid_bar(4 * CSRB);

    for (int c = blockIdx.x; c < NB_SCAN; c += CSRB) {
        const int i = c * 256 + t;
        int v = (i < N_NODES) ? __ldcg(&g_cnt[i]) : 0;
        s[t] = v;
        if (t == 0) sh_base = __ldcg(&g_boff[c]);
        __syncthreads();
        for (int o = 1; o < 256; o <<= 1) {
            int x = (t >= o) ? s[t - o] : 0;
            __syncthreads();
            s[t] += x;
            __syncthreads();
        }
        if (i < N_NODES) {
            int off = sh_base + s[t] - v;
            g_off[i] = off;
            g_cnt[i] = off;
        }
        __syncthreads();
    }
    if (blockIdx.x == 0 && t == 0) g_off[N_NODES] = N_EDGES;
    grid_bar(5 * CSRB);

    for (int e = gid; e < N_EDGES; e += gs) {
        int r = __ldcg(&g_sr[N_EDGES + e]);
        int pos = atomicAdd(&g_cnt[r], 1);
        g_sid[pos] = __ldcg(&g_sr[e]);
        g_eix[pos] = e;
    }
}

// --------------------------- pull aggregation -------------------------------
__global__ void __launch_bounds__(256)
pull_kernel(const float4* __restrict__ nodes4, const float4* __restrict__ ea4) {
    int n = blockIdx.x * 8 + (threadIdx.x >> 5);
    if (n >= N_NODES) return;
    const int lane = threadIdx.x & 31;
    const int beg = g_off[n], end = g_off[n + 1];
    float4 an = make_float4(0.f, 0.f, 0.f, 0.f);
    float4 ae = make_float4(0.f, 0.f, 0.f, 0.f);
    int i = beg;
    for (; i + 4 <= end; i += 4) {
        int s0 = __ldg(&g_sid[i]),     s1 = __ldg(&g_sid[i + 1]);
        int s2 = __ldg(&g_sid[i + 2]), s3 = __ldg(&g_sid[i + 3]);
        float4 v0 = __ldg(nodes4 + (size_t)s0 * 32 + lane);
        float4 v1 = __ldg(nodes4 + (size_t)s1 * 32 + lane);
        float4 v2 = __ldg(nodes4 + (size_t)s2 * 32 + lane);
        float4 v3 = __ldg(nodes4 + (size_t)s3 * 32 + lane);
        an.x += v0.x + v1.x + v2.x + v3.x;
        an.y += v0.y + v1.y + v2.y + v3.y;
        an.z += v0.z + v1.z + v2.z + v3.z;
        an.w += v0.w + v1.w + v2.w + v3.w;
        if (lane < 8) {
            int e0 = __ldg(&g_eix[i]),     e1 = __ldg(&g_eix[i + 1]);
            int e2 = __ldg(&g_eix[i + 2]), e3 = __ldg(&g_eix[i + 3]);
            float4 w0 = __ldg(ea4 + (size_t)e0 * 8 + lane);
            float4 w1 = __ldg(ea4 + (size_t)e1 * 8 + lane);
            float4 w2 = __ldg(ea4 + (size_t)e2 * 8 + lane);
            float4 w3 = __ldg(ea4 + (size_t)e3 * 8 + lane);
            ae.x += w0.x + w1.x + w2.x + w3.x;
            ae.y += w0.y + w1.y + w2.y + w3.y;
            ae.z += w0.z + w1.z + w2.z + w3.z;
            ae.w += w0.w + w1.w + w2.w + w3.w;
        }
    }
    for (; i < end; i++) {
        int s = __ldg(&g_sid[i]);
        float4 v = __ldg(nodes4 + (size_t)s * 32 + lane);
        an.x += v.x; an.y += v.y; an.z += v.z; an.w += v.w;
        if (lane < 8) {
            int e = __ldg(&g_eix[i]);
            float4 w = __ldg(ea4 + (size_t)e * 8 + lane);
            ae.x += w.x; ae.y += w.y; ae.z += w.z; ae.w += w.w;
        }
    }
    float4* dst = reinterpret_cast<float4*>(g_agg) + (size_t)n * 40;
    dst[lane] = an;
    if (lane < 8) dst[32 + lane] = ae;
}

// --------------------------- fused node phase (M=64, 2 blk/SM) --------------
__global__ void __launch_bounds__(256, 2)
node_phase_kernel(const float* __restrict__ nodes,
                  const float* __restrict__ b1,
                  const float* __restrict__ g1,
                  const float* __restrict__ be1,
                  const float* __restrict__ b2,
                  const float* __restrict__ g2,
                  const float* __restrict__ be2,
                  const float* __restrict__ gf,
                  const float* __restrict__ bef,
                  float* __restrict__ out) {
    extern __shared__ uint16_t smu[];
    uint16_t* sAhi = smu;
    uint16_t* sAlo = smu + MROWS * KP1;

    __shared__ float sb1[D], sg1[D], sbe1[D];
    __shared__ float sb2[D], sg2[D], sbe2[D], sgf[D], sbef[D];
    __shared__ float sredS[MROWS][4], sredQ[MROWS][4];

    const int tid = threadIdx.x;
    const int n0 = blockIdx.x * MROWS;
    if (tid < D) {
        sb1[tid] = b1[tid]; sg1[tid] = g1[tid]; sbe1[tid] = be1[tid];
        sb2[tid] = b2[tid]; sg2[tid] = g2[tid]; sbe2[tid] = be2[tid];
        sgf[tid] = gf[tid]; sbef[tid] = bef[tid];
    }

    // ---- load + convert A = [nodes | agg] (64 rows) ----
    const float4* nsrc = (const float4*)nodes;
    #pragma unroll
    for (int it = 0; it < 8; it++) {
        int idx = it * 256 + tid;                 // 64*32 = 2048
        int row = idx >> 5, c4 = idx & 31;
        float4 v = make_float4(0.f, 0.f, 0.f, 0.f);
        if (n0 + row < N_NODES) v = __ldg(nsrc + (size_t)(n0 + row) * 32 + c4);
        cvt_store(sAhi, sAlo, row * KP1 + c4 * 4, v);
    }
    const float4* asrc = (const float4*)g_agg;
    #pragma unroll
    for (int it = 0; it < 10; it++) {
        int idx = it * 256 + tid;                 // 64*40 = 2560
        int row = idx / 40, c4 = idx % 40;
        float4 v = make_float4(0.f, 0.f, 0.f, 0.f);
        if (n0 + row < N_NODES) v = asrc[(size_t)(n0 + row) * 40 + c4];
        cvt_store(sAhi, sAlo, row * KP1 + 128 + c4 * 4, v);
    }
    __syncthreads();

    const int lane = tid & 31;
    const int wid  = tid >> 5;        // 0..7
    const int wm   = wid >> 2;        // 0..1 (32 rows each)
    const int wn   = wid & 3;         // 0..3 (32 cols each)
    const int qr   = lane >> 2;
    const int qk   = 2 * (lane & 3);
    const int nbase = wn * 32;

    const int mrow = ((lane >> 3) & 1) * 8 + (lane & 7);
    const int kof  = (lane >> 4) * 8;
    const uint32_t sbase = smem_u32(smu);
    const uint32_t aHi0 = sbase + ((wm * 32 + mrow) * KP1 + kof) * 2;
    const uint32_t aHi1 = aHi0 + 16 * KP1 * 2;
    const uint32_t aLo0 = aHi0 + MROWS * KP1 * 2;
    const uint32_t aLo1 = aHi1 + MROWS * KP1 * 2;

    const uint4* wp1 = (const uint4*)g_w1p;
    const uint4* wp2 = (const uint4*)g_w2p;
    const uint4* wpn = (const uint4*)g_wnp;
    uint4 B0[4], B1[4];

    // =================== GEMM 1: [nodes|agg] @ Wcat^T (K=288) ===============
    float acc[2][4][4];
    #pragma unroll
    for (int mf = 0; mf < 2; mf++)
        #pragma unroll
        for (int nf = 0; nf < 4; nf++)
            #pragma unroll
            for (int i = 0; i < 4; i++) acc[mf][nf][i] = 0.f;

    load_bp(wp1, 0, wn, lane, B0);
    #pragma unroll 1
    for (int ks = 0; ks < KS1; ks += 2) {
        load_bp(wp1, ks + 1, wn, lane, B1);
        mma_step_lm(acc, aHi0 + ks * 32, aHi1 + ks * 32,
                    aLo0 + ks * 32, aLo1 + ks * 32, B0);
        if (ks + 2 < KS1) load_bp(wp1, ks + 2, wn, lane, B0);
        mma_step_lm(acc, aHi0 + (ks + 1) * 32, aHi1 + (ks + 1) * 32,
                    aLo0 + (ks + 1) * 32, aLo1 + (ks + 1) * 32, B1);
    }

    load_bp(wp2, 0, wn, lane, B0);   // prefetch GEMM2 behind LN1 epilogue

    // ---- bias + relu ----
    float vals[2][4][4];
    #pragma unroll
    for (int mf = 0; mf < 2; mf++)
        #pragma unroll
        for (int nf = 0; nf < 4; nf++) {
            int c = nbase + nf * 8 + qk;
            vals[mf][nf][0] = fmaxf(acc[mf][nf][0] + sb1[c], 0.f);
            vals[mf][nf][1] = fmaxf(acc[mf][nf][1] + sb1[c + 1], 0.f);
            vals[mf][nf][2] = fmaxf(acc[mf][nf][2] + sb1[c], 0.f);
            vals[mf][nf][3] = fmaxf(acc[mf][nf][3] + sb1[c + 1], 0.f);
        }

    // ---- LN1 reductions ----
    #pragma unroll
    for (int mf = 0; mf < 2; mf++)
        #pragma unroll
        for (int h = 0; h < 2; h++) {
            float s = 0.f, q = 0.f;
            #pragma unroll
            for (int nf = 0; nf < 4; nf++) {
                float v0 = vals[mf][nf][2 * h], v1 = vals[mf][nf][2 * h + 1];
                s += v0 + v1; q += v0 * v0 + v1 * v1;
            }
            s += __shfl_xor_sync(0xffffffffu, s, 1);
            s += __shfl_xor_sync(0xffffffffu, s, 2);
            q += __shfl_xor_sync(0xffffffffu, q, 1);
            q += __shfl_xor_sync(0xffffffffu, q, 2);
            int r = wm * 32 + mf * 16 + h * 8 + qr;
            if ((lane & 3) == 0) { sredS[r][wn] = s; sredQ[r][wn] = q; }
        }
    __syncthreads();

    // ---- LN1 apply; write h into the agg columns of sA ----
    #pragma unroll
    for (int mf = 0; mf < 2; mf++)
        #pragma unroll
        for (int h = 0; h < 2; h++) {
            int r = wm * 32 + mf * 16 + h * 8 + qr;
            float S = sredS[r][0] + sredS[r][1] + sredS[r][2] + sredS[r][3];
            float Q = sredQ[r][0] + sredQ[r][1] + sredQ[r][2] + sredQ[r][3];
            float mu = S * (1.f / 128.f);
            float var = Q * (1.f / 128.f) - mu * mu;
            float rs = rsqrtf(var + LN_EPS);
            #pragma unroll
            for (int nf = 0; nf < 4; nf++) {
                int c = nbase + nf * 8 + qk;
                float y0 = (vals[mf][nf][2 * h] - mu) * rs * sg1[c] + sbe1[c];
                float y1 = (vals[mf][nf][2 * h + 1] - mu) * rs * sg1[c + 1] + sbe1[c + 1];
                uint16_t h0 = f2bf(y0), h1 = f2bf(y1);
                uint16_t l0 = f2bf(y0 - bf2f(h0)), l1 = f2bf(y1 - bf2f(h1));
                *(uint32_t*)(sAhi + r * KP1 + 128 + c) = ((uint32_t)h1 << 16) | h0;
                *(uint32_t*)(sAlo + r * KP1 + 128 + c) = ((uint32_t)l1 << 16) | l0;
            }
        }
    __syncthreads();

    // =================== GEMM 2: h @ W2^T (K=128) ===========================
    #pragma unroll
    for (int mf = 0; mf < 2; mf++)
        #pragma unroll
        for (int nf = 0; nf < 4; nf++)
            #pragma unroll
            for (int i = 0; i < 4; i++) acc[mf][nf][i] = 0.f;
    #pragma unroll 1
    for (int ks = 0; ks < KS2; ks += 2) {
        load_bp(wp2, ks + 1, wn, lane, B1);
        mma_step_lm(acc, aHi0 + 256 + ks * 32, aHi1 + 256 + ks * 32,
                    aLo0 + 256 + ks * 32, aLo1 + 256 + ks * 32, B0);
        if (ks + 2 < KS2) load_bp(wp2, ks + 2, wn, lane, B0);
        mma_step_lm(acc, aHi0 + 256 + (ks + 1) * 32, aHi1 + 256 + (ks + 1) * 32,
                    aLo0 + 256 + (ks + 1) * 32, aLo1 + 256 + (ks + 1) * 32, B1);
    }

    load_bp(wpn, 0, wn, lane, B0);   // prefetch GEMM3 behind LN2 epilogue

    // ---- bias + relu -> uvals ----
    float uvals[2][4][4];
    #pragma unroll
    for (int mf = 0; mf < 2; mf++)
        #pragma unroll
        for (int nf = 0; nf < 4; nf++) {
            int c = nbase + nf * 8 + qk;
            uvals[mf][nf][0] = fmaxf(acc[mf][nf][0] + sb2[c], 0.f);
            uvals[mf][nf][1] = fmaxf(acc[mf][nf][1] + sb2[c + 1], 0.f);
            uvals[mf][nf][2] = fmaxf(acc[mf][nf][2] + sb2[c], 0.f);
            uvals[mf][nf][3] = fmaxf(acc[mf][nf][3] + sb2[c + 1], 0.f);
        }

    // ---- LN2 ----
    __syncthreads();
    #pragma unroll
    for (int mf = 0; mf < 2; mf++)
        #pragma unroll
        for (int h = 0; h < 2; h++) {
            float s = 0.f, q = 0.f;
            #pragma unroll
            for (int nf = 0; nf < 4; nf++) {
                float v0 = uvals[mf][nf][2 * h], v1 = uvals[mf][nf][2 * h + 1];
                s += v0 + v1; q += v0 * v0 + v1 * v1;
            }
            s += __shfl_xor_sync(0xffffffffu, s, 1);
            s += __shfl_xor_sync(0xffffffffu, s, 2);
            q += __shfl_xor_sync(0xffffffffu, q, 1);
            q += __shfl_xor_sync(0xffffffffu, q, 2);
            int r = wm * 32 + mf * 16 + h * 8 + qr;
            if ((lane & 3) == 0) { sredS[r][wn] = s; sredQ[r][wn] = q; }
        }
    __syncthreads();

    #pragma unroll
    for (int mf = 0; mf < 2; mf++)
        #pragma unroll
        for (int h = 0; h < 2; h++) {
            int r = wm * 32 + mf * 16 + h * 8 + qr;
            float S = sredS[r][0] + sredS[r][1] + sredS[r][2] + sredS[r][3];
            float Q = sredQ[r][0] + sredQ[r][1] + sredQ[r][2] + sredQ[r][3];
            float mu = S * (1.f / 128.f);
            float var = Q * (1.f / 128.f) - mu * mu;
            float rs = rsqrtf(var + LN_EPS);
            #pragma unroll
            for (int nf = 0; nf < 4; nf++) {
                int c = nbase + nf * 8 + qk;
                uvals[mf][nf][2 * h]     = (uvals[mf][nf][2 * h] - mu) * rs * sg2[c] + sbe2[c];
                uvals[mf][nf][2 * h + 1] = (uvals[mf][nf][2 * h + 1] - mu) * rs * sg2[c + 1] + sbe2[c + 1];
            }
        }
    __syncthreads();

    // =================== GEMM 3: nodes @ Wn^T (K=128) =======================
    #pragma unroll
    for (int mf = 0; mf < 2; mf++)
        #pragma unroll
        for (int nf = 0; nf < 4; nf++)
            #pragma unroll
            for (int i = 0; i < 4; i++) acc[mf][nf][i] = 0.f;
    #pragma unroll 1
    for (int ks = 0; ks < KS2; ks += 2) {
        load_bp(wpn, ks + 1, wn, lane, B1);
        mma_step_lm(acc, aHi0 + ks * 32, aHi1 + ks * 32,
                    aLo0 + ks * 32, aLo1 + ks * 32, B0);
        if (ks + 2 < KS2) load_bp(wpn, ks + 2, wn, lane, B0);
        mma_step_lm(acc, aHi0 + (ks + 1) * 32, aHi1 + (ks + 1) * 32,
                    aLo0 + (ks + 1) * 32, aLo1 + (ks + 1) * 32, B1);
    }

    // ---- v = acc + u; final LN ----
    #pragma unroll
    for (int mf = 0; mf < 2; mf++)
        #pragma unroll
        for (int nf = 0; nf < 4; nf++)
            #pragma unroll
            for (int i = 0; i < 4; i++)
                uvals[mf][nf][i] += acc[mf][nf][i];

    #pragma unroll
    for (int mf = 0; mf < 2; mf++)
        #pragma unroll
        for (int h = 0; h < 2; h++) {
            float s = 0.f, q = 0.f;
            #pragma unroll
            for (int nf = 0; nf < 4; nf++) {
                float v0 = uvals[mf][nf][2 * h], v1 = uvals[mf][nf][2 * h + 1];
                s += v0 + v1; q += v0 * v0 + v1 * v1;
            }
            s += __shfl_xor_sync(0xffffffffu, s, 1);
            s += __shfl_xor_sync(0xffffffffu, s, 2);
            q += __shfl_xor_sync(0xffffffffu, q, 1);
            q += __shfl_xor_sync(0xffffffffu, q, 2);
            int r = wm * 32 + mf * 16 + h * 8 + qr;
            if ((lane & 3) == 0) { sredS[r][wn] = s; sredQ[r][wn] = q; }
        }
    __syncthreads();

    #pragma unroll
    for (int mf = 0; mf < 2; mf++)
        #pragma unroll
        for (int h = 0; h < 2; h++) {
            int r = wm * 32 + mf * 16 + h * 8 + qr;
            int node = n0 + r;
            if (node >= N_NODES) continue;
            float S = sredS[r][0] + sredS[r][1] + sredS[r][2] + sredS[r][3];
            float Q = sredQ[r][0] + sredQ[r][1] + sredQ[r][2] + sredQ[r][3];
            float mu = S * (1.f / 128.f);
            float var = Q * (1.f / 128.f) - mu * mu;
            float rs = rsqrtf(var + LN_EPS);
            #pragma unroll
            for (int nf = 0; nf < 4; nf++) {
                int c = nbase + nf * 8 + qk;
                float2 o;
                o.x = (uvals[mf][nf][2 * h] - mu) * rs * sgf[c] + sbef[c];
                o.y = (uvals[mf][nf][2 * h + 1] - mu) * rs * sgf[c + 1] + sbef[c + 1];
                *(float2*)(out + (size_t)node * D + c) = o;
            }
        }
}

// --------------------------- launch -----------------------------------------
extern "C" void kernel_launch(void* const* d_in, const int* in_sizes, int n_in,
                              void* d_out, int out_size) {
    const float* nodes     = (const float*)d_in[0];
    const void*  eidx      = d_in[1];
    const float* edge_attr = (const float*)d_in[2];
    const float* Wm        = (const float*)d_in[3];
    const float* Wn        = (const float*)d_in[4];
    const float* W1        = (const float*)d_in[5];
    const float* b1        = (const float*)d_in[6];
    const float* g1        = (const float*)d_in[7];
    const float* be1       = (const float*)d_in[8];
    const float* W2        = (const float*)d_in[9];
    const float* b2        = (const float*)d_in[10];
    const float* g2        = (const float*)d_in[11];
    const float* be2       = (const float*)d_in[12];
    const float* gf        = (const float*)d_in[13];
    const float* bef       = (const float*)d_in[14];
    float* out = (float*)d_out;

    const int smem = MROWS * KP1 * 2 * (int)sizeof(uint16_t);   // 75776
    cudaFuncSetAttribute(node_phase_kernel, cudaFuncAttributeMaxDynamicSharedMemorySize, smem);

    prep_kernel<<<D, AD>>>(W1, Wm, W2, Wn);                                  // 1 (+bar reset)
    csr_build_kernel<<<CSRB, 256>>>(eidx);                                   // 2
    pull_kernel<<<(N_NODES + 7) / 8, 256>>>(                                 // 3
        (const float4*)nodes, (const float4*)edge_attr);
    node_phase_kernel<<<NGRP, 256, smem>>>(nodes, b1, g1, be1,               // 4
                                           b2, g2, be2, gf, bef, out);
}

// round 9
// speedup vs baseline: 3.9525x; 1.0015x over previous
#include <cuda_runtime.h>
#include <cuda_bf16.h>
#include <cstdint>

// ---------------------------------------------------------------------------
// LinearMessagePassingLayer — GB300 sm_103a, round 8.
//   prep:  ONE kernel (Wf + all fragment packing)
//   csr:   persistent kernel (software grid barrier)
//   pull:  CSR gather-sum (x4 unroll)   [~78us, DRAM floor]
//   node:  fused MLP, M=64 tiles, 256 thr, 2 blocks/SM (epilogue overlap)
// ---------------------------------------------------------------------------

#define N_NODES 100000
#define N_EDGES 800000
#define D       128
#define ED      32
#define AD      160
#define LN_EPS  1e-5f
#define NB_SCAN ((N_NODES + 255) / 256)   // 391

#define KS1   18
#define KP1   296
#define KS2   8
#define MROWS 64
#define NGRP  ((N_NODES + MROWS - 1) / MROWS)   // 1563
#define CSRB  128

// --------------------------- device scratch -------------------------------
__device__ float    g_agg[(size_t)N_NODES * AD];
// prepacked fragment weights: [ks][ngrp(16)][lane(32)] uint4 {hi0,hi1,lo0,lo1}
__device__ uint4    g_w1p[KS1 * 16 * 32];
__device__ uint4    g_w2p[KS2 * 16 * 32];
__device__ uint4    g_wnp[KS2 * 16 * 32];
__device__ int      g_sr[2 * N_EDGES];
__device__ int      g_cnt[N_NODES];
__device__ int      g_off[N_NODES + 1];
__device__ int      g_sid[N_EDGES];
__device__ int      g_eix[N_EDGES];
__device__ int      g_bsum[NB_SCAN];
__device__ int      g_boff[NB_SCAN];
__device__ unsigned g_bar;

// --------------------------- helpers ---------------------------------------
__device__ __forceinline__ uint16_t f2bf(float x) {
    __nv_bfloat16 h = __float2bfloat16(x);
    return *reinterpret_cast<uint16_t*>(&h);
}
__device__ __forceinline__ float bf2f(uint16_t b) {
    __nv_bfloat16 h = *reinterpret_cast<__nv_bfloat16*>(&b);
    return __bfloat162float(h);
}

__device__ __forceinline__ uint32_t smem_u32(const void* p) {
    uint32_t a;
    asm("{ .reg .u64 t; cvta.to.shared.u64 t, %1; cvt.u32.u64 %0, t; }"
        : "=r"(a) : "l"(p));
    return a;
}

__device__ __forceinline__ void mma_bf16(float (&c)[4], const uint32_t (&a)[4],
                                         uint32_t b0, uint32_t b1) {
    asm volatile(
        "mma.sync.aligned.m16n8k16.row.col.f32.bf16.bf16.f32 "
        "{%0,%1,%2,%3},{%4,%5,%6,%7},{%8,%9},{%0,%1,%2,%3};\n"
        : "+f"(c[0]), "+f"(c[1]), "+f"(c[2]), "+f"(c[3])
        : "r"(a[0]), "r"(a[1]), "r"(a[2]), "r"(a[3]), "r"(b0), "r"(b1));
}

__device__ __forceinline__ void ldsm_x4(uint32_t (&a)[4], uint32_t addr) {
    asm volatile("ldmatrix.sync.aligned.m8n8.x4.shared.b16 {%0,%1,%2,%3}, [%4];"
                 : "=r"(a[0]), "=r"(a[1]), "=r"(a[2]), "=r"(a[3]) : "r"(addr));
}

__device__ __forceinline__ void cvt_store(uint16_t* hi, uint16_t* lo, int off, float4 v) {
    uint16_t h0 = f2bf(v.x), h1 = f2bf(v.y), h2 = f2bf(v.z), h3 = f2bf(v.w);
    uint16_t l0 = f2bf(v.x - bf2f(h0)), l1 = f2bf(v.y - bf2f(h1));
    uint16_t l2 = f2bf(v.z - bf2f(h2)), l3 = f2bf(v.w - bf2f(h3));
    *(uint32_t*)(hi + off)     = ((uint32_t)h1 << 16) | h0;
    *(uint32_t*)(hi + off + 2) = ((uint32_t)h3 << 16) | h2;
    *(uint32_t*)(lo + off)     = ((uint32_t)l1 << 16) | l0;
    *(uint32_t*)(lo + off + 2) = ((uint32_t)l3 << 16) | l2;
}

__device__ __forceinline__ void mma_step_lm(float (&acc)[2][4][4],
                                            uint32_t aHi0, uint32_t aHi1,
                                            uint32_t aLo0, uint32_t aLo1,
                                            const uint4 (&B)[4]) {
    uint32_t ah0[4], ah1[4], al0[4], al1[4];
    ldsm_x4(ah0, aHi0);
    ldsm_x4(ah1, aHi1);
    ldsm_x4(al0, aLo0);
    ldsm_x4(al1, aLo1);
#pragma unroll
    for (int nf = 0; nf < 4; nf++) {
        mma_bf16(acc[0][nf], ah0, B[nf].x, B[nf].y);
        mma_bf16(acc[0][nf], ah0, B[nf].z, B[nf].w);
        mma_bf16(acc[0][nf], al0, B[nf].x, B[nf].y);
        mma_bf16(acc[1][nf], ah1, B[nf].x, B[nf].y);
        mma_bf16(acc[1][nf], ah1, B[nf].z, B[nf].w);
        mma_bf16(acc[1][nf], al1, B[nf].x, B[nf].y);
    }
}

__device__ __forceinline__ void load_bp(const uint4* __restrict__ wp, int ks,
                                        int wn, int lane, uint4 (&B)[4]) {
#pragma unroll
    for (int nf = 0; nf < 4; nf++)
        B[nf] = __ldg(wp + ((size_t)ks * 16 + wn * 4 + nf) * 32 + lane);
}

__device__ __forceinline__ uint4 pack_frag(float v0, float v1, float v2, float v3) {
    uint16_t h0 = f2bf(v0), h1 = f2bf(v1), h2 = f2bf(v2), h3 = f2bf(v3);
    uint16_t l0 = f2bf(v0 - bf2f(h0)), l1 = f2bf(v1 - bf2f(h1));
    uint16_t l2 = f2bf(v2 - bf2f(h2)), l3 = f2bf(v3 - bf2f(h3));
    uint4 r;
    r.x = ((uint32_t)h1 << 16) | h0;
    r.y = ((uint32_t)h3 << 16) | h2;
    r.z = ((uint32_t)l1 << 16) | l0;
    r.w = ((uint32_t)l3 << 16) | l2;
    return r;
}

// --------------------------- prep (fuse + pack, one kernel) -----------------
// Block j handles output row n=j: computes Wf[j][*] in smem, packs w1/w2/wn frags.
__global__ void __launch_bounds__(AD)
prep_kernel(const float* __restrict__ W1, const float* __restrict__ Wm,
            const float* __restrict__ W2, const float* __restrict__ Wn) {
    __shared__ float sw[D];
    __shared__ float swf[AD];
    const int j = blockIdx.x, c = threadIdx.x;
    if (j == 0 && c == 0) g_bar = 0u;       // reset csr grid barrier per replay
    if (c < D) sw[c] = W1[j * (2 * D) + D + c];
    __syncthreads();
    {
        float s = 0.f;
        #pragma unroll 8
        for (int k = 0; k < D; k++)
            s += sw[k] * __ldg(&Wm[k * AD + c]);
        swf[c] = s;
    }
    __syncthreads();

    const int ngrp = j >> 3, qr = j & 7;
    if (c < KS1 * 4) {
        int ks = c >> 2, qkq = c & 3;
        int lane = qr * 4 + qkq;
        int k0 = ks * 16 + 2 * qkq;
        float v[4];
        #pragma unroll
        for (int jj = 0; jj < 4; jj++) {
            int k = k0 + (jj >> 1) * 8 + (jj & 1);
            v[jj] = (k < D) ? W1[j * (2 * D) + k] : swf[k - D];
        }
        g_w1p[ks * 512 + ngrp * 32 + lane] = pack_frag(v[0], v[1], v[2], v[3]);
    } else if (c < KS1 * 4 + KS2 * 4) {
        int t = c - KS1 * 4;
        int ks = t >> 2, qkq = t & 3;
        int lane = qr * 4 + qkq;
        int k0 = ks * 16 + 2 * qkq;
        g_w2p[ks * 512 + ngrp * 32 + lane] =
            pack_frag(W2[j * D + k0], W2[j * D + k0 + 1],
                      W2[j * D + k0 + 8], W2[j * D + k0 + 9]);
    } else if (c < KS1 * 4 + 2 * KS2 * 4) {
        int t = c - KS1 * 4 - KS2 * 4;
        int ks = t >> 2, qkq = t & 3;
        int lane = qr * 4 + qkq;
        int k0 = ks * 16 + 2 * qkq;
        g_wnp[ks * 512 + ngrp * 32 + lane] =
            pack_frag(Wn[j * D + k0], Wn[j * D + k0 + 1],
                      Wn[j * D + k0 + 8], Wn[j * D + k0 + 9]);
    }
}

// --------------------------- CSR build (persistent) ------------------------
__device__ __forceinline__ void grid_bar(unsigned target) {
    __syncthreads();
    if (threadIdx.x == 0) {
        __threadfence();
        atomicAdd(&g_bar, 1u);
        while (*(volatile unsigned*)&g_bar < target) { }
        __threadfence();
    }
    __syncthreads();
}

__global__ void __launch_bounds__(256)
csr_build_kernel(const void* __restrict__ p) {
    __shared__ int s[256];
    __shared__ int sh_base;
    __shared__ int anynz;
    const int t   = threadIdx.x;
    const int gid = blockIdx.x * 256 + t;
    const int gs  = CSRB * 256;

    for (int i = gid; i < N_NODES; i += gs) g_cnt[i] = 0;
    grid_bar(1 * CSRB);

    if (t == 0) anynz = 0;
    __syncthreads();
    if (t < 64) {
        if (((const unsigned int*)p)[2 * t + 1] != 0u) atomicOr(&anynz, 1);
    }
    __syncthreads();
    const int is64 = (anynz == 0);
    for (int i = gid; i < 2 * N_EDGES; i += gs) {
        int v = is64 ? (int)((const long long*)p)[i] : ((const int*)p)[i];
        g_sr[i] = v;
        if (i >= N_EDGES) atomicAdd(&g_cnt[v], 1);
    }
    grid_bar(2 * CSRB);

    {
        int w = gid >> 5, lane = t & 31;
        if (w < NB_SCAN) {
            int sum = 0;
            int base = w * 256 + lane * 8;
            #pragma unroll
            for (int j = 0; j < 8; j++) {
                int idx = base + j;
                if (idx < N_NODES) sum += __ldcg(&g_cnt[idx]);
            }
            #pragma unroll
            for (int o = 16; o; o >>= 1) sum += __shfl_xor_sync(0xffffffffu, sum, o);
            if (lane == 0) g_bsum[w] = sum;
        }
    }
    grid_bar(3 * CSRB);

    if (blockIdx.x == 0) {
        int a = (2 * t < NB_SCAN)     ? __ldcg(&g_bsum[2 * t])     : 0;
        int b = (2 * t + 1 < NB_SCAN) ? __ldcg(&g_bsum[2 * t + 1]) : 0;
        int c = a + b;
        s[t] = c;
        __syncthreads();
        for (int o = 1; o < 256; o <<= 1) {
            int x = (t >= o) ? s[t - o] : 0;
            __syncthreads();
            s[t] += x;
            __syncthreads();
        }
        int excl = s[t] - c;
        if (2 * t < NB_SCAN)     g_boff[2 * t]     = excl;
        if (2 * t + 1 < NB_SCAN) g_boff[2 * t + 1] = excl + a;
    }
    grid_bar(4 * CSRB);

    for (int c = blockIdx.x; c < NB_SCAN; c += CSRB) {
        const int i = c * 256 + t;
        int v = (i < N_NODES) ? __ldcg(&g_cnt[i]) : 0;
        s[t] = v;
        if (t == 0) sh_base = __ldcg(&g_boff[c]);
        __syncthreads();
        for (int o = 1; o < 256; o <<= 1) {
            int x = (t >= o) ? s[t - o] : 0;
            __syncthreads();
            s[t] += x;
            __syncthreads();
        }
        if (i < N_NODES) {
            int off = sh_base + s[t] - v;
            g_off[i] = off;
            g_cnt[i] = off;
        }
        __syncthreads();
    }
    if (blockIdx.x == 0 && t == 0) g_off[N_NODES] = N_EDGES;
    grid_bar(5 * CSRB);

    for (int e = gid; e < N_EDGES; e += gs) {
        int r = __ldcg(&g_sr[N_EDGES + e]);
        int pos = atomicAdd(&g_cnt[r], 1);
        g_sid[pos] = __ldcg(&g_sr[e]);
        g_eix[pos] = e;
    }
}

// --------------------------- pull aggregation -------------------------------
__global__ void __launch_bounds__(256)
pull_kernel(const float4* __restrict__ nodes4, const float4* __restrict__ ea4) {
    int n = blockIdx.x * 8 + (threadIdx.x >> 5);
    if (n >= N_NODES) return;
    const int lane = threadIdx.x & 31;
    const int beg = g_off[n], end = g_off[n + 1];
    float4 an = make_float4(0.f, 0.f, 0.f, 0.f);
    float4 ae = make_float4(0.f, 0.f, 0.f, 0.f);
    int i = beg;
    for (; i + 4 <= end; i += 4) {
        int s0 = __ldg(&g_sid[i]),     s1 = __ldg(&g_sid[i + 1]);
        int s2 = __ldg(&g_sid[i + 2]), s3 = __ldg(&g_sid[i + 3]);
        float4 v0 = __ldg(nodes4 + (size_t)s0 * 32 + lane);
        float4 v1 = __ldg(nodes4 + (size_t)s1 * 32 + lane);
        float4 v2 = __ldg(nodes4 + (size_t)s2 * 32 + lane);
        float4 v3 = __ldg(nodes4 + (size_t)s3 * 32 + lane);
        an.x += v0.x + v1.x + v2.x + v3.x;
        an.y += v0.y + v1.y + v2.y + v3.y;
        an.z += v0.z + v1.z + v2.z + v3.z;
        an.w += v0.w + v1.w + v2.w + v3.w;
        if (lane < 8) {
            int e0 = __ldg(&g_eix[i]),     e1 = __ldg(&g_eix[i + 1]);
            int e2 = __ldg(&g_eix[i + 2]), e3 = __ldg(&g_eix[i + 3]);
            float4 w0 = __ldg(ea4 + (size_t)e0 * 8 + lane);
            float4 w1 = __ldg(ea4 + (size_t)e1 * 8 + lane);
            float4 w2 = __ldg(ea4 + (size_t)e2 * 8 + lane);
            float4 w3 = __ldg(ea4 + (size_t)e3 * 8 + lane);
            ae.x += w0.x + w1.x + w2.x + w3.x;
            ae.y += w0.y + w1.y + w2.y + w3.y;
            ae.z += w0.z + w1.z + w2.z + w3.z;
            ae.w += w0.w + w1.w + w2.w + w3.w;
        }
    }
    for (; i < end; i++) {
        int s = __ldg(&g_sid[i]);
        float4 v = __ldg(nodes4 + (size_t)s * 32 + lane);
        an.x += v.x; an.y += v.y; an.z += v.z; an.w += v.w;
        if (lane < 8) {
            int e = __ldg(&g_eix[i]);
            float4 w = __ldg(ea4 + (size_t)e * 8 + lane);
            ae.x += w.x; ae.y += w.y; ae.z += w.z; ae.w += w.w;
        }
    }
    float4* dst = reinterpret_cast<float4*>(g_agg) + (size_t)n * 40;
    dst[lane] = an;
    if (lane < 8) dst[32 + lane] = ae;
}

// --------------------------- fused node phase (M=64, 2 blk/SM) --------------
__global__ void __launch_bounds__(256, 2)
node_phase_kernel(const float* __restrict__ nodes,
                  const float* __restrict__ b1,
                  const float* __restrict__ g1,
                  const float* __restrict__ be1,
                  const float* __restrict__ b2,
                  const float* __restrict__ g2,
                  const float* __restrict__ be2,
                  const float* __restrict__ gf,
                  const float* __restrict__ bef,
                  float* __restrict__ out) {
    extern __shared__ uint16_t smu[];
    uint16_t* sAhi = smu;
    uint16_t* sAlo = smu + MROWS * KP1;

    __shared__ float sb1[D], sg1[D], sbe1[D];
    __shared__ float sb2[D], sg2[D], sbe2[D], sgf[D], sbef[D];
    __shared__ float sredS[MROWS][4], sredQ[MROWS][4];

    const int tid = threadIdx.x;
    const int n0 = blockIdx.x * MROWS;
    if (tid < D) {
        sb1[tid] = b1[tid]; sg1[tid] = g1[tid]; sbe1[tid] = be1[tid];
        sb2[tid] = b2[tid]; sg2[tid] = g2[tid]; sbe2[tid] = be2[tid];
        sgf[tid] = gf[tid]; sbef[tid] = bef[tid];
    }

    // ---- load + convert A = [nodes | agg] (64 rows) ----
    const float4* nsrc = (const float4*)nodes;
    #pragma unroll
    for (int it = 0; it < 8; it++) {
        int idx = it * 256 + tid;                 // 64*32 = 2048
        int row = idx >> 5, c4 = idx & 31;
        float4 v = make_float4(0.f, 0.f, 0.f, 0.f);
        if (n0 + row < N_NODES) v = __ldg(nsrc + (size_t)(n0 + row) * 32 + c4);
        cvt_store(sAhi, sAlo, row * KP1 + c4 * 4, v);
    }
    const float4* asrc = (const float4*)g_agg;
    #pragma unroll
    for (int it = 0; it < 10; it++) {
        int idx = it * 256 + tid;                 // 64*40 = 2560
        int row = idx / 40, c4 = idx % 40;
        float4 v = make_float4(0.f, 0.f, 0.f, 0.f);
        if (n0 + row < N_NODES) v = asrc[(size_t)(n0 + row) * 40 + c4];
        cvt_store(sAhi, sAlo, row * KP1 + 128 + c4 * 4, v);
    }
    __syncthreads();

    const int lane = tid & 31;
    const int wid  = tid >> 5;        // 0..7
    const int wm   = wid >> 2;        // 0..1 (32 rows each)
    const int wn   = wid & 3;         // 0..3 (32 cols each)
    const int qr   = lane >> 2;
    const int qk   = 2 * (lane & 3);
    const int nbase = wn * 32;

    const int mrow = ((lane >> 3) & 1) * 8 + (lane & 7);
    const int kof  = (lane >> 4) * 8;
    const uint32_t sbase = smem_u32(smu);
    const uint32_t aHi0 = sbase + ((wm * 32 + mrow) * KP1 + kof) * 2;
    const uint32_t aHi1 = aHi0 + 16 * KP1 * 2;
    const uint32_t aLo0 = aHi0 + MROWS * KP1 * 2;
    const uint32_t aLo1 = aHi1 + MROWS * KP1 * 2;

    const uint4* wp1 = (const uint4*)g_w1p;
    const uint4* wp2 = (const uint4*)g_w2p;
    const uint4* wpn = (const uint4*)g_wnp;
    uint4 B0[4], B1[4];

    // =================== GEMM 1: [nodes|agg] @ Wcat^T (K=288) ===============
    float acc[2][4][4];
    #pragma unroll
    for (int mf = 0; mf < 2; mf++)
        #pragma unroll
        for (int nf = 0; nf < 4; nf++)
            #pragma unroll
            for (int i = 0; i < 4; i++) acc[mf][nf][i] = 0.f;

    load_bp(wp1, 0, wn, lane, B0);
    #pragma unroll 1
    for (int ks = 0; ks < KS1; ks += 2) {
        load_bp(wp1, ks + 1, wn, lane, B1);
        mma_step_lm(acc, aHi0 + ks * 32, aHi1 + ks * 32,
                    aLo0 + ks * 32, aLo1 + ks * 32, B0);
        if (ks + 2 < KS1) load_bp(wp1, ks + 2, wn, lane, B0);
        mma_step_lm(acc, aHi0 + (ks + 1) * 32, aHi1 + (ks + 1) * 32,
                    aLo0 + (ks + 1) * 32, aLo1 + (ks + 1) * 32, B1);
    }

    load_bp(wp2, 0, wn, lane, B0);   // prefetch GEMM2 behind LN1 epilogue

    // ---- bias + relu ----
    float vals[2][4][4];
    #pragma unroll
    for (int mf = 0; mf < 2; mf++)
        #pragma unroll
        for (int nf = 0; nf < 4; nf++) {
            int c = nbase + nf * 8 + qk;
            vals[mf][nf][0] = fmaxf(acc[mf][nf][0] + sb1[c], 0.f);
            vals[mf][nf][1] = fmaxf(acc[mf][nf][1] + sb1[c + 1], 0.f);
            vals[mf][nf][2] = fmaxf(acc[mf][nf][2] + sb1[c], 0.f);
            vals[mf][nf][3] = fmaxf(acc[mf][nf][3] + sb1[c + 1], 0.f);
        }

    // ---- LN1 reductions ----
    #pragma unroll
    for (int mf = 0; mf < 2; mf++)
        #pragma unroll
        for (int h = 0; h < 2; h++) {
            float s = 0.f, q = 0.f;
            #pragma unroll
            for (int nf = 0; nf < 4; nf++) {
                float v0 = vals[mf][nf][2 * h], v1 = vals[mf][nf][2 * h + 1];
                s += v0 + v1; q += v0 * v0 + v1 * v1;
            }
            s += __shfl_xor_sync(0xffffffffu, s, 1);
            s += __shfl_xor_sync(0xffffffffu, s, 2);
            q += __shfl_xor_sync(0xffffffffu, q, 1);
            q += __shfl_xor_sync(0xffffffffu, q, 2);
            int r = wm * 32 + mf * 16 + h * 8 + qr;
            if ((lane & 3) == 0) { sredS[r][wn] = s; sredQ[r][wn] = q; }
        }
    __syncthreads();

    // ---- LN1 apply; write h into the agg columns of sA ----
    #pragma unroll
    for (int mf = 0; mf < 2; mf++)
        #pragma unroll
        for (int h = 0; h < 2; h++) {
            int r = wm * 32 + mf * 16 + h * 8 + qr;
            float S = sredS[r][0] + sredS[r][1] + sredS[r][2] + sredS[r][3];
            float Q = sredQ[r][0] + sredQ[r][1] + sredQ[r][2] + sredQ[r][3];
            float mu = S * (1.f / 128.f);
            float var = Q * (1.f / 128.f) - mu * mu;
            float rs = rsqrtf(var + LN_EPS);
            #pragma unroll
            for (int nf = 0; nf < 4; nf++) {
                int c = nbase + nf * 8 + qk;
                float y0 = (vals[mf][nf][2 * h] - mu) * rs * sg1[c] + sbe1[c];
                float y1 = (vals[mf][nf][2 * h + 1] - mu) * rs * sg1[c + 1] + sbe1[c + 1];
                uint16_t h0 = f2bf(y0), h1 = f2bf(y1);
                uint16_t l0 = f2bf(y0 - bf2f(h0)), l1 = f2bf(y1 - bf2f(h1));
                *(uint32_t*)(sAhi + r * KP1 + 128 + c) = ((uint32_t)h1 << 16) | h0;
                *(uint32_t*)(sAlo + r * KP1 + 128 + c) = ((uint32_t)l1 << 16) | l0;
            }
        }
    __syncthreads();

    // =================== GEMM 2: h @ W2^T (K=128) ===========================
    #pragma unroll
    for (int mf = 0; mf < 2; mf++)
        #pragma unroll
        for (int nf = 0; nf < 4; nf++)
            #pragma unroll
            for (int i = 0; i < 4; i++) acc[mf][nf][i] = 0.f;
    #pragma unroll 1
    for (int ks = 0; ks < KS2; ks += 2) {
        load_bp(wp2, ks + 1, wn, lane, B1);
        mma_step_lm(acc, aHi0 + 256 + ks * 32, aHi1 + 256 + ks * 32,
                    aLo0 + 256 + ks * 32, aLo1 + 256 + ks * 32, B0);
        if (ks + 2 < KS2) load_bp(wp2, ks + 2, wn, lane, B0);
        mma_step_lm(acc, aHi0 + 256 + (ks + 1) * 32, aHi1 + 256 + (ks + 1) * 32,
                    aLo0 + 256 + (ks + 1) * 32, aLo1 + 256 + (ks + 1) * 32, B1);
    }

    load_bp(wpn, 0, wn, lane, B0);   // prefetch GEMM3 behind LN2 epilogue

    // ---- bias + relu -> uvals ----
    float uvals[2][4][4];
    #pragma unroll
    for (int mf = 0; mf < 2; mf++)
        #pragma unroll
        for (int nf = 0; nf < 4; nf++) {
            int c = nbase + nf * 8 + qk;
            uvals[mf][nf][0] = fmaxf(acc[mf][nf][0] + sb2[c], 0.f);
            uvals[mf][nf][1] = fmaxf(acc[mf][nf][1] + sb2[c + 1], 0.f);
            uvals[mf][nf][2] = fmaxf(acc[mf][nf][2] + sb2[c], 0.f);
            uvals[mf][nf][3] = fmaxf(acc[mf][nf][3] + sb2[c + 1], 0.f);
        }

    // ---- LN2 ----
    __syncthreads();
    #pragma unroll
    for (int mf = 0; mf < 2; mf++)
        #pragma unroll
        for (int h = 0; h < 2; h++) {
            float s = 0.f, q = 0.f;
            #pragma unroll
            for (int nf = 0; nf < 4; nf++) {
                float v0 = uvals[mf][nf][2 * h], v1 = uvals[mf][nf][2 * h + 1];
                s += v0 + v1; q += v0 * v0 + v1 * v1;
            }
            s += __shfl_xor_sync(0xffffffffu, s, 1);
            s += __shfl_xor_sync(0xffffffffu, s, 2);
            q += __shfl_xor_sync(0xffffffffu, q, 1);
            q += __shfl_xor_sync(0xffffffffu, q, 2);
            int r = wm * 32 + mf * 16 + h * 8 + qr;
            if ((lane & 3) == 0) { sredS[r][wn] = s; sredQ[r][wn] = q; }
        }
    __syncthreads();

    #pragma unroll
    for (int mf = 0; mf < 2; mf++)
        #pragma unroll
        for (int h = 0; h < 2; h++) {
            int r = wm * 32 + mf * 16 + h * 8 + qr;
            float S = sredS[r][0] + sredS[r][1] + sredS[r][2] + sredS[r][3];
            float Q = sredQ[r][0] + sredQ[r][1] + sredQ[r][2] + sredQ[r][3];
            float mu = S * (1.f / 128.f);
            float var = Q * (1.f / 128.f) - mu * mu;
            float rs = rsqrtf(var + LN_EPS);
            #pragma unroll
            for (int nf = 0; nf < 4; nf++) {
                int c = nbase + nf * 8 + qk;
                uvals[mf][nf][2 * h]     = (uvals[mf][nf][2 * h] - mu) * rs * sg2[c] + sbe2[c];
                uvals[mf][nf][2 * h + 1] = (uvals[mf][nf][2 * h + 1] - mu) * rs * sg2[c + 1] + sbe2[c + 1];
            }
        }
    __syncthreads();

    // =================== GEMM 3: nodes @ Wn^T (K=128) =======================
    #pragma unroll
    for (int mf = 0; mf < 2; mf++)
        #pragma unroll
        for (int nf = 0; nf < 4; nf++)
            #pragma unroll
            for (int i = 0; i < 4; i++) acc[mf][nf][i] = 0.f;
    #pragma unroll 1
    for (int ks = 0; ks < KS2; ks += 2) {
        load_bp(wpn, ks + 1, wn, lane, B1);
        mma_step_lm(acc, aHi0 + ks * 32, aHi1 + ks * 32,
                    aLo0 + ks * 32, aLo1 + ks * 32, B0);
        if (ks + 2 < KS2) load_bp(wpn, ks + 2, wn, lane, B0);
        mma_step_lm(acc, aHi0 + (ks + 1) * 32, aHi1 + (ks + 1) * 32,
                    aLo0 + (ks + 1) * 32, aLo1 + (ks + 1) * 32, B1);
    }

    // ---- v = acc + u; final LN ----
    #pragma unroll
    for (int mf = 0; mf < 2; mf++)
        #pragma unroll
        for (int nf = 0; nf < 4; nf++)
            #pragma unroll
            for (int i = 0; i < 4; i++)
                uvals[mf][nf][i] += acc[mf][nf][i];

    #pragma unroll
    for (int mf = 0; mf < 2; mf++)
        #pragma unroll
        for (int h = 0; h < 2; h++) {
            float s = 0.f, q = 0.f;
            #pragma unroll
            for (int nf = 0; nf < 4; nf++) {
                float v0 = uvals[mf][nf][2 * h], v1 = uvals[mf][nf][2 * h + 1];
                s += v0 + v1; q += v0 * v0 + v1 * v1;
            }
            s += __shfl_xor_sync(0xffffffffu, s, 1);
            s += __shfl_xor_sync(0xffffffffu, s, 2);
            q += __shfl_xor_sync(0xffffffffu, q, 1);
            q += __shfl_xor_sync(0xffffffffu, q, 2);
            int r = wm * 32 + mf * 16 + h * 8 + qr;
            if ((lane & 3) == 0) { sredS[r][wn] = s; sredQ[r][wn] = q; }
        }
    __syncthreads();

    #pragma unroll
    for (int mf = 0; mf < 2; mf++)
        #pragma unroll
        for (int h = 0; h < 2; h++) {
            int r = wm * 32 + mf * 16 + h * 8 + qr;
            int node = n0 + r;
            if (node >= N_NODES) continue;
            float S = sredS[r][0] + sredS[r][1] + sredS[r][2] + sredS[r][3];
            float Q = sredQ[r][0] + sredQ[r][1] + sredQ[r][2] + sredQ[r][3];
            float mu = S * (1.f / 128.f);
            float var = Q * (1.f / 128.f) - mu * mu;
            float rs = rsqrtf(var + LN_EPS);
            #pragma unroll
            for (int nf = 0; nf < 4; nf++) {
                int c = nbase + nf * 8 + qk;
                float2 o;
                o.x = (uvals[mf][nf][2 * h] - mu) * rs * sgf[c] + sbef[c];
                o.y = (uvals[mf][nf][2 * h + 1] - mu) * rs * sgf[c + 1] + sbef[c + 1];
                *(float2*)(out + (size_t)node * D + c) = o;
            }
        }
}

// --------------------------- launch -----------------------------------------
extern "C" void kernel_launch(void* const* d_in, const int* in_sizes, int n_in,
                              void* d_out, int out_size) {
    const float* nodes     = (const float*)d_in[0];
    const void*  eidx      = d_in[1];
    const float* edge_attr = (const float*)d_in[2];
    const float* Wm        = (const float*)d_in[3];
    const float* Wn        = (const float*)d_in[4];
    const float* W1        = (const float*)d_in[5];
    const float* b1        = (const float*)d_in[6];
    const float* g1        = (const float*)d_in[7];
    const float* be1       = (const float*)d_in[8];
    const float* W2        = (const float*)d_in[9];
    const float* b2        = (const float*)d_in[10];
    const float* g2        = (const float*)d_in[11];
    const float* be2       = (const float*)d_in[12];
    const float* gf        = (const float*)d_in[13];
    const float* bef       = (const float*)d_in[14];
    float* out = (float*)d_out;

    const int smem = MROWS * KP1 * 2 * (int)sizeof(uint16_t);   // 75776
    cudaFuncSetAttribute(node_phase_kernel, cudaFuncAttributeMaxDynamicSharedMemorySize, smem);

    prep_kernel<<<D, AD>>>(W1, Wm, W2, Wn);                                  // 1 (+bar reset)
    csr_build_kernel<<<CSRB, 256>>>(eidx);                                   // 2
    pull_kernel<<<(N_NODES + 7) / 8, 256>>>(                                 // 3
        (const float4*)nodes, (const float4*)edge_attr);
    node_phase_kernel<<<NGRP, 256, smem>>>(nodes, b1, g1, be1,               // 4
                                           b2, g2, be2, gf, bef, out);
}